// round 6
// baseline (speedup 1.0000x reference)
#include <cuda_runtime.h>
#include <math.h>

#define NLV 50000
#define NPV 150000
#define EV  500000
#define NGV 256

// ---------------- device-global scratch (module-load allocated; no runtime alloc) ----
__device__ float g_xl   [NLV*128];
__device__ float g_xl2  [NLV*128];
__device__ float g_xlsum[NLV*128];
__device__ float g_prel [NLV*128];
__device__ float g_xp   [NPV*128];
__device__ float g_xp2  [NPV*128];
__device__ float g_xpsum[NPV*128];
__device__ float g_prep [NPV*128];
__device__ float g_rbf  [EV*8];
__device__ float g_A    [(size_t)NLV*512];
__device__ float g_B    [(size_t)NPV*512];
__device__ float g_cvec [512];
__device__ int   g_dst_cnt[NPV];
__device__ int   g_dst_ptr[NPV+1];
__device__ int   g_dst_edges[EV];
__device__ int   g_src_cnt[NLV];
__device__ int   g_src_ptr[NLV+1];
__device__ int   g_src_edges[EV];
__device__ int   g_scan_tmp[NPV];
__device__ int   g_bsum[512];
__device__ float g_out_w  [NGV*128];
__device__ float g_out_max[NGV*128];

// ---------------- helpers ----------------
__device__ __forceinline__ void atomicMaxFloat(float* addr, float v) {
    if (v >= 0.0f) atomicMax((int*)addr, __float_as_int(v));
    else           atomicMin((unsigned int*)addr, __float_as_uint(v));
}

// ---------------- node embedding: Y[M,128] = X[M,44] @ Wnode[44,128] --------------
__global__ void k_embed(const float* __restrict__ X, float* __restrict__ Y,
                        const float* __restrict__ Wn, int M) {
    __shared__ float xs[4][44];
    int r0 = blockIdx.x * 4;
    int tid = threadIdx.x;  // 128
    for (int i = tid; i < 4 * 44; i += 128) {
        int rr = i / 44, kk = i % 44;
        xs[rr][kk] = (r0 + rr < M) ? X[(size_t)(r0 + rr) * 44 + kk] : 0.f;
    }
    __syncthreads();
    int col = tid;
    #pragma unroll
    for (int rr = 0; rr < 4; rr++) {
        if (r0 + rr < M) {
            float s = 0.f;
            #pragma unroll
            for (int kk = 0; kk < 44; kk++) s = fmaf(xs[rr][kk], Wn[kk * 128 + col], s);
            Y[(size_t)(r0 + rr) * 128 + col] = s;
        }
    }
}

// ---------------- RBF: mu_k = 5k/7, 1/sigma = 1.6 --------------------------------
__global__ void k_rbf(const float* __restrict__ ea) {
    int e = blockIdx.x * 256 + threadIdx.x;
    if (e < EV) {
        float d = ea[e];
        #pragma unroll
        for (int k = 0; k < 8; k++) {
            float t = (d - (5.0f / 7.0f) * (float)k) * 1.6f;
            g_rbf[e * 8 + k] = __expf(-t * t);
        }
    }
}

// ---------------- CSR construction ----------------
__global__ void k_hist(const int* __restrict__ src, const int* __restrict__ dst) {
    int e = blockIdx.x * 256 + threadIdx.x;
    if (e < EV) {
        atomicAdd(&g_dst_cnt[dst[e]], 1);
        atomicAdd(&g_src_cnt[src[e]], 1);
    }
}
__global__ void k_scan1(const int* __restrict__ cnt, int* __restrict__ excl,
                        int* __restrict__ bsum, int n) {
    __shared__ int s[1024];
    int i = blockIdx.x * 1024 + threadIdx.x;
    int v = (i < n) ? cnt[i] : 0;
    s[threadIdx.x] = v;
    __syncthreads();
    for (int off = 1; off < 1024; off <<= 1) {
        int t = 0;
        if ((int)threadIdx.x >= off) t = s[threadIdx.x - off];
        __syncthreads();
        s[threadIdx.x] += t;
        __syncthreads();
    }
    if (i < n) excl[i] = s[threadIdx.x] - v;
    if (threadIdx.x == 1023) bsum[blockIdx.x] = s[1023];
}
__global__ void k_scan2(int* bsum, int nb) {
    if (threadIdx.x == 0 && blockIdx.x == 0) {
        int acc = 0;
        for (int b = 0; b < nb; b++) { int t = bsum[b]; bsum[b] = acc; acc += t; }
    }
}
__global__ void k_scan3(const int* __restrict__ excl, const int* __restrict__ bsum,
                        int* __restrict__ ptr, int n) {
    int i = blockIdx.x * 1024 + threadIdx.x;
    if (i < n) ptr[i] = excl[i] + bsum[i >> 10];
    if (i == 0) ptr[n] = EV;
}
__global__ void k_fill(const int* __restrict__ src, const int* __restrict__ dst) {
    int e = blockIdx.x * 256 + threadIdx.x;
    if (e < EV) {
        int d = dst[e]; int p = atomicAdd(&g_dst_cnt[d], 1); g_dst_edges[g_dst_ptr[d] + p] = e;
        int s = src[e]; int q = atomicAdd(&g_src_cnt[s], 1); g_src_edges[g_src_ptr[s] + q] = e;
    }
}

// ---------------- aggregation: pre[w] = mean_e silu(rbf@Wb+bb) * xsrc[partner(e)] --
__global__ __launch_bounds__(256) void k_agg(
    const int* __restrict__ ptr, const int* __restrict__ eidx,
    const int* __restrict__ partner, const float* __restrict__ xsrc,
    const float* __restrict__ Wb_i, const float* __restrict__ bb_i,
    float* __restrict__ pre, int n_dst)
{
    int w = (blockIdx.x * blockDim.x + threadIdx.x) >> 5;
    int lane = threadIdx.x & 31;
    if (w >= n_dst) return;
    float wreg[8][4], bias[4], acc[4] = {0.f, 0.f, 0.f, 0.f};
    #pragma unroll
    for (int c = 0; c < 4; c++) {
        bias[c] = bb_i[c * 32 + lane];
        #pragma unroll
        for (int k = 0; k < 8; k++) wreg[k][c] = Wb_i[k * 128 + c * 32 + lane];
    }
    int s = ptr[w], e = ptr[w + 1];
    for (int p = s; p < e; p++) {
        int ed = eidx[p];
        float rv = (lane < 8) ? g_rbf[ed * 8 + lane] : 0.f;
        float r[8];
        #pragma unroll
        for (int k = 0; k < 8; k++) r[k] = __shfl_sync(0xffffffffu, rv, k);
        const float* xr = xsrc + (size_t)partner[ed] * 128;
        #pragma unroll
        for (int c = 0; c < 4; c++) {
            float t = bias[c];
            #pragma unroll
            for (int k = 0; k < 8; k++) t = fmaf(r[k], wreg[k][c], t);
            float sg = 1.f / (1.f + __expf(-t));
            acc[c] += (t * sg) * xr[c * 32 + lane];
        }
    }
    float inv = 1.f / (float)((e - s) > 1 ? (e - s) : 1);
    #pragma unroll
    for (int c = 0; c < 4; c++) pre[(size_t)w * 128 + c * 32 + lane] = acc[c] * inv;
}

// ---------------- generic fused SGEMM ----------------
// C[M,N] = act( A0[M,K0]@W0[K0,N] + A1[M,K1]@W1[K1,N] + bias ); optional sum += C
// tile 64x128, BK=16, 256 threads, 8x4 micro. N multiple of 128, K0/K1 multiples of 16.
__global__ __launch_bounds__(256) void k_gemm(
    const float* __restrict__ A0, const float* __restrict__ W0,
    const float* __restrict__ A1, const float* __restrict__ W1,
    const float* __restrict__ bias, float* __restrict__ C,
    float* __restrict__ sum, int M, int N, int K0, int K1, int act)
{
    __shared__ float As[16][68];
    __shared__ float Ws[16][128];
    int tid = threadIdx.x;
    int m0 = blockIdx.y * 64;
    int n0 = blockIdx.x * 128;
    int K = K0 + K1;
    float acc[8][4];
    #pragma unroll
    for (int r = 0; r < 8; r++)
        #pragma unroll
        for (int c = 0; c < 4; c++) acc[r][c] = 0.f;

    int le = tid >> 2;
    int lk = (tid & 3) * 4;
    int arow = m0 + le;
    int ty = tid >> 5, tx = tid & 31;
    int wr = tid >> 7, wc = tid & 127;

    for (int k = 0; k < K; k += 16) {
        const float* Ab; const float* Wb_; int kl; int stride;
        if (k < K0) { Ab = A0; Wb_ = W0; kl = k; stride = K0; }
        else        { Ab = A1; Wb_ = W1; kl = k - K0; stride = K1; }
        float4 a4 = make_float4(0.f, 0.f, 0.f, 0.f);
        if (arow < M) a4 = *(const float4*)(Ab + (size_t)arow * stride + kl + lk);
        As[lk + 0][le] = a4.x; As[lk + 1][le] = a4.y;
        As[lk + 2][le] = a4.z; As[lk + 3][le] = a4.w;
        #pragma unroll
        for (int i = 0; i < 8; i++) {
            int r = wr + 2 * i;
            Ws[r][wc] = Wb_[(size_t)(kl + r) * N + n0 + wc];
        }
        __syncthreads();
        #pragma unroll
        for (int kk = 0; kk < 16; kk++) {
            float4 v0 = *(const float4*)&As[kk][ty * 8];
            float4 v1 = *(const float4*)&As[kk][ty * 8 + 4];
            float a[8] = {v0.x, v0.y, v0.z, v0.w, v1.x, v1.y, v1.z, v1.w};
            float b[4];
            #pragma unroll
            for (int c = 0; c < 4; c++) b[c] = Ws[kk][tx + 32 * c];
            #pragma unroll
            for (int r = 0; r < 8; r++)
                #pragma unroll
                for (int c = 0; c < 4; c++) acc[r][c] = fmaf(a[r], b[c], acc[r][c]);
        }
        __syncthreads();
    }
    #pragma unroll
    for (int r = 0; r < 8; r++) {
        int row = m0 + ty * 8 + r;
        if (row < M) {
            #pragma unroll
            for (int c = 0; c < 4; c++) {
                int col = n0 + tx + 32 * c;
                float v = acc[r][c];
                if (bias) v += bias[col];
                if (act == 1) v = (v >= 0.f) ? v : 0.01f * v;
                C[(size_t)row * N + col] = v;
                if (sum) sum[(size_t)row * N + col] += v;
            }
        }
    }
}

// ---------------- cvec[j] = sum_k W_el[k] * W1[256+k][j] ----------------
__global__ void k_cvec(const float* __restrict__ W_el, const float* __restrict__ W1) {
    int j = blockIdx.x * 256 + threadIdx.x;
    if (j < 512) {
        float s = 0.f;
        #pragma unroll
        for (int k = 0; k < 8; k++) s = fmaf(W_el[k], W1[(size_t)(256 + k) * 512 + j], s);
        g_cvec[j] = s;
    }
}

__global__ void k_init_out() {
    int i = blockIdx.x * 256 + threadIdx.x;
    if (i < NGV * 128) { g_out_w[i] = 0.f; g_out_max[i] = -INFINITY; }
}

// ---------------- fused edge MLP + per-graph reduction ----------------
// per tile of 64 edges (src-CSR order, batch-monotone):
//   h[e,k] = relu(A[src][k] + B[dst][k] + d_e*cvec[k])   (k<512, b1 folded into A)
//   m = h @ W2 + b2 ; w = tanh(m @ Wm + bm)
//   out_w[g] += w*m (segmented) ; out_max[g] = max(m)
__global__ __launch_bounds__(256) void k_edge(
    const float* __restrict__ Al, const float* __restrict__ Bp,
    const float* __restrict__ W2, const float* __restrict__ b2,
    const float* __restrict__ Wm, const float* __restrict__ bm,
    const int* __restrict__ src, const int* __restrict__ dst,
    const float* __restrict__ ea, const int* __restrict__ lbatch)
{
    __shared__ float As[16][68];
    __shared__ float Ws[16][128];
    __shared__ float sm[64][129];
    __shared__ int se_a[64], se_b[64], se_g[64];
    __shared__ float se_d[64];
    __shared__ float cs[512];

    int tid = threadIdx.x;
    int t0 = blockIdx.x * 64;
    if (tid < 64) {
        int slot = t0 + tid;
        if (slot < EV) {
            int e = g_src_edges[slot];
            int s = src[e];
            se_a[tid] = s; se_b[tid] = dst[e];
            se_d[tid] = ea[e];
            se_g[tid] = lbatch[s];
        } else { se_a[tid] = 0; se_b[tid] = 0; se_d[tid] = 0.f; se_g[tid] = -1; }
    }
    for (int i = tid; i < 512; i += 256) cs[i] = g_cvec[i];
    __syncthreads();

    int le = tid >> 2;
    int lk = (tid & 3) * 4;
    const float* arow = Al + (size_t)se_a[le] * 512;
    const float* brow = Bp + (size_t)se_b[le] * 512;
    float dv = se_d[le];

    int ty = tid >> 5, tx = tid & 31;
    int eb = ty * 8;
    int wr = tid >> 7, wc = tid & 127;

    float acc[8][4];
    #pragma unroll
    for (int r = 0; r < 8; r++)
        #pragma unroll
        for (int c = 0; c < 4; c++) acc[r][c] = 0.f;

    // ---- GEMM 1: m = h @ W2, h built on the fly ----
    for (int k = 0; k < 512; k += 16) {
        float4 a4 = *(const float4*)(arow + k + lk);
        float4 b4 = *(const float4*)(brow + k + lk);
        float4 c4 = *(const float4*)(cs + k + lk);
        As[lk + 0][le] = fmaxf(a4.x + b4.x + dv * c4.x, 0.f);
        As[lk + 1][le] = fmaxf(a4.y + b4.y + dv * c4.y, 0.f);
        As[lk + 2][le] = fmaxf(a4.z + b4.z + dv * c4.z, 0.f);
        As[lk + 3][le] = fmaxf(a4.w + b4.w + dv * c4.w, 0.f);
        #pragma unroll
        for (int i = 0; i < 8; i++) {
            int r = wr + 2 * i;
            Ws[r][wc] = W2[(size_t)(k + r) * 128 + wc];
        }
        __syncthreads();
        #pragma unroll
        for (int kk = 0; kk < 16; kk++) {
            float4 v0 = *(const float4*)&As[kk][eb];
            float4 v1 = *(const float4*)&As[kk][eb + 4];
            float a[8] = {v0.x, v0.y, v0.z, v0.w, v1.x, v1.y, v1.z, v1.w};
            float b[4];
            #pragma unroll
            for (int c = 0; c < 4; c++) b[c] = Ws[kk][tx + 32 * c];
            #pragma unroll
            for (int r = 0; r < 8; r++)
                #pragma unroll
                for (int c = 0; c < 4; c++) acc[r][c] = fmaf(a[r], b[c], acc[r][c]);
        }
        __syncthreads();
    }

    // m = acc + b2 ; keep in regs and stage to shared for the second GEMM
    float m[8][4];
    #pragma unroll
    for (int r = 0; r < 8; r++)
        #pragma unroll
        for (int c = 0; c < 4; c++) {
            m[r][c] = acc[r][c] + b2[tx + 32 * c];
            sm[eb + r][tx + 32 * c] = m[r][c];
            acc[r][c] = 0.f;
        }
    __syncthreads();

    // ---- GEMM 2: w = tanh(m @ Wm + bm) ----
    for (int k = 0; k < 128; k += 16) {
        #pragma unroll
        for (int i = 0; i < 8; i++) {
            int r = wr + 2 * i;
            Ws[r][wc] = Wm[(size_t)(k + r) * 128 + wc];
        }
        __syncthreads();
        #pragma unroll
        for (int kk = 0; kk < 16; kk++) {
            float b[4];
            #pragma unroll
            for (int c = 0; c < 4; c++) b[c] = Ws[kk][tx + 32 * c];
            #pragma unroll
            for (int r = 0; r < 8; r++) {
                float a = sm[eb + r][k + kk];
                #pragma unroll
                for (int c = 0; c < 4; c++) acc[r][c] = fmaf(a, b[c], acc[r][c]);
            }
        }
        __syncthreads();
    }

    // ---- segmented per-graph reduction (edges contiguous per thread) ----
    #pragma unroll
    for (int c = 0; c < 4; c++) {
        int col = tx + 32 * c;
        float bmv = bm[col];
        float s = 0.f, mx = -INFINITY;
        int cg = se_g[eb];
        #pragma unroll
        for (int r = 0; r < 8; r++) {
            int g = se_g[eb + r];
            if (g != cg) {
                if (cg >= 0) {
                    atomicAdd(&g_out_w[cg * 128 + col], s);
                    atomicMaxFloat(&g_out_max[cg * 128 + col], mx);
                }
                cg = g; s = 0.f; mx = -INFINITY;
            }
            float w = tanhf(acc[r][c] + bmv);
            s += w * m[r][c];
            mx = fmaxf(mx, m[r][c]);
        }
        if (cg >= 0) {
            atomicAdd(&g_out_w[cg * 128 + col], s);
            atomicMaxFloat(&g_out_max[cg * 128 + col], mx);
        }
    }
}

__global__ void k_final(float* __restrict__ out) {
    int i = blockIdx.x * 256 + threadIdx.x;
    if (i < NGV * 256) {
        int g = i >> 8, j = i & 255;
        float v;
        if (j < 128) v = g_out_w[g * 128 + j];
        else {
            v = g_out_max[g * 128 + j - 128];
            if (!isfinite(v)) v = 0.f;
        }
        out[i] = v;
    }
}

// ---------------- host orchestration ----------------
#define SYM(p, s) do { void* _t = nullptr; cudaGetSymbolAddress(&_t, s); p = (decltype(p))_t; } while (0)

extern "C" void kernel_launch(void* const* d_in, const int* in_sizes, int n_in,
                              void* d_out, int out_size) {
    const float* x_l    = (const float*)d_in[0];
    const float* x_p    = (const float*)d_in[1];
    const float* ea     = (const float*)d_in[2];
    const int*   esrc   = (const int*)  d_in[3];
    const int*   edst   = (const int*)  d_in[4];
    const int*   lbatch = (const int*)  d_in[5];
    const float* W_node = (const float*)d_in[6];
    const float* W_el   = (const float*)d_in[7];
    const float* Wb     = (const float*)d_in[8];
    const float* bb     = (const float*)d_in[9];
    const float* Wn     = (const float*)d_in[10];
    const float* Ws_    = (const float*)d_in[11];
    const float* bconv  = (const float*)d_in[12];
    const float* W1     = (const float*)d_in[13];
    const float* b1     = (const float*)d_in[14];
    const float* W2     = (const float*)d_in[15];
    const float* b2     = (const float*)d_in[16];
    const float* Wm     = (const float*)d_in[17];
    const float* bm     = (const float*)d_in[18];

    float *xl, *xl2, *xlsum, *prel, *xp, *xp2, *xpsum, *prep, *Abuf, *Bbuf;
    int *dcnt, *dptr, *dedges, *scnt, *sptr, *sedges, *stmp, *bsum;
    SYM(xl, g_xl); SYM(xl2, g_xl2); SYM(xlsum, g_xlsum); SYM(prel, g_prel);
    SYM(xp, g_xp); SYM(xp2, g_xp2); SYM(xpsum, g_xpsum); SYM(prep, g_prep);
    SYM(Abuf, g_A); SYM(Bbuf, g_B);
    SYM(dcnt, g_dst_cnt); SYM(dptr, g_dst_ptr); SYM(dedges, g_dst_edges);
    SYM(scnt, g_src_cnt); SYM(sptr, g_src_ptr); SYM(sedges, g_src_edges);
    SYM(stmp, g_scan_tmp); SYM(bsum, g_bsum);

    // node embedding
    k_embed<<<(NLV + 3) / 4, 128>>>(x_l, xl, W_node, NLV);
    k_embed<<<(NPV + 3) / 4, 128>>>(x_p, xp, W_node, NPV);

    // rbf + cvec
    k_rbf<<<(EV + 255) / 256, 256>>>(ea);
    k_cvec<<<2, 256>>>(W_el, W1);

    // CSR (dst and src)
    cudaMemsetAsync(dcnt, 0, NPV * sizeof(int));
    cudaMemsetAsync(scnt, 0, NLV * sizeof(int));
    k_hist<<<(EV + 255) / 256, 256>>>(esrc, edst);
    int nbp = (NPV + 1023) / 1024, nbl = (NLV + 1023) / 1024;
    k_scan1<<<nbp, 1024>>>(dcnt, stmp, bsum, NPV);
    k_scan2<<<1, 1>>>(bsum, nbp);
    k_scan3<<<nbp, 1024>>>(stmp, bsum, dptr, NPV);
    k_scan1<<<nbl, 1024>>>(scnt, stmp, bsum, NLV);
    k_scan2<<<1, 1>>>(bsum, nbl);
    k_scan3<<<nbl, 1024>>>(stmp, bsum, sptr, NLV);
    cudaMemsetAsync(dcnt, 0, NPV * sizeof(int));
    cudaMemsetAsync(scnt, 0, NLV * sizeof(int));
    k_fill<<<(EV + 255) / 256, 256>>>(esrc, edst);

    // running sums
    cudaMemsetAsync(xlsum, 0, (size_t)NLV * 128 * sizeof(float));
    cudaMemsetAsync(xpsum, 0, (size_t)NPV * 128 * sizeof(float));

    // 3 hetero layers
    float *cxl = xl, *cxp = xp, *nxl = xl2, *nxp = xp2;
    for (int l = 0; l < 3; l++) {
        int ilp = 2 * l, ipl = 2 * l + 1;
        // pre_p: protein-side aggregation (dst CSR, partner = src, x = ligand)
        k_agg<<<(NPV * 32 + 255) / 256, 256>>>(dptr, dedges, esrc, cxl,
                Wb + ilp * 1024, bb + ilp * 128, prep, NPV);
        // pre_l: ligand-side aggregation (src CSR, partner = dst, x = protein)
        k_agg<<<(NLV * 32 + 255) / 256, 256>>>(sptr, sedges, edst, cxp,
                Wb + ipl * 1024, bb + ipl * 128, prel, NLV);
        // xp_new = lrelu(xp@Ws + pre_p@Wn + b); xpsum += xp_new
        k_gemm<<<dim3(1, (NPV + 63) / 64), 256>>>(cxp, Ws_ + (size_t)ilp * 16384,
                prep, Wn + (size_t)ilp * 16384, bconv + ilp * 128,
                nxp, xpsum, NPV, 128, 128, 128, 1);
        // xl_new = lrelu(xl@Ws + pre_l@Wn + b); xlsum += xl_new
        k_gemm<<<dim3(1, (NLV + 63) / 64), 256>>>(cxl, Ws_ + (size_t)ipl * 16384,
                prel, Wn + (size_t)ipl * 16384, bconv + ipl * 128,
                nxl, xlsum, NLV, 128, 128, 128, 1);
        float* t;
        t = cxl; cxl = nxl; nxl = t;
        t = cxp; cxp = nxp; nxp = t;
    }

    // edge readout factorization
    k_gemm<<<dim3(4, (NLV + 63) / 64), 256>>>(xlsum, W1, nullptr, nullptr, b1,
            Abuf, nullptr, NLV, 512, 128, 0, 0);
    k_gemm<<<dim3(4, (NPV + 63) / 64), 256>>>(xpsum, W1 + (size_t)128 * 512,
            nullptr, nullptr, nullptr, Bbuf, nullptr, NPV, 512, 128, 0, 0);

    k_init_out<<<(NGV * 128 + 255) / 256, 256>>>();
    k_edge<<<(EV + 63) / 64, 256>>>(Abuf, Bbuf, W2, b2, Wm, bm, esrc, edst, ea, lbatch);
    k_final<<<(NGV * 256 + 255) / 256, 256>>>((float*)d_out);
}

// round 7
// speedup vs baseline: 1.2613x; 1.2613x over previous
#include <cuda_runtime.h>
#include <math.h>

#define NLV 50000
#define NPV 150000
#define EV  500000
#define NGV 256

// ---------------- device-global scratch ----------------
__device__ float g_xl   [NLV*128];
__device__ float g_xl2  [NLV*128];
__device__ float g_xlsum[NLV*128];
__device__ float g_prel [NLV*128];
__device__ float g_xp   [NPV*128];
__device__ float g_xp2  [NPV*128];
__device__ float g_xpsum[NPV*128];
__device__ float g_prep [NPV*128];
__device__ float g_rbf  [EV*8];
__device__ float g_A    [(size_t)NLV*512];
__device__ float g_B    [(size_t)NPV*512];
__device__ float g_cvec [512];
__device__ int   g_dst_cnt[NPV];
__device__ int   g_dst_ptr[NPV+1];
__device__ int   g_dst_edges[EV];
__device__ int   g_src_cnt[NLV];
__device__ int   g_src_ptr[NLV+1];
__device__ int   g_src_edges[EV];
__device__ int   g_scan_tmp[NPV];
__device__ int   g_bsum[512];
__device__ float g_out_w  [NGV*128];
__device__ float g_out_max[NGV*128];

// ---------------- helpers ----------------
__device__ __forceinline__ void atomicMaxFloat(float* addr, float v) {
    if (v >= 0.0f) atomicMax((int*)addr, __float_as_int(v));
    else           atomicMin((unsigned int*)addr, __float_as_uint(v));
}
__device__ __forceinline__ void ffma2(unsigned long long& d,
                                      unsigned long long a,
                                      unsigned long long b) {
    asm("fma.rn.f32x2 %0, %1, %2, %0;" : "+l"(d) : "l"(a), "l"(b));
}
__device__ __forceinline__ float plo(unsigned long long v) {
    return __uint_as_float((unsigned int)v);
}
__device__ __forceinline__ float phi(unsigned long long v) {
    return __uint_as_float((unsigned int)(v >> 32));
}
__device__ __forceinline__ float fast_tanh(float x) {
    float y; asm("tanh.approx.f32 %0, %1;" : "=f"(y) : "f"(x)); return y;
}

// ---------------- node embedding: Y[M,128] = X[M,44] @ Wnode[44,128] ----------
__global__ void k_embed(const float* __restrict__ X, float* __restrict__ Y,
                        const float* __restrict__ Wn, int M) {
    __shared__ float xs[4][44];
    int r0 = blockIdx.x * 4;
    int tid = threadIdx.x;  // 128
    for (int i = tid; i < 4 * 44; i += 128) {
        int rr = i / 44, kk = i % 44;
        xs[rr][kk] = (r0 + rr < M) ? X[(size_t)(r0 + rr) * 44 + kk] : 0.f;
    }
    __syncthreads();
    int col = tid;
    #pragma unroll
    for (int rr = 0; rr < 4; rr++) {
        if (r0 + rr < M) {
            float s = 0.f;
            #pragma unroll
            for (int kk = 0; kk < 44; kk++) s = fmaf(xs[rr][kk], Wn[kk * 128 + col], s);
            Y[(size_t)(r0 + rr) * 128 + col] = s;
        }
    }
}

// ---------------- RBF ----------------
__global__ void k_rbf(const float* __restrict__ ea) {
    int e = blockIdx.x * 256 + threadIdx.x;
    if (e < EV) {
        float d = ea[e];
        #pragma unroll
        for (int k = 0; k < 8; k++) {
            float t = (d - (5.0f / 7.0f) * (float)k) * 1.6f;
            g_rbf[e * 8 + k] = __expf(-t * t);
        }
    }
}

// ---------------- CSR construction ----------------
__global__ void k_hist(const int* __restrict__ src, const int* __restrict__ dst) {
    int e = blockIdx.x * 256 + threadIdx.x;
    if (e < EV) {
        atomicAdd(&g_dst_cnt[dst[e]], 1);
        atomicAdd(&g_src_cnt[src[e]], 1);
    }
}
__global__ void k_scan1(const int* __restrict__ cnt, int* __restrict__ excl,
                        int* __restrict__ bsum, int n) {
    __shared__ int s[1024];
    int i = blockIdx.x * 1024 + threadIdx.x;
    int v = (i < n) ? cnt[i] : 0;
    s[threadIdx.x] = v;
    __syncthreads();
    for (int off = 1; off < 1024; off <<= 1) {
        int t = 0;
        if ((int)threadIdx.x >= off) t = s[threadIdx.x - off];
        __syncthreads();
        s[threadIdx.x] += t;
        __syncthreads();
    }
    if (i < n) excl[i] = s[threadIdx.x] - v;
    if (threadIdx.x == 1023) bsum[blockIdx.x] = s[1023];
}
__global__ void k_scan2(int* bsum, int nb) {
    if (threadIdx.x == 0 && blockIdx.x == 0) {
        int acc = 0;
        for (int b = 0; b < nb; b++) { int t = bsum[b]; bsum[b] = acc; acc += t; }
    }
}
__global__ void k_scan3(const int* __restrict__ excl, const int* __restrict__ bsum,
                        int* __restrict__ ptr, int n) {
    int i = blockIdx.x * 1024 + threadIdx.x;
    if (i < n) ptr[i] = excl[i] + bsum[i >> 10];
    if (i == 0) ptr[n] = EV;
}
__global__ void k_fill(const int* __restrict__ src, const int* __restrict__ dst) {
    int e = blockIdx.x * 256 + threadIdx.x;
    if (e < EV) {
        int d = dst[e]; int p = atomicAdd(&g_dst_cnt[d], 1); g_dst_edges[g_dst_ptr[d] + p] = e;
        int s = src[e]; int q = atomicAdd(&g_src_cnt[s], 1); g_src_edges[g_src_ptr[s] + q] = e;
    }
}

// ---------------- aggregation ----------------
__global__ __launch_bounds__(256) void k_agg(
    const int* __restrict__ ptr, const int* __restrict__ eidx,
    const int* __restrict__ partner, const float* __restrict__ xsrc,
    const float* __restrict__ Wb_i, const float* __restrict__ bb_i,
    float* __restrict__ pre, int n_dst)
{
    int w = (blockIdx.x * blockDim.x + threadIdx.x) >> 5;
    int lane = threadIdx.x & 31;
    if (w >= n_dst) return;
    float wreg[8][4], bias[4], acc[4] = {0.f, 0.f, 0.f, 0.f};
    #pragma unroll
    for (int c = 0; c < 4; c++) {
        bias[c] = bb_i[c * 32 + lane];
        #pragma unroll
        for (int k = 0; k < 8; k++) wreg[k][c] = Wb_i[k * 128 + c * 32 + lane];
    }
    int s = ptr[w], e = ptr[w + 1];
    for (int p = s; p < e; p++) {
        int ed = eidx[p];
        float rv = (lane < 8) ? g_rbf[ed * 8 + lane] : 0.f;
        float r[8];
        #pragma unroll
        for (int k = 0; k < 8; k++) r[k] = __shfl_sync(0xffffffffu, rv, k);
        const float* xr = xsrc + (size_t)partner[ed] * 128;
        #pragma unroll
        for (int c = 0; c < 4; c++) {
            float t = bias[c];
            #pragma unroll
            for (int k = 0; k < 8; k++) t = fmaf(r[k], wreg[k][c], t);
            float sg = 1.f / (1.f + __expf(-t));
            acc[c] += (t * sg) * xr[c * 32 + lane];
        }
    }
    float inv = 1.f / (float)((e - s) > 1 ? (e - s) : 1);
    #pragma unroll
    for (int c = 0; c < 4; c++) pre[(size_t)w * 128 + c * 32 + lane] = acc[c] * inv;
}

// ---------------- generic fused SGEMM (f32x2 inner loop) ----------------
// C[M,N] = act( A0[M,K0]@W0 + A1[M,K1]@W1 + bias ); optional sum += C
// tile 64x128, BK=16, 256 threads, 8x4 micro, K paired along k for fma.rn.f32x2.
__global__ __launch_bounds__(256) void k_gemm(
    const float* __restrict__ A0, const float* __restrict__ W0,
    const float* __restrict__ A1, const float* __restrict__ W1,
    const float* __restrict__ bias, float* __restrict__ C,
    float* __restrict__ sum, int M, int N, int K0, int K1, int act)
{
    __shared__ float2 AsP[8][66];    // [k-pair][row]
    __shared__ float2 WsP[8][128];   // [k-pair][col]
    int tid = threadIdx.x;
    int m0 = blockIdx.y * 64;
    int n0 = blockIdx.x * 128;
    int K = K0 + K1;

    unsigned long long acc[8][4];
    #pragma unroll
    for (int r = 0; r < 8; r++)
        #pragma unroll
        for (int c = 0; c < 4; c++) acc[r][c] = 0ull;

    int le = tid >> 2;
    int lk4 = (tid & 3) * 4;
    int kp0 = lk4 >> 1;
    int arow = m0 + le;
    int ty = tid >> 5, tx = tid & 31, eb = ty * 8;
    int wr = tid >> 7, wc = tid & 127;

    for (int k = 0; k < K; k += 16) {
        const float* Ab; const float* Wb_; int kl; int stride;
        if (k < K0) { Ab = A0; Wb_ = W0; kl = k; stride = K0; }
        else        { Ab = A1; Wb_ = W1; kl = k - K0; stride = K1; }
        float4 a4 = make_float4(0.f, 0.f, 0.f, 0.f);
        if (arow < M) a4 = *(const float4*)(Ab + (size_t)arow * stride + kl + lk4);
        AsP[kp0][le]     = make_float2(a4.x, a4.y);
        AsP[kp0 + 1][le] = make_float2(a4.z, a4.w);
        #pragma unroll
        for (int i = 0; i < 8; i++) {
            int r = wr + 2 * i;
            ((float*)&WsP[i][wc])[wr] = Wb_[(size_t)(kl + r) * N + n0 + wc];
        }
        __syncthreads();
        #pragma unroll
        for (int kp = 0; kp < 8; kp++) {
            unsigned long long a[8], b[4];
            #pragma unroll
            for (int r = 0; r < 8; r++)
                a[r] = *(const unsigned long long*)&AsP[kp][eb + r];
            #pragma unroll
            for (int c = 0; c < 4; c++)
                b[c] = *(const unsigned long long*)&WsP[kp][tx + 32 * c];
            #pragma unroll
            for (int r = 0; r < 8; r++)
                #pragma unroll
                for (int c = 0; c < 4; c++) ffma2(acc[r][c], a[r], b[c]);
        }
        __syncthreads();
    }
    #pragma unroll
    for (int r = 0; r < 8; r++) {
        int row = m0 + eb + r;
        if (row < M) {
            #pragma unroll
            for (int c = 0; c < 4; c++) {
                int col = n0 + tx + 32 * c;
                float v = plo(acc[r][c]) + phi(acc[r][c]);
                if (bias) v += bias[col];
                if (act == 1) v = (v >= 0.f) ? v : 0.01f * v;
                C[(size_t)row * N + col] = v;
                if (sum) sum[(size_t)row * N + col] += v;
            }
        }
    }
}

// ---------------- cvec ----------------
__global__ void k_cvec(const float* __restrict__ W_el, const float* __restrict__ W1) {
    int j = blockIdx.x * 256 + threadIdx.x;
    if (j < 512) {
        float s = 0.f;
        #pragma unroll
        for (int k = 0; k < 8; k++) s = fmaf(W_el[k], W1[(size_t)(256 + k) * 512 + j], s);
        g_cvec[j] = s;
    }
}

__global__ void k_init_out() {
    int i = blockIdx.x * 256 + threadIdx.x;
    if (i < NGV * 128) { g_out_w[i] = 0.f; g_out_max[i] = -INFINITY; }
}

// ---------------- fused edge MLP + per-graph reduction (f32x2) ----------------
__global__ __launch_bounds__(256) void k_edge(
    const float* __restrict__ Al, const float* __restrict__ Bp,
    const float* __restrict__ W2, const float* __restrict__ b2,
    const float* __restrict__ Wm, const float* __restrict__ bm,
    const int* __restrict__ src, const int* __restrict__ dst,
    const float* __restrict__ ea, const int* __restrict__ lbatch)
{
    __shared__ float2 AsP[8][66];
    __shared__ float2 WsP[8][128];
    __shared__ float  smm[64][130];
    __shared__ int se_a[64], se_b[64], se_g[64];
    __shared__ float se_d[64];
    __shared__ float cs[512];

    int tid = threadIdx.x;
    int t0 = blockIdx.x * 64;
    if (tid < 64) {
        int slot = t0 + tid;
        if (slot < EV) {
            int e = g_src_edges[slot];
            int s = src[e];
            se_a[tid] = s; se_b[tid] = dst[e];
            se_d[tid] = ea[e];
            se_g[tid] = lbatch[s];
        } else { se_a[tid] = 0; se_b[tid] = 0; se_d[tid] = 0.f; se_g[tid] = -1; }
    }
    for (int i = tid; i < 512; i += 256) cs[i] = g_cvec[i];
    __syncthreads();

    int le = tid >> 2;
    int lk4 = (tid & 3) * 4;
    int kp0 = lk4 >> 1;
    const float* arow = Al + (size_t)se_a[le] * 512;
    const float* brow = Bp + (size_t)se_b[le] * 512;
    float dv = se_d[le];

    int ty = tid >> 5, tx = tid & 31, eb = ty * 8;
    int wr = tid >> 7, wc = tid & 127;

    unsigned long long acc[8][4];
    #pragma unroll
    for (int r = 0; r < 8; r++)
        #pragma unroll
        for (int c = 0; c < 4; c++) acc[r][c] = 0ull;

    // ---- GEMM 1: m = relu(A[src]+B[dst]+d*cvec) @ W2 ----
    for (int k = 0; k < 512; k += 16) {
        float4 a4 = *(const float4*)(arow + k + lk4);
        float4 b4 = *(const float4*)(brow + k + lk4);
        float4 c4 = *(const float4*)(cs + k + lk4);
        float h0 = fmaxf(a4.x + b4.x + dv * c4.x, 0.f);
        float h1 = fmaxf(a4.y + b4.y + dv * c4.y, 0.f);
        float h2 = fmaxf(a4.z + b4.z + dv * c4.z, 0.f);
        float h3 = fmaxf(a4.w + b4.w + dv * c4.w, 0.f);
        AsP[kp0][le]     = make_float2(h0, h1);
        AsP[kp0 + 1][le] = make_float2(h2, h3);
        #pragma unroll
        for (int i = 0; i < 8; i++) {
            int r = wr + 2 * i;
            ((float*)&WsP[i][wc])[wr] = W2[(size_t)(k + r) * 128 + wc];
        }
        __syncthreads();
        #pragma unroll
        for (int kp = 0; kp < 8; kp++) {
            unsigned long long a[8], b[4];
            #pragma unroll
            for (int r = 0; r < 8; r++)
                a[r] = *(const unsigned long long*)&AsP[kp][eb + r];
            #pragma unroll
            for (int c = 0; c < 4; c++)
                b[c] = *(const unsigned long long*)&WsP[kp][tx + 32 * c];
            #pragma unroll
            for (int r = 0; r < 8; r++)
                #pragma unroll
                for (int c = 0; c < 4; c++) ffma2(acc[r][c], a[r], b[c]);
        }
        __syncthreads();
    }

    // m = acc + b2 ; keep in regs, stage to shared (even stride 130)
    float m[8][4];
    #pragma unroll
    for (int r = 0; r < 8; r++)
        #pragma unroll
        for (int c = 0; c < 4; c++) {
            float v = plo(acc[r][c]) + phi(acc[r][c]) + b2[tx + 32 * c];
            m[r][c] = v;
            smm[eb + r][tx + 32 * c] = v;
            acc[r][c] = 0ull;
        }

    // ---- GEMM 2: w = tanh(m @ Wm + bm) ----
    for (int k = 0; k < 128; k += 16) {
        #pragma unroll
        for (int i = 0; i < 8; i++) {
            int r = wr + 2 * i;
            ((float*)&WsP[i][wc])[wr] = Wm[(size_t)(k + r) * 128 + wc];
        }
        __syncthreads();
        #pragma unroll
        for (int kp = 0; kp < 8; kp++) {
            unsigned long long a[8], b[4];
            #pragma unroll
            for (int c = 0; c < 4; c++)
                b[c] = *(const unsigned long long*)&WsP[kp][tx + 32 * c];
            #pragma unroll
            for (int r = 0; r < 8; r++)
                a[r] = *(const unsigned long long*)&smm[eb + r][k + 2 * kp];
            #pragma unroll
            for (int r = 0; r < 8; r++)
                #pragma unroll
                for (int c = 0; c < 4; c++) ffma2(acc[r][c], a[r], b[c]);
        }
        __syncthreads();
    }

    // ---- segmented per-graph reduction ----
    #pragma unroll
    for (int c = 0; c < 4; c++) {
        int col = tx + 32 * c;
        float bmv = bm[col];
        float s = 0.f, mx = -INFINITY;
        int cg = se_g[eb];
        #pragma unroll
        for (int r = 0; r < 8; r++) {
            int g = se_g[eb + r];
            if (g != cg) {
                if (cg >= 0) {
                    atomicAdd(&g_out_w[cg * 128 + col], s);
                    atomicMaxFloat(&g_out_max[cg * 128 + col], mx);
                }
                cg = g; s = 0.f; mx = -INFINITY;
            }
            float w = fast_tanh(plo(acc[r][c]) + phi(acc[r][c]) + bmv);
            s += w * m[r][c];
            mx = fmaxf(mx, m[r][c]);
        }
        if (cg >= 0) {
            atomicAdd(&g_out_w[cg * 128 + col], s);
            atomicMaxFloat(&g_out_max[cg * 128 + col], mx);
        }
    }
}

__global__ void k_final(float* __restrict__ out) {
    int i = blockIdx.x * 256 + threadIdx.x;
    if (i < NGV * 256) {
        int g = i >> 8, j = i & 255;
        float v;
        if (j < 128) v = g_out_w[g * 128 + j];
        else {
            v = g_out_max[g * 128 + j - 128];
            if (!isfinite(v)) v = 0.f;
        }
        out[i] = v;
    }
}

// ---------------- host orchestration ----------------
#define SYM(p, s) do { void* _t = nullptr; cudaGetSymbolAddress(&_t, s); p = (decltype(p))_t; } while (0)

extern "C" void kernel_launch(void* const* d_in, const int* in_sizes, int n_in,
                              void* d_out, int out_size) {
    const float* x_l    = (const float*)d_in[0];
    const float* x_p    = (const float*)d_in[1];
    const float* ea     = (const float*)d_in[2];
    const int*   esrc   = (const int*)  d_in[3];
    const int*   edst   = (const int*)  d_in[4];
    const int*   lbatch = (const int*)  d_in[5];
    const float* W_node = (const float*)d_in[6];
    const float* W_el   = (const float*)d_in[7];
    const float* Wb     = (const float*)d_in[8];
    const float* bb     = (const float*)d_in[9];
    const float* Wn     = (const float*)d_in[10];
    const float* Ws_    = (const float*)d_in[11];
    const float* bconv  = (const float*)d_in[12];
    const float* W1     = (const float*)d_in[13];
    const float* b1     = (const float*)d_in[14];
    const float* W2     = (const float*)d_in[15];
    const float* b2     = (const float*)d_in[16];
    const float* Wm     = (const float*)d_in[17];
    const float* bm     = (const float*)d_in[18];

    float *xl, *xl2, *xlsum, *prel, *xp, *xp2, *xpsum, *prep, *Abuf, *Bbuf;
    int *dcnt, *dptr, *dedges, *scnt, *sptr, *sedges, *stmp, *bsum;
    SYM(xl, g_xl); SYM(xl2, g_xl2); SYM(xlsum, g_xlsum); SYM(prel, g_prel);
    SYM(xp, g_xp); SYM(xp2, g_xp2); SYM(xpsum, g_xpsum); SYM(prep, g_prep);
    SYM(Abuf, g_A); SYM(Bbuf, g_B);
    SYM(dcnt, g_dst_cnt); SYM(dptr, g_dst_ptr); SYM(dedges, g_dst_edges);
    SYM(scnt, g_src_cnt); SYM(sptr, g_src_ptr); SYM(sedges, g_src_edges);
    SYM(stmp, g_scan_tmp); SYM(bsum, g_bsum);

    // node embedding
    k_embed<<<(NLV + 3) / 4, 128>>>(x_l, xl, W_node, NLV);
    k_embed<<<(NPV + 3) / 4, 128>>>(x_p, xp, W_node, NPV);

    // rbf + cvec
    k_rbf<<<(EV + 255) / 256, 256>>>(ea);
    k_cvec<<<2, 256>>>(W_el, W1);

    // CSR (dst and src)
    cudaMemsetAsync(dcnt, 0, NPV * sizeof(int));
    cudaMemsetAsync(scnt, 0, NLV * sizeof(int));
    k_hist<<<(EV + 255) / 256, 256>>>(esrc, edst);
    int nbp = (NPV + 1023) / 1024, nbl = (NLV + 1023) / 1024;
    k_scan1<<<nbp, 1024>>>(dcnt, stmp, bsum, NPV);
    k_scan2<<<1, 1>>>(bsum, nbp);
    k_scan3<<<nbp, 1024>>>(stmp, bsum, dptr, NPV);
    k_scan1<<<nbl, 1024>>>(scnt, stmp, bsum, NLV);
    k_scan2<<<1, 1>>>(bsum, nbl);
    k_scan3<<<nbl, 1024>>>(stmp, bsum, sptr, NLV);
    cudaMemsetAsync(dcnt, 0, NPV * sizeof(int));
    cudaMemsetAsync(scnt, 0, NLV * sizeof(int));
    k_fill<<<(EV + 255) / 256, 256>>>(esrc, edst);

    // running sums
    cudaMemsetAsync(xlsum, 0, (size_t)NLV * 128 * sizeof(float));
    cudaMemsetAsync(xpsum, 0, (size_t)NPV * 128 * sizeof(float));

    // 3 hetero layers
    float *cxl = xl, *cxp = xp, *nxl = xl2, *nxp = xp2;
    for (int l = 0; l < 3; l++) {
        int ilp = 2 * l, ipl = 2 * l + 1;
        k_agg<<<(NPV * 32 + 255) / 256, 256>>>(dptr, dedges, esrc, cxl,
                Wb + ilp * 1024, bb + ilp * 128, prep, NPV);
        k_agg<<<(NLV * 32 + 255) / 256, 256>>>(sptr, sedges, edst, cxp,
                Wb + ipl * 1024, bb + ipl * 128, prel, NLV);
        k_gemm<<<dim3(1, (NPV + 63) / 64), 256>>>(cxp, Ws_ + (size_t)ilp * 16384,
                prep, Wn + (size_t)ilp * 16384, bconv + ilp * 128,
                nxp, xpsum, NPV, 128, 128, 128, 1);
        k_gemm<<<dim3(1, (NLV + 63) / 64), 256>>>(cxl, Ws_ + (size_t)ipl * 16384,
                prel, Wn + (size_t)ipl * 16384, bconv + ipl * 128,
                nxl, xlsum, NLV, 128, 128, 128, 1);
        float* t;
        t = cxl; cxl = nxl; nxl = t;
        t = cxp; cxp = nxp; nxp = t;
    }

    // edge readout factorization
    k_gemm<<<dim3(4, (NLV + 63) / 64), 256>>>(xlsum, W1, nullptr, nullptr, b1,
            Abuf, nullptr, NLV, 512, 128, 0, 0);
    k_gemm<<<dim3(4, (NPV + 63) / 64), 256>>>(xpsum, W1 + (size_t)128 * 512,
            nullptr, nullptr, nullptr, Bbuf, nullptr, NPV, 512, 128, 0, 0);

    k_init_out<<<(NGV * 128 + 255) / 256, 256>>>();
    k_edge<<<(EV + 63) / 64, 256>>>(Abuf, Bbuf, W2, b2, Wm, bm, esrc, edst, ea, lbatch);
    k_final<<<(NGV * 256 + 255) / 256, 256>>>((float*)d_out);
}

// round 8
// speedup vs baseline: 1.5332x; 1.2156x over previous
#include <cuda_runtime.h>
#include <math.h>

#define NLV 50000
#define NPV 150000
#define EV  500000
#define NGV 256

// ---------------- device-global scratch ----------------
__device__ float g_xl   [NLV*128];
__device__ float g_xl2  [NLV*128];
__device__ float g_xlsum[NLV*128];
__device__ float g_prel [NLV*128];
__device__ float g_xp   [NPV*128];
__device__ float g_xp2  [NPV*128];
__device__ float g_xpsum[NPV*128];
__device__ float g_prep [NPV*128];
__device__ float g_rbf  [EV*8];
__device__ float g_A    [(size_t)NLV*512];
__device__ float g_B    [(size_t)NPV*512];
__device__ float g_cvec [512];
__device__ int   g_dst_cnt[NPV];
__device__ int   g_dst_ptr[NPV+1];
__device__ int   g_dst_edges[EV];
__device__ int   g_src_cnt[NLV];
__device__ int   g_src_ptr[NLV+1];
__device__ int   g_src_edges[EV];
__device__ int   g_scan_tmp[NPV];
__device__ int   g_bsum[512];
__device__ float g_out_w  [NGV*128];
__device__ float g_out_max[NGV*128];

// ---------------- helpers ----------------
__device__ __forceinline__ void atomicMaxFloat(float* addr, float v) {
    if (v >= 0.0f) atomicMax((int*)addr, __float_as_int(v));
    else           atomicMin((unsigned int*)addr, __float_as_uint(v));
}
__device__ __forceinline__ float fast_tanh(float x) {
    float y; asm("tanh.approx.f32 %0, %1;" : "=f"(y) : "f"(x)); return y;
}

// ---------------- node embedding ----------------
__global__ void k_embed(const float* __restrict__ X, float* __restrict__ Y,
                        const float* __restrict__ Wn, int M) {
    __shared__ float xs[4][44];
    int r0 = blockIdx.x * 4;
    int tid = threadIdx.x;  // 128
    for (int i = tid; i < 4 * 44; i += 128) {
        int rr = i / 44, kk = i % 44;
        xs[rr][kk] = (r0 + rr < M) ? X[(size_t)(r0 + rr) * 44 + kk] : 0.f;
    }
    __syncthreads();
    int col = tid;
    #pragma unroll
    for (int rr = 0; rr < 4; rr++) {
        if (r0 + rr < M) {
            float s = 0.f;
            #pragma unroll
            for (int kk = 0; kk < 44; kk++) s = fmaf(xs[rr][kk], Wn[kk * 128 + col], s);
            Y[(size_t)(r0 + rr) * 128 + col] = s;
        }
    }
}

// ---------------- RBF ----------------
__global__ void k_rbf(const float* __restrict__ ea) {
    int e = blockIdx.x * 256 + threadIdx.x;
    if (e < EV) {
        float d = ea[e];
        #pragma unroll
        for (int k = 0; k < 8; k++) {
            float t = (d - (5.0f / 7.0f) * (float)k) * 1.6f;
            g_rbf[e * 8 + k] = __expf(-t * t);
        }
    }
}

// ---------------- CSR construction ----------------
__global__ void k_hist(const int* __restrict__ src, const int* __restrict__ dst) {
    int e = blockIdx.x * 256 + threadIdx.x;
    if (e < EV) {
        atomicAdd(&g_dst_cnt[dst[e]], 1);
        atomicAdd(&g_src_cnt[src[e]], 1);
    }
}
__global__ void k_scan1(const int* __restrict__ cnt, int* __restrict__ excl,
                        int* __restrict__ bsum, int n) {
    __shared__ int s[1024];
    int i = blockIdx.x * 1024 + threadIdx.x;
    int v = (i < n) ? cnt[i] : 0;
    s[threadIdx.x] = v;
    __syncthreads();
    for (int off = 1; off < 1024; off <<= 1) {
        int t = 0;
        if ((int)threadIdx.x >= off) t = s[threadIdx.x - off];
        __syncthreads();
        s[threadIdx.x] += t;
        __syncthreads();
    }
    if (i < n) excl[i] = s[threadIdx.x] - v;
    if (threadIdx.x == 1023) bsum[blockIdx.x] = s[1023];
}
__global__ void k_scan2(int* bsum, int nb) {
    if (threadIdx.x == 0 && blockIdx.x == 0) {
        int acc = 0;
        for (int b = 0; b < nb; b++) { int t = bsum[b]; bsum[b] = acc; acc += t; }
    }
}
__global__ void k_scan3(const int* __restrict__ excl, const int* __restrict__ bsum,
                        int* __restrict__ ptr, int n) {
    int i = blockIdx.x * 1024 + threadIdx.x;
    if (i < n) ptr[i] = excl[i] + bsum[i >> 10];
    if (i == 0) ptr[n] = EV;
}
__global__ void k_fill(const int* __restrict__ src, const int* __restrict__ dst) {
    int e = blockIdx.x * 256 + threadIdx.x;
    if (e < EV) {
        int d = dst[e]; int p = atomicAdd(&g_dst_cnt[d], 1); g_dst_edges[g_dst_ptr[d] + p] = e;
        int s = src[e]; int q = atomicAdd(&g_src_cnt[s], 1); g_src_edges[g_src_ptr[s] + q] = e;
    }
}

// ---------------- aggregation ----------------
__global__ __launch_bounds__(256) void k_agg(
    const int* __restrict__ ptr, const int* __restrict__ eidx,
    const int* __restrict__ partner, const float* __restrict__ xsrc,
    const float* __restrict__ Wb_i, const float* __restrict__ bb_i,
    float* __restrict__ pre, int n_dst)
{
    int w = (blockIdx.x * blockDim.x + threadIdx.x) >> 5;
    int lane = threadIdx.x & 31;
    if (w >= n_dst) return;
    float wreg[8][4], bias[4], acc[4] = {0.f, 0.f, 0.f, 0.f};
    #pragma unroll
    for (int c = 0; c < 4; c++) {
        bias[c] = bb_i[c * 32 + lane];
        #pragma unroll
        for (int k = 0; k < 8; k++) wreg[k][c] = Wb_i[k * 128 + c * 32 + lane];
    }
    int s = ptr[w], e = ptr[w + 1];
    for (int p = s; p < e; p++) {
        int ed = eidx[p];
        float rv = (lane < 8) ? g_rbf[ed * 8 + lane] : 0.f;
        float r[8];
        #pragma unroll
        for (int k = 0; k < 8; k++) r[k] = __shfl_sync(0xffffffffu, rv, k);
        const float* xr = xsrc + (size_t)partner[ed] * 128;
        #pragma unroll
        for (int c = 0; c < 4; c++) {
            float t = bias[c];
            #pragma unroll
            for (int k = 0; k < 8; k++) t = fmaf(r[k], wreg[k][c], t);
            float sg = 1.f / (1.f + __expf(-t));
            acc[c] += (t * sg) * xr[c * 32 + lane];
        }
    }
    float inv = 1.f / (float)((e - s) > 1 ? (e - s) : 1);
    #pragma unroll
    for (int c = 0; c < 4; c++) pre[(size_t)w * 128 + c * 32 + lane] = acc[c] * inv;
}

// ---------------- fused SGEMM: 128x128 tile, BK=16, 8x8 micro ----------------
// C[M,N] = act( A0[M,K0]@W0 + A1[M,K1]@W1 + bias ); optional sum += C
__global__ __launch_bounds__(256, 2) void k_gemm(
    const float* __restrict__ A0, const float* __restrict__ W0,
    const float* __restrict__ A1, const float* __restrict__ W1,
    const float* __restrict__ bias, float* __restrict__ C,
    float* __restrict__ sum, int M, int N, int K0, int K1, int act)
{
    __shared__ float As[16 * 132];
    __shared__ float Ws[16 * 132];
    int tid = threadIdx.x;
    int m0 = blockIdx.y * 128;
    int n0 = blockIdx.x * 128;
    int K = K0 + K1;

    float acc[8][8];
    #pragma unroll
    for (int r = 0; r < 8; r++)
        #pragma unroll
        for (int c = 0; c < 8; c++) acc[r][c] = 0.f;

    int le  = tid >> 1;            // 0..127  (A row within tile)
    int lk8 = (tid & 1) * 8;       // 0 or 8  (k offset)
    int arow = m0 + le;
    int wrow = tid >> 4;           // 0..15
    int wcol = (tid & 15) * 8;     // 0..120
    int rb = (tid >> 4) * 8;       // 0..120 (output row base)
    int cb = (tid & 15) * 8;       // 0..120 (output col base)

    for (int k = 0; k < K; k += 16) {
        const float* Ab; const float* Wb_; int kl; int stride;
        if (k < K0) { Ab = A0; Wb_ = W0; kl = k; stride = K0; }
        else        { Ab = A1; Wb_ = W1; kl = k - K0; stride = K1; }
        float4 a0 = make_float4(0.f,0.f,0.f,0.f), a1 = a0;
        if (arow < M) {
            const float* p = Ab + (size_t)arow * stride + kl + lk8;
            a0 = *(const float4*)p; a1 = *(const float4*)(p + 4);
        }
        As[(lk8 + 0) * 132 + le] = a0.x; As[(lk8 + 1) * 132 + le] = a0.y;
        As[(lk8 + 2) * 132 + le] = a0.z; As[(lk8 + 3) * 132 + le] = a0.w;
        As[(lk8 + 4) * 132 + le] = a1.x; As[(lk8 + 5) * 132 + le] = a1.y;
        As[(lk8 + 6) * 132 + le] = a1.z; As[(lk8 + 7) * 132 + le] = a1.w;
        {
            const float* p = Wb_ + (size_t)(kl + wrow) * N + n0 + wcol;
            float4 w0 = *(const float4*)p, w1 = *(const float4*)(p + 4);
            *(float4*)(Ws + wrow * 132 + wcol) = w0;
            *(float4*)(Ws + wrow * 132 + wcol + 4) = w1;
        }
        __syncthreads();
        #pragma unroll
        for (int kk = 0; kk < 16; kk++) {
            float4 av0 = *(const float4*)(As + kk * 132 + rb);
            float4 av1 = *(const float4*)(As + kk * 132 + rb + 4);
            float4 bv0 = *(const float4*)(Ws + kk * 132 + cb);
            float4 bv1 = *(const float4*)(Ws + kk * 132 + cb + 4);
            float a[8] = {av0.x, av0.y, av0.z, av0.w, av1.x, av1.y, av1.z, av1.w};
            float b[8] = {bv0.x, bv0.y, bv0.z, bv0.w, bv1.x, bv1.y, bv1.z, bv1.w};
            #pragma unroll
            for (int r = 0; r < 8; r++)
                #pragma unroll
                for (int c = 0; c < 8; c++) acc[r][c] = fmaf(a[r], b[c], acc[r][c]);
        }
        __syncthreads();
    }
    float bv[8];
    if (bias) {
        *(float4*)bv       = *(const float4*)(bias + n0 + cb);
        *(float4*)(bv + 4) = *(const float4*)(bias + n0 + cb + 4);
    } else {
        #pragma unroll
        for (int c = 0; c < 8; c++) bv[c] = 0.f;
    }
    #pragma unroll
    for (int r = 0; r < 8; r++) {
        int row = m0 + rb + r;
        if (row < M) {
            float v[8];
            #pragma unroll
            for (int c = 0; c < 8; c++) {
                float t = acc[r][c] + bv[c];
                if (act == 1) t = (t >= 0.f) ? t : 0.01f * t;
                v[c] = t;
            }
            float* cp = C + (size_t)row * N + n0 + cb;
            *(float4*)cp = *(float4*)v;
            *(float4*)(cp + 4) = *(float4*)(v + 4);
            if (sum) {
                float* sp = sum + (size_t)row * N + n0 + cb;
                float4 s0 = *(float4*)sp, s1 = *(float4*)(sp + 4);
                s0.x += v[0]; s0.y += v[1]; s0.z += v[2]; s0.w += v[3];
                s1.x += v[4]; s1.y += v[5]; s1.z += v[6]; s1.w += v[7];
                *(float4*)sp = s0; *(float4*)(sp + 4) = s1;
            }
        }
    }
}

// ---------------- cvec ----------------
__global__ void k_cvec(const float* __restrict__ W_el, const float* __restrict__ W1) {
    int j = blockIdx.x * 256 + threadIdx.x;
    if (j < 512) {
        float s = 0.f;
        #pragma unroll
        for (int k = 0; k < 8; k++) s = fmaf(W_el[k], W1[(size_t)(256 + k) * 512 + j], s);
        g_cvec[j] = s;
    }
}

__global__ void k_init_out() {
    int i = blockIdx.x * 256 + threadIdx.x;
    if (i < NGV * 128) { g_out_w[i] = 0.f; g_out_max[i] = -INFINITY; }
}

// ---------------- fused edge MLP + per-graph reduction: 128-edge tiles ------------
// dynamic smem layout (floats):
//   As   [16*132]    @ 0
//   Ws   [16*132]    @ 2112
//   smm  [128*132]   @ 4224
//   cs   [512]       @ 21120
//   se_d [128]       @ 21632
//   se_a [128] (int) @ 21760
//   se_b [128] (int) @ 21888
//   se_g [128] (int) @ 22016
#define EDGE_SMEM_FLOATS 22144
__global__ __launch_bounds__(256, 2) void k_edge(
    const float* __restrict__ Al, const float* __restrict__ Bp,
    const float* __restrict__ W2, const float* __restrict__ b2,
    const float* __restrict__ Wm, const float* __restrict__ bm,
    const int* __restrict__ src, const int* __restrict__ dst,
    const float* __restrict__ ea, const int* __restrict__ lbatch)
{
    extern __shared__ float dynsm[];
    float* As   = dynsm;
    float* Ws   = dynsm + 2112;
    float* smm  = dynsm + 4224;
    float* cs   = dynsm + 21120;
    float* se_d = dynsm + 21632;
    int*   se_a = (int*)(dynsm + 21760);
    int*   se_b = (int*)(dynsm + 21888);
    int*   se_g = (int*)(dynsm + 22016);

    int tid = threadIdx.x;
    int t0 = blockIdx.x * 128;
    if (tid < 128) {
        int slot = t0 + tid;
        if (slot < EV) {
            int e = g_src_edges[slot];
            int s = src[e];
            se_a[tid] = s; se_b[tid] = dst[e];
            se_d[tid] = ea[e];
            se_g[tid] = lbatch[s];
        } else { se_a[tid] = 0; se_b[tid] = 0; se_d[tid] = 0.f; se_g[tid] = -1; }
    }
    for (int i = tid; i < 512; i += 256) cs[i] = g_cvec[i];
    __syncthreads();

    int le  = tid >> 1;
    int lk8 = (tid & 1) * 8;
    const float* arow = Al + (size_t)se_a[le] * 512;
    const float* brow = Bp + (size_t)se_b[le] * 512;
    float dv = se_d[le];
    int wrow = tid >> 4;
    int wcol = (tid & 15) * 8;
    int rb = (tid >> 4) * 8;
    int cb = (tid & 15) * 8;

    float acc[8][8];
    #pragma unroll
    for (int r = 0; r < 8; r++)
        #pragma unroll
        for (int c = 0; c < 8; c++) acc[r][c] = 0.f;

    // ---- GEMM 1: m = relu(A[src]+B[dst]+d*cvec) @ W2 ----
    for (int k = 0; k < 512; k += 16) {
        const float* pa = arow + k + lk8;
        const float* pb = brow + k + lk8;
        float4 a0 = *(const float4*)pa, a1 = *(const float4*)(pa + 4);
        float4 b0 = *(const float4*)pb, b1 = *(const float4*)(pb + 4);
        float4 c0 = *(const float4*)(cs + k + lk8), c1 = *(const float4*)(cs + k + lk8 + 4);
        As[(lk8 + 0) * 132 + le] = fmaxf(a0.x + b0.x + dv * c0.x, 0.f);
        As[(lk8 + 1) * 132 + le] = fmaxf(a0.y + b0.y + dv * c0.y, 0.f);
        As[(lk8 + 2) * 132 + le] = fmaxf(a0.z + b0.z + dv * c0.z, 0.f);
        As[(lk8 + 3) * 132 + le] = fmaxf(a0.w + b0.w + dv * c0.w, 0.f);
        As[(lk8 + 4) * 132 + le] = fmaxf(a1.x + b1.x + dv * c1.x, 0.f);
        As[(lk8 + 5) * 132 + le] = fmaxf(a1.y + b1.y + dv * c1.y, 0.f);
        As[(lk8 + 6) * 132 + le] = fmaxf(a1.z + b1.z + dv * c1.z, 0.f);
        As[(lk8 + 7) * 132 + le] = fmaxf(a1.w + b1.w + dv * c1.w, 0.f);
        {
            const float* p = W2 + (size_t)(k + wrow) * 128 + wcol;
            float4 w0 = *(const float4*)p, w1 = *(const float4*)(p + 4);
            *(float4*)(Ws + wrow * 132 + wcol) = w0;
            *(float4*)(Ws + wrow * 132 + wcol + 4) = w1;
        }
        __syncthreads();
        #pragma unroll
        for (int kk = 0; kk < 16; kk++) {
            float4 av0 = *(const float4*)(As + kk * 132 + rb);
            float4 av1 = *(const float4*)(As + kk * 132 + rb + 4);
            float4 bv0 = *(const float4*)(Ws + kk * 132 + cb);
            float4 bv1 = *(const float4*)(Ws + kk * 132 + cb + 4);
            float a[8] = {av0.x, av0.y, av0.z, av0.w, av1.x, av1.y, av1.z, av1.w};
            float b[8] = {bv0.x, bv0.y, bv0.z, bv0.w, bv1.x, bv1.y, bv1.z, bv1.w};
            #pragma unroll
            for (int r = 0; r < 8; r++)
                #pragma unroll
                for (int c = 0; c < 8; c++) acc[r][c] = fmaf(a[r], b[c], acc[r][c]);
        }
        __syncthreads();
    }

    // m = acc + b2 -> smm
    {
        float bv[8];
        *(float4*)bv       = *(const float4*)(b2 + cb);
        *(float4*)(bv + 4) = *(const float4*)(b2 + cb + 4);
        #pragma unroll
        for (int r = 0; r < 8; r++) {
            float v[8];
            #pragma unroll
            for (int c = 0; c < 8; c++) { v[c] = acc[r][c] + bv[c]; acc[r][c] = 0.f; }
            float* p = smm + (rb + r) * 132 + cb;
            *(float4*)p = *(float4*)v;
            *(float4*)(p + 4) = *(float4*)(v + 4);
        }
    }
    __syncthreads();

    // ---- GEMM 2: w = tanh(m @ Wm + bm) ----
    for (int k = 0; k < 128; k += 16) {
        {
            const float* p = Wm + (size_t)(k + wrow) * 128 + wcol;
            float4 w0 = *(const float4*)p, w1 = *(const float4*)(p + 4);
            *(float4*)(Ws + wrow * 132 + wcol) = w0;
            *(float4*)(Ws + wrow * 132 + wcol + 4) = w1;
        }
        __syncthreads();
        #pragma unroll
        for (int kk = 0; kk < 16; kk++) {
            float a[8];
            #pragma unroll
            for (int r = 0; r < 8; r++) a[r] = smm[(rb + r) * 132 + k + kk];
            float4 bv0 = *(const float4*)(Ws + kk * 132 + cb);
            float4 bv1 = *(const float4*)(Ws + kk * 132 + cb + 4);
            float b[8] = {bv0.x, bv0.y, bv0.z, bv0.w, bv1.x, bv1.y, bv1.z, bv1.w};
            #pragma unroll
            for (int r = 0; r < 8; r++)
                #pragma unroll
                for (int c = 0; c < 8; c++) acc[r][c] = fmaf(a[r], b[c], acc[r][c]);
        }
        __syncthreads();
    }

    // ---- segmented per-graph reduction (rows = consecutive sorted edges) ----
    {
        float bmr[8];
        *(float4*)bmr       = *(const float4*)(bm + cb);
        *(float4*)(bmr + 4) = *(const float4*)(bm + cb + 4);
        #pragma unroll
        for (int c = 0; c < 8; c++) {
            int col = cb + c;
            float s = 0.f, mx = -INFINITY;
            int cg = se_g[rb];
            #pragma unroll
            for (int r = 0; r < 8; r++) {
                int g = se_g[rb + r];
                if (g != cg) {
                    if (cg >= 0) {
                        atomicAdd(&g_out_w[cg * 128 + col], s);
                        atomicMaxFloat(&g_out_max[cg * 128 + col], mx);
                    }
                    cg = g; s = 0.f; mx = -INFINITY;
                }
                float mv = smm[(rb + r) * 132 + col];
                float w = fast_tanh(acc[r][c] + bmr[c]);
                s += w * mv;
                mx = fmaxf(mx, mv);
            }
            if (cg >= 0) {
                atomicAdd(&g_out_w[cg * 128 + col], s);
                atomicMaxFloat(&g_out_max[cg * 128 + col], mx);
            }
        }
    }
}

__global__ void k_final(float* __restrict__ out) {
    int i = blockIdx.x * 256 + threadIdx.x;
    if (i < NGV * 256) {
        int g = i >> 8, j = i & 255;
        float v;
        if (j < 128) v = g_out_w[g * 128 + j];
        else {
            v = g_out_max[g * 128 + j - 128];
            if (!isfinite(v)) v = 0.f;
        }
        out[i] = v;
    }
}

// ---------------- host orchestration ----------------
#define SYM(p, s) do { void* _t = nullptr; cudaGetSymbolAddress(&_t, s); p = (decltype(p))_t; } while (0)

extern "C" void kernel_launch(void* const* d_in, const int* in_sizes, int n_in,
                              void* d_out, int out_size) {
    const float* x_l    = (const float*)d_in[0];
    const float* x_p    = (const float*)d_in[1];
    const float* ea     = (const float*)d_in[2];
    const int*   esrc   = (const int*)  d_in[3];
    const int*   edst   = (const int*)  d_in[4];
    const int*   lbatch = (const int*)  d_in[5];
    const float* W_node = (const float*)d_in[6];
    const float* W_el   = (const float*)d_in[7];
    const float* Wb     = (const float*)d_in[8];
    const float* bb     = (const float*)d_in[9];
    const float* Wn     = (const float*)d_in[10];
    const float* Ws_    = (const float*)d_in[11];
    const float* bconv  = (const float*)d_in[12];
    const float* W1     = (const float*)d_in[13];
    const float* b1     = (const float*)d_in[14];
    const float* W2     = (const float*)d_in[15];
    const float* b2     = (const float*)d_in[16];
    const float* Wm     = (const float*)d_in[17];
    const float* bm     = (const float*)d_in[18];

    float *xl, *xl2, *xlsum, *prel, *xp, *xp2, *xpsum, *prep, *Abuf, *Bbuf;
    int *dcnt, *dptr, *dedges, *scnt, *sptr, *sedges, *stmp, *bsum;
    SYM(xl, g_xl); SYM(xl2, g_xl2); SYM(xlsum, g_xlsum); SYM(prel, g_prel);
    SYM(xp, g_xp); SYM(xp2, g_xp2); SYM(xpsum, g_xpsum); SYM(prep, g_prep);
    SYM(Abuf, g_A); SYM(Bbuf, g_B);
    SYM(dcnt, g_dst_cnt); SYM(dptr, g_dst_ptr); SYM(dedges, g_dst_edges);
    SYM(scnt, g_src_cnt); SYM(sptr, g_src_ptr); SYM(sedges, g_src_edges);
    SYM(stmp, g_scan_tmp); SYM(bsum, g_bsum);

    // allow >48KB dynamic smem for the edge kernel
    cudaFuncSetAttribute(k_edge, cudaFuncAttributeMaxDynamicSharedMemorySize,
                         EDGE_SMEM_FLOATS * (int)sizeof(float));

    // node embedding
    k_embed<<<(NLV + 3) / 4, 128>>>(x_l, xl, W_node, NLV);
    k_embed<<<(NPV + 3) / 4, 128>>>(x_p, xp, W_node, NPV);

    // rbf + cvec
    k_rbf<<<(EV + 255) / 256, 256>>>(ea);
    k_cvec<<<2, 256>>>(W_el, W1);

    // CSR (dst and src)
    cudaMemsetAsync(dcnt, 0, NPV * sizeof(int));
    cudaMemsetAsync(scnt, 0, NLV * sizeof(int));
    k_hist<<<(EV + 255) / 256, 256>>>(esrc, edst);
    int nbp = (NPV + 1023) / 1024, nbl = (NLV + 1023) / 1024;
    k_scan1<<<nbp, 1024>>>(dcnt, stmp, bsum, NPV);
    k_scan2<<<1, 1>>>(bsum, nbp);
    k_scan3<<<nbp, 1024>>>(stmp, bsum, dptr, NPV);
    k_scan1<<<nbl, 1024>>>(scnt, stmp, bsum, NLV);
    k_scan2<<<1, 1>>>(bsum, nbl);
    k_scan3<<<nbl, 1024>>>(stmp, bsum, sptr, NLV);
    cudaMemsetAsync(dcnt, 0, NPV * sizeof(int));
    cudaMemsetAsync(scnt, 0, NLV * sizeof(int));
    k_fill<<<(EV + 255) / 256, 256>>>(esrc, edst);

    // running sums
    cudaMemsetAsync(xlsum, 0, (size_t)NLV * 128 * sizeof(float));
    cudaMemsetAsync(xpsum, 0, (size_t)NPV * 128 * sizeof(float));

    // 3 hetero layers
    float *cxl = xl, *cxp = xp, *nxl = xl2, *nxp = xp2;
    for (int l = 0; l < 3; l++) {
        int ilp = 2 * l, ipl = 2 * l + 1;
        k_agg<<<(NPV * 32 + 255) / 256, 256>>>(dptr, dedges, esrc, cxl,
                Wb + ilp * 1024, bb + ilp * 128, prep, NPV);
        k_agg<<<(NLV * 32 + 255) / 256, 256>>>(sptr, sedges, edst, cxp,
                Wb + ipl * 1024, bb + ipl * 128, prel, NLV);
        k_gemm<<<dim3(1, (NPV + 127) / 128), 256>>>(cxp, Ws_ + (size_t)ilp * 16384,
                prep, Wn + (size_t)ilp * 16384, bconv + ilp * 128,
                nxp, xpsum, NPV, 128, 128, 128, 1);
        k_gemm<<<dim3(1, (NLV + 127) / 128), 256>>>(cxl, Ws_ + (size_t)ipl * 16384,
                prel, Wn + (size_t)ipl * 16384, bconv + ipl * 128,
                nxl, xlsum, NLV, 128, 128, 128, 1);
        float* t;
        t = cxl; cxl = nxl; nxl = t;
        t = cxp; cxp = nxp; nxp = t;
    }

    // edge readout factorization
    k_gemm<<<dim3(4, (NLV + 127) / 128), 256>>>(xlsum, W1, nullptr, nullptr, b1,
            Abuf, nullptr, NLV, 512, 128, 0, 0);
    k_gemm<<<dim3(4, (NPV + 127) / 128), 256>>>(xpsum, W1 + (size_t)128 * 512,
            nullptr, nullptr, nullptr, Bbuf, nullptr, NPV, 512, 128, 0, 0);

    k_init_out<<<(NGV * 128 + 255) / 256, 256>>>();
    k_edge<<<(EV + 127) / 128, 256, EDGE_SMEM_FLOATS * (int)sizeof(float)>>>(
            Abuf, Bbuf, W2, b2, Wm, bm, esrc, edst, ea, lbatch);
    k_final<<<(NGV * 256 + 255) / 256, 256>>>((float*)d_out);
}

// round 9
// speedup vs baseline: 1.8049x; 1.1773x over previous
#include <cuda_runtime.h>
#include <math.h>

#define NLV 50000
#define NPV 150000
#define EV  500000
#define NGV 256

// ---------------- device-global scratch ----------------
__device__ float g_xl   [NLV*128];
__device__ float g_xl2  [NLV*128];
__device__ float g_xlsum[NLV*128];
__device__ float g_prel [NLV*128];
__device__ float g_xp   [NPV*128];
__device__ float g_xp2  [NPV*128];
__device__ float g_xpsum[NPV*128];
__device__ float g_prep [NPV*128];
__device__ float g_rbf  [EV*8];
__device__ float g_A    [(size_t)NLV*512];
__device__ float g_B    [(size_t)NPV*512];
__device__ float g_cvec [512];
__device__ int   g_dst_cnt[NPV];
__device__ int   g_dst_ptr[NPV+1];
__device__ int   g_dst_edges[EV];
__device__ int   g_src_cnt[NLV];
__device__ int   g_src_ptr[NLV+1];
__device__ int   g_src_edges[EV];
__device__ int   g_scan_tmp[NPV];
__device__ int   g_bsum[512];
__device__ float g_out_w  [NGV*128];
__device__ float g_out_max[NGV*128];

// ---------------- helpers ----------------
__device__ __forceinline__ void atomicMaxFloat(float* addr, float v) {
    if (v >= 0.0f) atomicMax((int*)addr, __float_as_int(v));
    else           atomicMin((unsigned int*)addr, __float_as_uint(v));
}
__device__ __forceinline__ float fast_tanh(float x) {
    float y; asm("tanh.approx.f32 %0, %1;" : "=f"(y) : "f"(x)); return y;
}
__device__ __forceinline__ unsigned f2tf32(float f) {
    unsigned u; asm("cvt.rna.tf32.f32 %0, %1;" : "=r"(u) : "f"(f)); return u;
}
__device__ __forceinline__ void mma_tf32(float4& d,
        unsigned a0, unsigned a1, unsigned a2, unsigned a3,
        unsigned b0, unsigned b1) {
    asm("mma.sync.aligned.m16n8k8.row.col.f32.tf32.tf32.f32 "
        "{%0,%1,%2,%3}, {%4,%5,%6,%7}, {%8,%9}, {%0,%1,%2,%3};"
        : "+f"(d.x), "+f"(d.y), "+f"(d.z), "+f"(d.w)
        : "r"(a0), "r"(a1), "r"(a2), "r"(a3), "r"(b0), "r"(b1));
}

// ---------------- node embedding ----------------
__global__ void k_embed(const float* __restrict__ X, float* __restrict__ Y,
                        const float* __restrict__ Wn, int M) {
    __shared__ float xs[4][44];
    int r0 = blockIdx.x * 4;
    int tid = threadIdx.x;  // 128
    for (int i = tid; i < 4 * 44; i += 128) {
        int rr = i / 44, kk = i % 44;
        xs[rr][kk] = (r0 + rr < M) ? X[(size_t)(r0 + rr) * 44 + kk] : 0.f;
    }
    __syncthreads();
    int col = tid;
    #pragma unroll
    for (int rr = 0; rr < 4; rr++) {
        if (r0 + rr < M) {
            float s = 0.f;
            #pragma unroll
            for (int kk = 0; kk < 44; kk++) s = fmaf(xs[rr][kk], Wn[kk * 128 + col], s);
            Y[(size_t)(r0 + rr) * 128 + col] = s;
        }
    }
}

// ---------------- RBF ----------------
__global__ void k_rbf(const float* __restrict__ ea) {
    int e = blockIdx.x * 256 + threadIdx.x;
    if (e < EV) {
        float d = ea[e];
        #pragma unroll
        for (int k = 0; k < 8; k++) {
            float t = (d - (5.0f / 7.0f) * (float)k) * 1.6f;
            g_rbf[e * 8 + k] = __expf(-t * t);
        }
    }
}

// ---------------- CSR construction ----------------
__global__ void k_hist(const int* __restrict__ src, const int* __restrict__ dst) {
    int e = blockIdx.x * 256 + threadIdx.x;
    if (e < EV) {
        atomicAdd(&g_dst_cnt[dst[e]], 1);
        atomicAdd(&g_src_cnt[src[e]], 1);
    }
}
__global__ void k_scan1(const int* __restrict__ cnt, int* __restrict__ excl,
                        int* __restrict__ bsum, int n) {
    __shared__ int s[1024];
    int i = blockIdx.x * 1024 + threadIdx.x;
    int v = (i < n) ? cnt[i] : 0;
    s[threadIdx.x] = v;
    __syncthreads();
    for (int off = 1; off < 1024; off <<= 1) {
        int t = 0;
        if ((int)threadIdx.x >= off) t = s[threadIdx.x - off];
        __syncthreads();
        s[threadIdx.x] += t;
        __syncthreads();
    }
    if (i < n) excl[i] = s[threadIdx.x] - v;
    if (threadIdx.x == 1023) bsum[blockIdx.x] = s[1023];
}
__global__ void k_scan2(int* bsum, int nb) {
    if (threadIdx.x == 0 && blockIdx.x == 0) {
        int acc = 0;
        for (int b = 0; b < nb; b++) { int t = bsum[b]; bsum[b] = acc; acc += t; }
    }
}
__global__ void k_scan3(const int* __restrict__ excl, const int* __restrict__ bsum,
                        int* __restrict__ ptr, int n) {
    int i = blockIdx.x * 1024 + threadIdx.x;
    if (i < n) ptr[i] = excl[i] + bsum[i >> 10];
    if (i == 0) ptr[n] = EV;
}
__global__ void k_fill(const int* __restrict__ src, const int* __restrict__ dst) {
    int e = blockIdx.x * 256 + threadIdx.x;
    if (e < EV) {
        int d = dst[e]; int p = atomicAdd(&g_dst_cnt[d], 1); g_dst_edges[g_dst_ptr[d] + p] = e;
        int s = src[e]; int q = atomicAdd(&g_src_cnt[s], 1); g_src_edges[g_src_ptr[s] + q] = e;
    }
}

// ---------------- aggregation ----------------
__global__ __launch_bounds__(256) void k_agg(
    const int* __restrict__ ptr, const int* __restrict__ eidx,
    const int* __restrict__ partner, const float* __restrict__ xsrc,
    const float* __restrict__ Wb_i, const float* __restrict__ bb_i,
    float* __restrict__ pre, int n_dst)
{
    int w = (blockIdx.x * blockDim.x + threadIdx.x) >> 5;
    int lane = threadIdx.x & 31;
    if (w >= n_dst) return;
    float wreg[8][4], bias[4], acc[4] = {0.f, 0.f, 0.f, 0.f};
    #pragma unroll
    for (int c = 0; c < 4; c++) {
        bias[c] = bb_i[c * 32 + lane];
        #pragma unroll
        for (int k = 0; k < 8; k++) wreg[k][c] = Wb_i[k * 128 + c * 32 + lane];
    }
    int s = ptr[w], e = ptr[w + 1];
    for (int p = s; p < e; p++) {
        int ed = eidx[p];
        float rv = (lane < 8) ? g_rbf[ed * 8 + lane] : 0.f;
        float r[8];
        #pragma unroll
        for (int k = 0; k < 8; k++) r[k] = __shfl_sync(0xffffffffu, rv, k);
        const float* xr = xsrc + (size_t)partner[ed] * 128;
        #pragma unroll
        for (int c = 0; c < 4; c++) {
            float t = bias[c];
            #pragma unroll
            for (int k = 0; k < 8; k++) t = fmaf(r[k], wreg[k][c], t);
            float sg = 1.f / (1.f + __expf(-t));
            acc[c] += (t * sg) * xr[c * 32 + lane];
        }
    }
    float inv = 1.f / (float)((e - s) > 1 ? (e - s) : 1);
    #pragma unroll
    for (int c = 0; c < 4; c++) pre[(size_t)w * 128 + c * 32 + lane] = acc[c] * inv;
}

// ---------------- fused SGEMM (fp32 scalar; used for conv chain) ----------------
__global__ __launch_bounds__(256, 2) void k_gemm(
    const float* __restrict__ A0, const float* __restrict__ W0,
    const float* __restrict__ A1, const float* __restrict__ W1,
    const float* __restrict__ bias, float* __restrict__ C,
    float* __restrict__ sum, int M, int N, int K0, int K1, int act)
{
    __shared__ float As[16 * 132];
    __shared__ float Ws[16 * 132];
    int tid = threadIdx.x;
    int m0 = blockIdx.y * 128;
    int n0 = blockIdx.x * 128;
    int K = K0 + K1;

    float acc[8][8];
    #pragma unroll
    for (int r = 0; r < 8; r++)
        #pragma unroll
        for (int c = 0; c < 8; c++) acc[r][c] = 0.f;

    int le  = tid >> 1;
    int lk8 = (tid & 1) * 8;
    int arow = m0 + le;
    int wrow = tid >> 4;
    int wcol = (tid & 15) * 8;
    int rb = (tid >> 4) * 8;
    int cb = (tid & 15) * 8;

    for (int k = 0; k < K; k += 16) {
        const float* Ab; const float* Wb_; int kl; int stride;
        if (k < K0) { Ab = A0; Wb_ = W0; kl = k; stride = K0; }
        else        { Ab = A1; Wb_ = W1; kl = k - K0; stride = K1; }
        float4 a0 = make_float4(0.f,0.f,0.f,0.f), a1 = a0;
        if (arow < M) {
            const float* p = Ab + (size_t)arow * stride + kl + lk8;
            a0 = *(const float4*)p; a1 = *(const float4*)(p + 4);
        }
        As[(lk8 + 0) * 132 + le] = a0.x; As[(lk8 + 1) * 132 + le] = a0.y;
        As[(lk8 + 2) * 132 + le] = a0.z; As[(lk8 + 3) * 132 + le] = a0.w;
        As[(lk8 + 4) * 132 + le] = a1.x; As[(lk8 + 5) * 132 + le] = a1.y;
        As[(lk8 + 6) * 132 + le] = a1.z; As[(lk8 + 7) * 132 + le] = a1.w;
        {
            const float* p = Wb_ + (size_t)(kl + wrow) * N + n0 + wcol;
            float4 w0 = *(const float4*)p, w1 = *(const float4*)(p + 4);
            *(float4*)(Ws + wrow * 132 + wcol) = w0;
            *(float4*)(Ws + wrow * 132 + wcol + 4) = w1;
        }
        __syncthreads();
        #pragma unroll
        for (int kk = 0; kk < 16; kk++) {
            float4 av0 = *(const float4*)(As + kk * 132 + rb);
            float4 av1 = *(const float4*)(As + kk * 132 + rb + 4);
            float4 bv0 = *(const float4*)(Ws + kk * 132 + cb);
            float4 bv1 = *(const float4*)(Ws + kk * 132 + cb + 4);
            float a[8] = {av0.x, av0.y, av0.z, av0.w, av1.x, av1.y, av1.z, av1.w};
            float b[8] = {bv0.x, bv0.y, bv0.z, bv0.w, bv1.x, bv1.y, bv1.z, bv1.w};
            #pragma unroll
            for (int r = 0; r < 8; r++)
                #pragma unroll
                for (int c = 0; c < 8; c++) acc[r][c] = fmaf(a[r], b[c], acc[r][c]);
        }
        __syncthreads();
    }
    float bv[8];
    if (bias) {
        *(float4*)bv       = *(const float4*)(bias + n0 + cb);
        *(float4*)(bv + 4) = *(const float4*)(bias + n0 + cb + 4);
    } else {
        #pragma unroll
        for (int c = 0; c < 8; c++) bv[c] = 0.f;
    }
    #pragma unroll
    for (int r = 0; r < 8; r++) {
        int row = m0 + rb + r;
        if (row < M) {
            float v[8];
            #pragma unroll
            for (int c = 0; c < 8; c++) {
                float t = acc[r][c] + bv[c];
                if (act == 1) t = (t >= 0.f) ? t : 0.01f * t;
                v[c] = t;
            }
            float* cp = C + (size_t)row * N + n0 + cb;
            *(float4*)cp = *(float4*)v;
            *(float4*)(cp + 4) = *(float4*)(v + 4);
            if (sum) {
                float* sp = sum + (size_t)row * N + n0 + cb;
                float4 s0 = *(float4*)sp, s1 = *(float4*)(sp + 4);
                s0.x += v[0]; s0.y += v[1]; s0.z += v[2]; s0.w += v[3];
                s1.x += v[4]; s1.y += v[5]; s1.z += v[6]; s1.w += v[7];
                *(float4*)sp = s0; *(float4*)(sp + 4) = s1;
            }
        }
    }
}

// ---------------- tf32 mma GEMM: C = A@W (+bias) ; 128x128 tile, 8 warps -------
__global__ __launch_bounds__(256, 2) void k_gemm32(
    const float* __restrict__ A, const float* __restrict__ W,
    const float* __restrict__ bias, float* __restrict__ C,
    int M, int N, int K)
{
    __shared__ unsigned AsU[16 * 132];
    __shared__ unsigned WsU[16 * 132];
    int tid = threadIdx.x;
    int m0 = blockIdx.y * 128;
    int n0 = blockIdx.x * 128;

    int warp = tid >> 5, lane = tid & 31;
    int g = lane >> 2, t = lane & 3;
    int warp_m = warp >> 1, warp_n = warp & 1;

    int le  = tid >> 1;
    int lk8 = (tid & 1) * 8;
    int arow = m0 + le;
    int wrow = tid >> 4;
    int wcol = (tid & 15) * 8;

    float4 facc[2][8];
    #pragma unroll
    for (int mt = 0; mt < 2; mt++)
        #pragma unroll
        for (int nt = 0; nt < 8; nt++) facc[mt][nt] = make_float4(0.f, 0.f, 0.f, 0.f);

    for (int k = 0; k < K; k += 16) {
        float4 a0 = make_float4(0.f,0.f,0.f,0.f), a1 = a0;
        if (arow < M) {
            const float* p = A + (size_t)arow * K + k + lk8;
            a0 = *(const float4*)p; a1 = *(const float4*)(p + 4);
        }
        AsU[(lk8 + 0) * 132 + le] = f2tf32(a0.x);
        AsU[(lk8 + 1) * 132 + le] = f2tf32(a0.y);
        AsU[(lk8 + 2) * 132 + le] = f2tf32(a0.z);
        AsU[(lk8 + 3) * 132 + le] = f2tf32(a0.w);
        AsU[(lk8 + 4) * 132 + le] = f2tf32(a1.x);
        AsU[(lk8 + 5) * 132 + le] = f2tf32(a1.y);
        AsU[(lk8 + 6) * 132 + le] = f2tf32(a1.z);
        AsU[(lk8 + 7) * 132 + le] = f2tf32(a1.w);
        {
            const float* p = W + (size_t)(k + wrow) * N + n0 + wcol;
            float4 w0 = *(const float4*)p, w1 = *(const float4*)(p + 4);
            WsU[wrow * 132 + wcol + 0] = f2tf32(w0.x);
            WsU[wrow * 132 + wcol + 1] = f2tf32(w0.y);
            WsU[wrow * 132 + wcol + 2] = f2tf32(w0.z);
            WsU[wrow * 132 + wcol + 3] = f2tf32(w0.w);
            WsU[wrow * 132 + wcol + 4] = f2tf32(w1.x);
            WsU[wrow * 132 + wcol + 5] = f2tf32(w1.y);
            WsU[wrow * 132 + wcol + 6] = f2tf32(w1.z);
            WsU[wrow * 132 + wcol + 7] = f2tf32(w1.w);
        }
        __syncthreads();
        #pragma unroll
        for (int kb = 0; kb < 16; kb += 8) {
            unsigned af[2][4];
            #pragma unroll
            for (int mt = 0; mt < 2; mt++) {
                int rowb = warp_m * 32 + mt * 16;
                af[mt][0] = AsU[(kb + t) * 132 + rowb + g];
                af[mt][1] = AsU[(kb + t) * 132 + rowb + g + 8];
                af[mt][2] = AsU[(kb + t + 4) * 132 + rowb + g];
                af[mt][3] = AsU[(kb + t + 4) * 132 + rowb + g + 8];
            }
            #pragma unroll
            for (int nt = 0; nt < 8; nt++) {
                int colb = warp_n * 64 + nt * 8;
                unsigned bf0 = WsU[(kb + t) * 132 + colb + g];
                unsigned bf1 = WsU[(kb + t + 4) * 132 + colb + g];
                mma_tf32(facc[0][nt], af[0][0], af[0][1], af[0][2], af[0][3], bf0, bf1);
                mma_tf32(facc[1][nt], af[1][0], af[1][1], af[1][2], af[1][3], bf0, bf1);
            }
        }
        __syncthreads();
    }
    #pragma unroll
    for (int mt = 0; mt < 2; mt++) {
        int rowb = m0 + warp_m * 32 + mt * 16;
        #pragma unroll
        for (int nt = 0; nt < 8; nt++) {
            int col = n0 + warp_n * 64 + nt * 8 + 2 * t;
            float ba = 0.f, bb_ = 0.f;
            if (bias) { ba = bias[col]; bb_ = bias[col + 1]; }
            int r0 = rowb + g, r1 = rowb + g + 8;
            if (r0 < M) {
                float2 v = make_float2(facc[mt][nt].x + ba, facc[mt][nt].y + bb_);
                *(float2*)(C + (size_t)r0 * N + col) = v;
            }
            if (r1 < M) {
                float2 v = make_float2(facc[mt][nt].z + ba, facc[mt][nt].w + bb_);
                *(float2*)(C + (size_t)r1 * N + col) = v;
            }
        }
    }
}

// ---------------- cvec ----------------
__global__ void k_cvec(const float* __restrict__ W_el, const float* __restrict__ W1) {
    int j = blockIdx.x * 256 + threadIdx.x;
    if (j < 512) {
        float s = 0.f;
        #pragma unroll
        for (int k = 0; k < 8; k++) s = fmaf(W_el[k], W1[(size_t)(256 + k) * 512 + j], s);
        g_cvec[j] = s;
    }
}

__global__ void k_init_out() {
    int i = blockIdx.x * 256 + threadIdx.x;
    if (i < NGV * 128) { g_out_w[i] = 0.f; g_out_max[i] = -INFINITY; }
}

// ---------------- fused edge MLP + per-graph reduction: 128-edge tiles ------------
// dynamic smem layout (floats):
//   As   [16*132]    @ 0      (tf32 bits during GEMM1)
//   Ws   [16*132]    @ 2112   (tf32 bits during GEMM1; fp32 W tiles in GEMM2)
//   smm  [128*132]   @ 4224   (fp32 m matrix)
//   cs   [512]       @ 21120
//   se_d [128]       @ 21632
//   se_a [128] (int) @ 21760
//   se_b [128] (int) @ 21888
//   se_g [128] (int) @ 22016
#define EDGE_SMEM_FLOATS 22144
__global__ __launch_bounds__(256, 2) void k_edge(
    const float* __restrict__ Al, const float* __restrict__ Bp,
    const float* __restrict__ W2, const float* __restrict__ b2,
    const float* __restrict__ Wm, const float* __restrict__ bm,
    const int* __restrict__ src, const int* __restrict__ dst,
    const float* __restrict__ ea, const int* __restrict__ lbatch)
{
    extern __shared__ float dynsm[];
    float* As   = dynsm;
    float* Ws   = dynsm + 2112;
    float* smm  = dynsm + 4224;
    float* cs   = dynsm + 21120;
    float* se_d = dynsm + 21632;
    int*   se_a = (int*)(dynsm + 21760);
    int*   se_b = (int*)(dynsm + 21888);
    int*   se_g = (int*)(dynsm + 22016);
    unsigned* AsU = (unsigned*)As;
    unsigned* WsU = (unsigned*)Ws;

    int tid = threadIdx.x;
    int t0 = blockIdx.x * 128;
    if (tid < 128) {
        int slot = t0 + tid;
        if (slot < EV) {
            int e = g_src_edges[slot];
            int s = src[e];
            se_a[tid] = s; se_b[tid] = dst[e];
            se_d[tid] = ea[e];
            se_g[tid] = lbatch[s];
        } else { se_a[tid] = 0; se_b[tid] = 0; se_d[tid] = 0.f; se_g[tid] = -1; }
    }
    for (int i = tid; i < 512; i += 256) cs[i] = g_cvec[i];
    __syncthreads();

    int warp = tid >> 5, lane = tid & 31;
    int g = lane >> 2, t = lane & 3;
    int warp_m = warp >> 1, warp_n = warp & 1;

    int le  = tid >> 1;
    int lk8 = (tid & 1) * 8;
    const float* arow = Al + (size_t)se_a[le] * 512;
    const float* brow = Bp + (size_t)se_b[le] * 512;
    float dv = se_d[le];
    int wrow = tid >> 4;
    int wcol = (tid & 15) * 8;
    int rb = (tid >> 4) * 8;
    int cb = (tid & 15) * 8;

    // ---- GEMM 1 (tf32 mma): m = relu(A[src]+B[dst]+d*cvec) @ W2 ----
    float4 facc[2][8];
    #pragma unroll
    for (int mt = 0; mt < 2; mt++)
        #pragma unroll
        for (int nt = 0; nt < 8; nt++) facc[mt][nt] = make_float4(0.f, 0.f, 0.f, 0.f);

    for (int k = 0; k < 512; k += 16) {
        const float* pa = arow + k + lk8;
        const float* pb = brow + k + lk8;
        float4 a0 = *(const float4*)pa, a1 = *(const float4*)(pa + 4);
        float4 b0 = *(const float4*)pb, b1 = *(const float4*)(pb + 4);
        float4 c0 = *(const float4*)(cs + k + lk8), c1 = *(const float4*)(cs + k + lk8 + 4);
        AsU[(lk8 + 0) * 132 + le] = f2tf32(fmaxf(a0.x + b0.x + dv * c0.x, 0.f));
        AsU[(lk8 + 1) * 132 + le] = f2tf32(fmaxf(a0.y + b0.y + dv * c0.y, 0.f));
        AsU[(lk8 + 2) * 132 + le] = f2tf32(fmaxf(a0.z + b0.z + dv * c0.z, 0.f));
        AsU[(lk8 + 3) * 132 + le] = f2tf32(fmaxf(a0.w + b0.w + dv * c0.w, 0.f));
        AsU[(lk8 + 4) * 132 + le] = f2tf32(fmaxf(a1.x + b1.x + dv * c1.x, 0.f));
        AsU[(lk8 + 5) * 132 + le] = f2tf32(fmaxf(a1.y + b1.y + dv * c1.y, 0.f));
        AsU[(lk8 + 6) * 132 + le] = f2tf32(fmaxf(a1.z + b1.z + dv * c1.z, 0.f));
        AsU[(lk8 + 7) * 132 + le] = f2tf32(fmaxf(a1.w + b1.w + dv * c1.w, 0.f));
        {
            const float* p = W2 + (size_t)(k + wrow) * 128 + wcol;
            float4 w0 = *(const float4*)p, w1 = *(const float4*)(p + 4);
            WsU[wrow * 132 + wcol + 0] = f2tf32(w0.x);
            WsU[wrow * 132 + wcol + 1] = f2tf32(w0.y);
            WsU[wrow * 132 + wcol + 2] = f2tf32(w0.z);
            WsU[wrow * 132 + wcol + 3] = f2tf32(w0.w);
            WsU[wrow * 132 + wcol + 4] = f2tf32(w1.x);
            WsU[wrow * 132 + wcol + 5] = f2tf32(w1.y);
            WsU[wrow * 132 + wcol + 6] = f2tf32(w1.z);
            WsU[wrow * 132 + wcol + 7] = f2tf32(w1.w);
        }
        __syncthreads();
        #pragma unroll
        for (int kb = 0; kb < 16; kb += 8) {
            unsigned af[2][4];
            #pragma unroll
            for (int mt = 0; mt < 2; mt++) {
                int rowb = warp_m * 32 + mt * 16;
                af[mt][0] = AsU[(kb + t) * 132 + rowb + g];
                af[mt][1] = AsU[(kb + t) * 132 + rowb + g + 8];
                af[mt][2] = AsU[(kb + t + 4) * 132 + rowb + g];
                af[mt][3] = AsU[(kb + t + 4) * 132 + rowb + g + 8];
            }
            #pragma unroll
            for (int nt = 0; nt < 8; nt++) {
                int colb = warp_n * 64 + nt * 8;
                unsigned bf0 = WsU[(kb + t) * 132 + colb + g];
                unsigned bf1 = WsU[(kb + t + 4) * 132 + colb + g];
                mma_tf32(facc[0][nt], af[0][0], af[0][1], af[0][2], af[0][3], bf0, bf1);
                mma_tf32(facc[1][nt], af[1][0], af[1][1], af[1][2], af[1][3], bf0, bf1);
            }
        }
        __syncthreads();
    }

    // m = facc + b2 -> smm (fragment-layout stores, fp32)
    #pragma unroll
    for (int mt = 0; mt < 2; mt++) {
        int rowb = warp_m * 32 + mt * 16;
        #pragma unroll
        for (int nt = 0; nt < 8; nt++) {
            int cc = warp_n * 64 + nt * 8 + 2 * t;
            float ba = b2[cc], bb_ = b2[cc + 1];
            *(float2*)(smm + (rowb + g) * 132 + cc) =
                make_float2(facc[mt][nt].x + ba, facc[mt][nt].y + bb_);
            *(float2*)(smm + (rowb + g + 8) * 132 + cc) =
                make_float2(facc[mt][nt].z + ba, facc[mt][nt].w + bb_);
        }
    }
    __syncthreads();

    // ---- GEMM 2 (scalar fp32): w = tanh(m @ Wm + bm) ----
    float acc[8][8];
    #pragma unroll
    for (int r = 0; r < 8; r++)
        #pragma unroll
        for (int c = 0; c < 8; c++) acc[r][c] = 0.f;

    for (int k = 0; k < 128; k += 16) {
        {
            const float* p = Wm + (size_t)(k + wrow) * 128 + wcol;
            float4 w0 = *(const float4*)p, w1 = *(const float4*)(p + 4);
            *(float4*)(Ws + wrow * 132 + wcol) = w0;
            *(float4*)(Ws + wrow * 132 + wcol + 4) = w1;
        }
        __syncthreads();
        #pragma unroll
        for (int kk = 0; kk < 16; kk++) {
            float a[8];
            #pragma unroll
            for (int r = 0; r < 8; r++) a[r] = smm[(rb + r) * 132 + k + kk];
            float4 bv0 = *(const float4*)(Ws + kk * 132 + cb);
            float4 bv1 = *(const float4*)(Ws + kk * 132 + cb + 4);
            float b[8] = {bv0.x, bv0.y, bv0.z, bv0.w, bv1.x, bv1.y, bv1.z, bv1.w};
            #pragma unroll
            for (int r = 0; r < 8; r++)
                #pragma unroll
                for (int c = 0; c < 8; c++) acc[r][c] = fmaf(a[r], b[c], acc[r][c]);
        }
        __syncthreads();
    }

    // ---- segmented per-graph reduction (rows = consecutive sorted edges) ----
    {
        float bmr[8];
        *(float4*)bmr       = *(const float4*)(bm + cb);
        *(float4*)(bmr + 4) = *(const float4*)(bm + cb + 4);
        #pragma unroll
        for (int c = 0; c < 8; c++) {
            int col = cb + c;
            float s = 0.f, mx = -INFINITY;
            int cg = se_g[rb];
            #pragma unroll
            for (int r = 0; r < 8; r++) {
                int gg = se_g[rb + r];
                if (gg != cg) {
                    if (cg >= 0) {
                        atomicAdd(&g_out_w[cg * 128 + col], s);
                        atomicMaxFloat(&g_out_max[cg * 128 + col], mx);
                    }
                    cg = gg; s = 0.f; mx = -INFINITY;
                }
                float mv = smm[(rb + r) * 132 + col];
                float w = fast_tanh(acc[r][c] + bmr[c]);
                s += w * mv;
                mx = fmaxf(mx, mv);
            }
            if (cg >= 0) {
                atomicAdd(&g_out_w[cg * 128 + col], s);
                atomicMaxFloat(&g_out_max[cg * 128 + col], mx);
            }
        }
    }
}

__global__ void k_final(float* __restrict__ out) {
    int i = blockIdx.x * 256 + threadIdx.x;
    if (i < NGV * 256) {
        int g = i >> 8, j = i & 255;
        float v;
        if (j < 128) v = g_out_w[g * 128 + j];
        else {
            v = g_out_max[g * 128 + j - 128];
            if (!isfinite(v)) v = 0.f;
        }
        out[i] = v;
    }
}

// ---------------- host orchestration ----------------
#define SYM(p, s) do { void* _t = nullptr; cudaGetSymbolAddress(&_t, s); p = (decltype(p))_t; } while (0)

extern "C" void kernel_launch(void* const* d_in, const int* in_sizes, int n_in,
                              void* d_out, int out_size) {
    const float* x_l    = (const float*)d_in[0];
    const float* x_p    = (const float*)d_in[1];
    const float* ea     = (const float*)d_in[2];
    const int*   esrc   = (const int*)  d_in[3];
    const int*   edst   = (const int*)  d_in[4];
    const int*   lbatch = (const int*)  d_in[5];
    const float* W_node = (const float*)d_in[6];
    const float* W_el   = (const float*)d_in[7];
    const float* Wb     = (const float*)d_in[8];
    const float* bb     = (const float*)d_in[9];
    const float* Wn     = (const float*)d_in[10];
    const float* Ws_    = (const float*)d_in[11];
    const float* bconv  = (const float*)d_in[12];
    const float* W1     = (const float*)d_in[13];
    const float* b1     = (const float*)d_in[14];
    const float* W2     = (const float*)d_in[15];
    const float* b2     = (const float*)d_in[16];
    const float* Wm     = (const float*)d_in[17];
    const float* bm     = (const float*)d_in[18];

    float *xl, *xl2, *xlsum, *prel, *xp, *xp2, *xpsum, *prep, *Abuf, *Bbuf;
    int *dcnt, *dptr, *dedges, *scnt, *sptr, *sedges, *stmp, *bsum;
    SYM(xl, g_xl); SYM(xl2, g_xl2); SYM(xlsum, g_xlsum); SYM(prel, g_prel);
    SYM(xp, g_xp); SYM(xp2, g_xp2); SYM(xpsum, g_xpsum); SYM(prep, g_prep);
    SYM(Abuf, g_A); SYM(Bbuf, g_B);
    SYM(dcnt, g_dst_cnt); SYM(dptr, g_dst_ptr); SYM(dedges, g_dst_edges);
    SYM(scnt, g_src_cnt); SYM(sptr, g_src_ptr); SYM(sedges, g_src_edges);
    SYM(stmp, g_scan_tmp); SYM(bsum, g_bsum);

    cudaFuncSetAttribute(k_edge, cudaFuncAttributeMaxDynamicSharedMemorySize,
                         EDGE_SMEM_FLOATS * (int)sizeof(float));

    // node embedding
    k_embed<<<(NLV + 3) / 4, 128>>>(x_l, xl, W_node, NLV);
    k_embed<<<(NPV + 3) / 4, 128>>>(x_p, xp, W_node, NPV);

    // rbf + cvec
    k_rbf<<<(EV + 255) / 256, 256>>>(ea);
    k_cvec<<<2, 256>>>(W_el, W1);

    // CSR (dst and src)
    cudaMemsetAsync(dcnt, 0, NPV * sizeof(int));
    cudaMemsetAsync(scnt, 0, NLV * sizeof(int));
    k_hist<<<(EV + 255) / 256, 256>>>(esrc, edst);
    int nbp = (NPV + 1023) / 1024, nbl = (NLV + 1023) / 1024;
    k_scan1<<<nbp, 1024>>>(dcnt, stmp, bsum, NPV);
    k_scan2<<<1, 1>>>(bsum, nbp);
    k_scan3<<<nbp, 1024>>>(stmp, bsum, dptr, NPV);
    k_scan1<<<nbl, 1024>>>(scnt, stmp, bsum, NLV);
    k_scan2<<<1, 1>>>(bsum, nbl);
    k_scan3<<<nbl, 1024>>>(stmp, bsum, sptr, NLV);
    cudaMemsetAsync(dcnt, 0, NPV * sizeof(int));
    cudaMemsetAsync(scnt, 0, NLV * sizeof(int));
    k_fill<<<(EV + 255) / 256, 256>>>(esrc, edst);

    // running sums
    cudaMemsetAsync(xlsum, 0, (size_t)NLV * 128 * sizeof(float));
    cudaMemsetAsync(xpsum, 0, (size_t)NPV * 128 * sizeof(float));

    // 3 hetero layers (fp32 — kept exact to avoid tf32 error compounding)
    float *cxl = xl, *cxp = xp, *nxl = xl2, *nxp = xp2;
    for (int l = 0; l < 3; l++) {
        int ilp = 2 * l, ipl = 2 * l + 1;
        k_agg<<<(NPV * 32 + 255) / 256, 256>>>(dptr, dedges, esrc, cxl,
                Wb + ilp * 1024, bb + ilp * 128, prep, NPV);
        k_agg<<<(NLV * 32 + 255) / 256, 256>>>(sptr, sedges, edst, cxp,
                Wb + ipl * 1024, bb + ipl * 128, prel, NLV);
        k_gemm<<<dim3(1, (NPV + 127) / 128), 256>>>(cxp, Ws_ + (size_t)ilp * 16384,
                prep, Wn + (size_t)ilp * 16384, bconv + ilp * 128,
                nxp, xpsum, NPV, 128, 128, 128, 1);
        k_gemm<<<dim3(1, (NLV + 127) / 128), 256>>>(cxl, Ws_ + (size_t)ipl * 16384,
                prel, Wn + (size_t)ipl * 16384, bconv + ipl * 128,
                nxl, xlsum, NLV, 128, 128, 128, 1);
        float* t;
        t = cxl; cxl = nxl; nxl = t;
        t = cxp; cxp = nxp; nxp = t;
    }

    // edge readout factorization (tf32 mma)
    k_gemm32<<<dim3(4, (NLV + 127) / 128), 256>>>(xlsum, W1, b1, Abuf, NLV, 512, 128);
    k_gemm32<<<dim3(4, (NPV + 127) / 128), 256>>>(xpsum, W1 + (size_t)128 * 512,
                                                  nullptr, Bbuf, NPV, 512, 128);

    k_init_out<<<(NGV * 128 + 255) / 256, 256>>>();
    k_edge<<<(EV + 127) / 128, 256, EDGE_SMEM_FLOATS * (int)sizeof(float)>>>(
            Abuf, Bbuf, W2, b2, Wm, bm, esrc, edst, ea, lbatch);
    k_final<<<(NGV * 256 + 255) / 256, 256>>>((float*)d_out);
}

// round 10
// speedup vs baseline: 2.1269x; 1.1784x over previous
#include <cuda_runtime.h>
#include <math.h>

#define NLV 50000
#define NPV 150000
#define EV  500000
#define NGV 256

// ---------------- device-global scratch ----------------
__device__ float g_xl   [NLV*128];
__device__ float g_xl2  [NLV*128];
__device__ float g_xlsum[NLV*128];
__device__ float g_prel [NLV*128];
__device__ float g_xp   [NPV*128];
__device__ float g_xp2  [NPV*128];
__device__ float g_xpsum[NPV*128];
__device__ float g_prep [NPV*128];
__device__ float g_rbf  [EV*8];
__device__ float g_A    [(size_t)NLV*512];
__device__ float g_B    [(size_t)NPV*512];
__device__ float g_cvec [512];
__device__ int   g_dst_cnt[NPV];
__device__ int   g_dst_ptr[NPV+1];
__device__ int   g_dst_edges[EV];
__device__ int   g_src_cnt[NLV];
__device__ int   g_src_ptr[NLV+1];
__device__ int   g_src_edges[EV];
__device__ int   g_scan_tmp[NPV];
__device__ int   g_bsum[512];
__device__ float g_out_w  [NGV*128];
__device__ float g_out_max[NGV*128];

// ---------------- helpers ----------------
__device__ __forceinline__ void atomicMaxFloat(float* addr, float v) {
    if (v >= 0.0f) atomicMax((int*)addr, __float_as_int(v));
    else           atomicMin((unsigned int*)addr, __float_as_uint(v));
}
__device__ __forceinline__ float fast_tanh(float x) {
    float y; asm("tanh.approx.f32 %0, %1;" : "=f"(y) : "f"(x)); return y;
}
__device__ __forceinline__ unsigned f2tf32(float f) {
    unsigned u; asm("cvt.rna.tf32.f32 %0, %1;" : "=r"(u) : "f"(f)); return u;
}
__device__ __forceinline__ void mma_tf32(float4& d,
        unsigned a0, unsigned a1, unsigned a2, unsigned a3,
        unsigned b0, unsigned b1) {
    asm("mma.sync.aligned.m16n8k8.row.col.f32.tf32.tf32.f32 "
        "{%0,%1,%2,%3}, {%4,%5,%6,%7}, {%8,%9}, {%0,%1,%2,%3};"
        : "+f"(d.x), "+f"(d.y), "+f"(d.z), "+f"(d.w)
        : "r"(a0), "r"(a1), "r"(a2), "r"(a3), "r"(b0), "r"(b1));
}

// ---------------- node embedding ----------------
__global__ void k_embed(const float* __restrict__ X, float* __restrict__ Y,
                        const float* __restrict__ Wn, int M) {
    __shared__ float xs[4][44];
    int r0 = blockIdx.x * 4;
    int tid = threadIdx.x;  // 128
    for (int i = tid; i < 4 * 44; i += 128) {
        int rr = i / 44, kk = i % 44;
        xs[rr][kk] = (r0 + rr < M) ? X[(size_t)(r0 + rr) * 44 + kk] : 0.f;
    }
    __syncthreads();
    int col = tid;
    #pragma unroll
    for (int rr = 0; rr < 4; rr++) {
        if (r0 + rr < M) {
            float s = 0.f;
            #pragma unroll
            for (int kk = 0; kk < 44; kk++) s = fmaf(xs[rr][kk], Wn[kk * 128 + col], s);
            Y[(size_t)(r0 + rr) * 128 + col] = s;
        }
    }
}

// ---------------- RBF ----------------
__global__ void k_rbf(const float* __restrict__ ea) {
    int e = blockIdx.x * 256 + threadIdx.x;
    if (e < EV) {
        float d = ea[e];
        #pragma unroll
        for (int k = 0; k < 8; k++) {
            float t = (d - (5.0f / 7.0f) * (float)k) * 1.6f;
            g_rbf[e * 8 + k] = __expf(-t * t);
        }
    }
}

// ---------------- CSR construction ----------------
__global__ void k_hist(const int* __restrict__ src, const int* __restrict__ dst) {
    int e = blockIdx.x * 256 + threadIdx.x;
    if (e < EV) {
        atomicAdd(&g_dst_cnt[dst[e]], 1);
        atomicAdd(&g_src_cnt[src[e]], 1);
    }
}
__global__ void k_scan1(const int* __restrict__ cnt, int* __restrict__ excl,
                        int* __restrict__ bsum, int n) {
    __shared__ int s[1024];
    int i = blockIdx.x * 1024 + threadIdx.x;
    int v = (i < n) ? cnt[i] : 0;
    s[threadIdx.x] = v;
    __syncthreads();
    for (int off = 1; off < 1024; off <<= 1) {
        int t = 0;
        if ((int)threadIdx.x >= off) t = s[threadIdx.x - off];
        __syncthreads();
        s[threadIdx.x] += t;
        __syncthreads();
    }
    if (i < n) excl[i] = s[threadIdx.x] - v;
    if (threadIdx.x == 1023) bsum[blockIdx.x] = s[1023];
}
__global__ void k_scan2(int* bsum, int nb) {
    if (threadIdx.x == 0 && blockIdx.x == 0) {
        int acc = 0;
        for (int b = 0; b < nb; b++) { int t = bsum[b]; bsum[b] = acc; acc += t; }
    }
}
__global__ void k_scan3(const int* __restrict__ excl, const int* __restrict__ bsum,
                        int* __restrict__ ptr, int n) {
    int i = blockIdx.x * 1024 + threadIdx.x;
    if (i < n) ptr[i] = excl[i] + bsum[i >> 10];
    if (i == 0) ptr[n] = EV;
}
__global__ void k_fill(const int* __restrict__ src, const int* __restrict__ dst) {
    int e = blockIdx.x * 256 + threadIdx.x;
    if (e < EV) {
        int d = dst[e]; int p = atomicAdd(&g_dst_cnt[d], 1); g_dst_edges[g_dst_ptr[d] + p] = e;
        int s = src[e]; int q = atomicAdd(&g_src_cnt[s], 1); g_src_edges[g_src_ptr[s] + q] = e;
    }
}

// ---------------- aggregation ----------------
__global__ __launch_bounds__(256) void k_agg(
    const int* __restrict__ ptr, const int* __restrict__ eidx,
    const int* __restrict__ partner, const float* __restrict__ xsrc,
    const float* __restrict__ Wb_i, const float* __restrict__ bb_i,
    float* __restrict__ pre, int n_dst)
{
    int w = (blockIdx.x * blockDim.x + threadIdx.x) >> 5;
    int lane = threadIdx.x & 31;
    if (w >= n_dst) return;
    float wreg[8][4], bias[4], acc[4] = {0.f, 0.f, 0.f, 0.f};
    #pragma unroll
    for (int c = 0; c < 4; c++) {
        bias[c] = bb_i[c * 32 + lane];
        #pragma unroll
        for (int k = 0; k < 8; k++) wreg[k][c] = Wb_i[k * 128 + c * 32 + lane];
    }
    int s = ptr[w], e = ptr[w + 1];
    for (int p = s; p < e; p++) {
        int ed = eidx[p];
        float rv = (lane < 8) ? g_rbf[ed * 8 + lane] : 0.f;
        float r[8];
        #pragma unroll
        for (int k = 0; k < 8; k++) r[k] = __shfl_sync(0xffffffffu, rv, k);
        const float* xr = xsrc + (size_t)partner[ed] * 128;
        #pragma unroll
        for (int c = 0; c < 4; c++) {
            float t = bias[c];
            #pragma unroll
            for (int k = 0; k < 8; k++) t = fmaf(r[k], wreg[k][c], t);
            float sg = 1.f / (1.f + __expf(-t));
            acc[c] += (t * sg) * xr[c * 32 + lane];
        }
    }
    float inv = 1.f / (float)((e - s) > 1 ? (e - s) : 1);
    #pragma unroll
    for (int c = 0; c < 4; c++) pre[(size_t)w * 128 + c * 32 + lane] = acc[c] * inv;
}

// ---------------- tf32 mma fused GEMM ----------------
// C[M,N] = act( A0[M,K0]@W0 + A1[M,K1]@W1 + bias ); optional sum += C
// 128x128 tile, 8 warps, m16n8k8 tf32.
__global__ __launch_bounds__(256, 2) void k_mma(
    const float* __restrict__ A0, const float* __restrict__ W0,
    const float* __restrict__ A1, const float* __restrict__ W1,
    const float* __restrict__ bias, float* __restrict__ C,
    float* __restrict__ sum, int M, int N, int K0, int K1, int act)
{
    __shared__ unsigned AsU[16 * 132];
    __shared__ unsigned WsU[16 * 132];
    int tid = threadIdx.x;
    int m0 = blockIdx.y * 128;
    int n0 = blockIdx.x * 128;
    int K = K0 + K1;

    int warp = tid >> 5, lane = tid & 31;
    int g = lane >> 2, t = lane & 3;
    int warp_m = warp >> 1, warp_n = warp & 1;

    int le  = tid >> 1;
    int lk8 = (tid & 1) * 8;
    int arow = m0 + le;
    int wrow = tid >> 4;
    int wcol = (tid & 15) * 8;

    float4 facc[2][8];
    #pragma unroll
    for (int mt = 0; mt < 2; mt++)
        #pragma unroll
        for (int nt = 0; nt < 8; nt++) facc[mt][nt] = make_float4(0.f, 0.f, 0.f, 0.f);

    for (int k = 0; k < K; k += 16) {
        const float* Ab; const float* Wb_; int kl; int stride;
        if (k < K0) { Ab = A0; Wb_ = W0; kl = k; stride = K0; }
        else        { Ab = A1; Wb_ = W1; kl = k - K0; stride = K1; }
        float4 a0 = make_float4(0.f,0.f,0.f,0.f), a1 = a0;
        if (arow < M) {
            const float* p = Ab + (size_t)arow * stride + kl + lk8;
            a0 = *(const float4*)p; a1 = *(const float4*)(p + 4);
        }
        AsU[(lk8 + 0) * 132 + le] = f2tf32(a0.x);
        AsU[(lk8 + 1) * 132 + le] = f2tf32(a0.y);
        AsU[(lk8 + 2) * 132 + le] = f2tf32(a0.z);
        AsU[(lk8 + 3) * 132 + le] = f2tf32(a0.w);
        AsU[(lk8 + 4) * 132 + le] = f2tf32(a1.x);
        AsU[(lk8 + 5) * 132 + le] = f2tf32(a1.y);
        AsU[(lk8 + 6) * 132 + le] = f2tf32(a1.z);
        AsU[(lk8 + 7) * 132 + le] = f2tf32(a1.w);
        {
            const float* p = Wb_ + (size_t)(kl + wrow) * N + n0 + wcol;
            float4 w0 = *(const float4*)p, w1 = *(const float4*)(p + 4);
            WsU[wrow * 132 + wcol + 0] = f2tf32(w0.x);
            WsU[wrow * 132 + wcol + 1] = f2tf32(w0.y);
            WsU[wrow * 132 + wcol + 2] = f2tf32(w0.z);
            WsU[wrow * 132 + wcol + 3] = f2tf32(w0.w);
            WsU[wrow * 132 + wcol + 4] = f2tf32(w1.x);
            WsU[wrow * 132 + wcol + 5] = f2tf32(w1.y);
            WsU[wrow * 132 + wcol + 6] = f2tf32(w1.z);
            WsU[wrow * 132 + wcol + 7] = f2tf32(w1.w);
        }
        __syncthreads();
        #pragma unroll
        for (int kb = 0; kb < 16; kb += 8) {
            unsigned af[2][4];
            #pragma unroll
            for (int mt = 0; mt < 2; mt++) {
                int rowb = warp_m * 32 + mt * 16;
                af[mt][0] = AsU[(kb + t) * 132 + rowb + g];
                af[mt][1] = AsU[(kb + t) * 132 + rowb + g + 8];
                af[mt][2] = AsU[(kb + t + 4) * 132 + rowb + g];
                af[mt][3] = AsU[(kb + t + 4) * 132 + rowb + g + 8];
            }
            #pragma unroll
            for (int nt = 0; nt < 8; nt++) {
                int colb = warp_n * 64 + nt * 8;
                unsigned bf0 = WsU[(kb + t) * 132 + colb + g];
                unsigned bf1 = WsU[(kb + t + 4) * 132 + colb + g];
                mma_tf32(facc[0][nt], af[0][0], af[0][1], af[0][2], af[0][3], bf0, bf1);
                mma_tf32(facc[1][nt], af[1][0], af[1][1], af[1][2], af[1][3], bf0, bf1);
            }
        }
        __syncthreads();
    }
    #pragma unroll
    for (int mt = 0; mt < 2; mt++) {
        int rowb = m0 + warp_m * 32 + mt * 16;
        #pragma unroll
        for (int nt = 0; nt < 8; nt++) {
            int col = n0 + warp_n * 64 + nt * 8 + 2 * t;
            float ba = 0.f, bb_ = 0.f;
            if (bias) { ba = bias[col]; bb_ = bias[col + 1]; }
            int r0 = rowb + g, r1 = rowb + g + 8;
            float vx = facc[mt][nt].x + ba, vy = facc[mt][nt].y + bb_;
            float vz = facc[mt][nt].z + ba, vw = facc[mt][nt].w + bb_;
            if (act == 1) {
                vx = (vx >= 0.f) ? vx : 0.01f * vx;
                vy = (vy >= 0.f) ? vy : 0.01f * vy;
                vz = (vz >= 0.f) ? vz : 0.01f * vz;
                vw = (vw >= 0.f) ? vw : 0.01f * vw;
            }
            if (r0 < M) {
                *(float2*)(C + (size_t)r0 * N + col) = make_float2(vx, vy);
                if (sum) {
                    float2 s = *(float2*)(sum + (size_t)r0 * N + col);
                    s.x += vx; s.y += vy;
                    *(float2*)(sum + (size_t)r0 * N + col) = s;
                }
            }
            if (r1 < M) {
                *(float2*)(C + (size_t)r1 * N + col) = make_float2(vz, vw);
                if (sum) {
                    float2 s = *(float2*)(sum + (size_t)r1 * N + col);
                    s.x += vz; s.y += vw;
                    *(float2*)(sum + (size_t)r1 * N + col) = s;
                }
            }
        }
    }
}

// ---------------- cvec ----------------
__global__ void k_cvec(const float* __restrict__ W_el, const float* __restrict__ W1) {
    int j = blockIdx.x * 256 + threadIdx.x;
    if (j < 512) {
        float s = 0.f;
        #pragma unroll
        for (int k = 0; k < 8; k++) s = fmaf(W_el[k], W1[(size_t)(256 + k) * 512 + j], s);
        g_cvec[j] = s;
    }
}

__global__ void k_init_out() {
    int i = blockIdx.x * 256 + threadIdx.x;
    if (i < NGV * 128) { g_out_w[i] = 0.f; g_out_max[i] = -INFINITY; }
}

// ---------------- fused edge MLP + per-graph reduction: 128-edge tiles ------------
// dynamic smem layout (floats):
//   As   [16*132]    @ 0      (tf32 bits)
//   Ws   [16*132]    @ 2112   (tf32 bits)
//   smm  [128*132]   @ 4224   (fp32 m matrix)
//   cs   [512]       @ 21120
//   se_d [128]       @ 21632
//   se_a [128] (int) @ 21760
//   se_b [128] (int) @ 21888
//   se_g [128] (int) @ 22016
#define EDGE_SMEM_FLOATS 22144
__global__ __launch_bounds__(256, 2) void k_edge(
    const float* __restrict__ Al, const float* __restrict__ Bp,
    const float* __restrict__ W2, const float* __restrict__ b2,
    const float* __restrict__ Wm, const float* __restrict__ bm,
    const int* __restrict__ src, const int* __restrict__ dst,
    const float* __restrict__ ea, const int* __restrict__ lbatch)
{
    extern __shared__ float dynsm[];
    float* smm  = dynsm + 4224;
    float* cs   = dynsm + 21120;
    float* se_d = dynsm + 21632;
    int*   se_a = (int*)(dynsm + 21760);
    int*   se_b = (int*)(dynsm + 21888);
    int*   se_g = (int*)(dynsm + 22016);
    unsigned* AsU = (unsigned*)dynsm;
    unsigned* WsU = (unsigned*)(dynsm + 2112);

    int tid = threadIdx.x;
    int t0 = blockIdx.x * 128;
    if (tid < 128) {
        int slot = t0 + tid;
        if (slot < EV) {
            int e = g_src_edges[slot];
            int s = src[e];
            se_a[tid] = s; se_b[tid] = dst[e];
            se_d[tid] = ea[e];
            se_g[tid] = lbatch[s];
        } else { se_a[tid] = 0; se_b[tid] = 0; se_d[tid] = 0.f; se_g[tid] = -1; }
    }
    for (int i = tid; i < 512; i += 256) cs[i] = g_cvec[i];
    __syncthreads();

    int warp = tid >> 5, lane = tid & 31;
    int g = lane >> 2, t = lane & 3;
    int warp_m = warp >> 1, warp_n = warp & 1;

    int le  = tid >> 1;
    int lk8 = (tid & 1) * 8;
    const float* arow = Al + (size_t)se_a[le] * 512;
    const float* brow = Bp + (size_t)se_b[le] * 512;
    float dv = se_d[le];
    int wrow = tid >> 4;
    int wcol = (tid & 15) * 8;

    // ---- GEMM 1 (tf32 mma): m = relu(A[src]+B[dst]+d*cvec) @ W2 ----
    float4 facc[2][8];
    #pragma unroll
    for (int mt = 0; mt < 2; mt++)
        #pragma unroll
        for (int nt = 0; nt < 8; nt++) facc[mt][nt] = make_float4(0.f, 0.f, 0.f, 0.f);

    for (int k = 0; k < 512; k += 16) {
        const float* pa = arow + k + lk8;
        const float* pb = brow + k + lk8;
        float4 a0 = *(const float4*)pa, a1 = *(const float4*)(pa + 4);
        float4 b0 = *(const float4*)pb, b1 = *(const float4*)(pb + 4);
        float4 c0 = *(const float4*)(cs + k + lk8), c1 = *(const float4*)(cs + k + lk8 + 4);
        AsU[(lk8 + 0) * 132 + le] = f2tf32(fmaxf(a0.x + b0.x + dv * c0.x, 0.f));
        AsU[(lk8 + 1) * 132 + le] = f2tf32(fmaxf(a0.y + b0.y + dv * c0.y, 0.f));
        AsU[(lk8 + 2) * 132 + le] = f2tf32(fmaxf(a0.z + b0.z + dv * c0.z, 0.f));
        AsU[(lk8 + 3) * 132 + le] = f2tf32(fmaxf(a0.w + b0.w + dv * c0.w, 0.f));
        AsU[(lk8 + 4) * 132 + le] = f2tf32(fmaxf(a1.x + b1.x + dv * c1.x, 0.f));
        AsU[(lk8 + 5) * 132 + le] = f2tf32(fmaxf(a1.y + b1.y + dv * c1.y, 0.f));
        AsU[(lk8 + 6) * 132 + le] = f2tf32(fmaxf(a1.z + b1.z + dv * c1.z, 0.f));
        AsU[(lk8 + 7) * 132 + le] = f2tf32(fmaxf(a1.w + b1.w + dv * c1.w, 0.f));
        {
            const float* p = W2 + (size_t)(k + wrow) * 128 + wcol;
            float4 w0 = *(const float4*)p, w1 = *(const float4*)(p + 4);
            WsU[wrow * 132 + wcol + 0] = f2tf32(w0.x);
            WsU[wrow * 132 + wcol + 1] = f2tf32(w0.y);
            WsU[wrow * 132 + wcol + 2] = f2tf32(w0.z);
            WsU[wrow * 132 + wcol + 3] = f2tf32(w0.w);
            WsU[wrow * 132 + wcol + 4] = f2tf32(w1.x);
            WsU[wrow * 132 + wcol + 5] = f2tf32(w1.y);
            WsU[wrow * 132 + wcol + 6] = f2tf32(w1.z);
            WsU[wrow * 132 + wcol + 7] = f2tf32(w1.w);
        }
        __syncthreads();
        #pragma unroll
        for (int kb = 0; kb < 16; kb += 8) {
            unsigned af[2][4];
            #pragma unroll
            for (int mt = 0; mt < 2; mt++) {
                int rowb = warp_m * 32 + mt * 16;
                af[mt][0] = AsU[(kb + t) * 132 + rowb + g];
                af[mt][1] = AsU[(kb + t) * 132 + rowb + g + 8];
                af[mt][2] = AsU[(kb + t + 4) * 132 + rowb + g];
                af[mt][3] = AsU[(kb + t + 4) * 132 + rowb + g + 8];
            }
            #pragma unroll
            for (int nt = 0; nt < 8; nt++) {
                int colb = warp_n * 64 + nt * 8;
                unsigned bf0 = WsU[(kb + t) * 132 + colb + g];
                unsigned bf1 = WsU[(kb + t + 4) * 132 + colb + g];
                mma_tf32(facc[0][nt], af[0][0], af[0][1], af[0][2], af[0][3], bf0, bf1);
                mma_tf32(facc[1][nt], af[1][0], af[1][1], af[1][2], af[1][3], bf0, bf1);
            }
        }
        __syncthreads();
    }

    // m = facc + b2 -> smm (fragment-layout stores, fp32)
    #pragma unroll
    for (int mt = 0; mt < 2; mt++) {
        int rowb = warp_m * 32 + mt * 16;
        #pragma unroll
        for (int nt = 0; nt < 8; nt++) {
            int cc = warp_n * 64 + nt * 8 + 2 * t;
            float ba = b2[cc], bb_ = b2[cc + 1];
            *(float2*)(smm + (rowb + g) * 132 + cc) =
                make_float2(facc[mt][nt].x + ba, facc[mt][nt].y + bb_);
            *(float2*)(smm + (rowb + g + 8) * 132 + cc) =
                make_float2(facc[mt][nt].z + ba, facc[mt][nt].w + bb_);
        }
    }
    __syncthreads();

    // ---- GEMM 2 (tf32 mma): u = m @ Wm ; w = tanh(u + bm) ----
    float4 facc2[2][8];
    #pragma unroll
    for (int mt = 0; mt < 2; mt++)
        #pragma unroll
        for (int nt = 0; nt < 8; nt++) facc2[mt][nt] = make_float4(0.f, 0.f, 0.f, 0.f);

    for (int k = 0; k < 128; k += 16) {
        {
            const float* p = Wm + (size_t)(k + wrow) * 128 + wcol;
            float4 w0 = *(const float4*)p, w1 = *(const float4*)(p + 4);
            WsU[wrow * 132 + wcol + 0] = f2tf32(w0.x);
            WsU[wrow * 132 + wcol + 1] = f2tf32(w0.y);
            WsU[wrow * 132 + wcol + 2] = f2tf32(w0.z);
            WsU[wrow * 132 + wcol + 3] = f2tf32(w0.w);
            WsU[wrow * 132 + wcol + 4] = f2tf32(w1.x);
            WsU[wrow * 132 + wcol + 5] = f2tf32(w1.y);
            WsU[wrow * 132 + wcol + 6] = f2tf32(w1.z);
            WsU[wrow * 132 + wcol + 7] = f2tf32(w1.w);
        }
        __syncthreads();
        #pragma unroll
        for (int kb = 0; kb < 16; kb += 8) {
            unsigned af[2][4];
            #pragma unroll
            for (int mt = 0; mt < 2; mt++) {
                int rowb = warp_m * 32 + mt * 16;
                af[mt][0] = f2tf32(smm[(rowb + g) * 132 + k + kb + t]);
                af[mt][1] = f2tf32(smm[(rowb + g + 8) * 132 + k + kb + t]);
                af[mt][2] = f2tf32(smm[(rowb + g) * 132 + k + kb + t + 4]);
                af[mt][3] = f2tf32(smm[(rowb + g + 8) * 132 + k + kb + t + 4]);
            }
            #pragma unroll
            for (int nt = 0; nt < 8; nt++) {
                int colb = warp_n * 64 + nt * 8;
                unsigned bf0 = WsU[(kb + t) * 132 + colb + g];
                unsigned bf1 = WsU[(kb + t + 4) * 132 + colb + g];
                mma_tf32(facc2[0][nt], af[0][0], af[0][1], af[0][2], af[0][3], bf0, bf1);
                mma_tf32(facc2[1][nt], af[1][0], af[1][1], af[1][2], af[1][3], bf0, bf1);
            }
        }
        __syncthreads();
    }

    // ---- per-graph reduction (fragment layout) ----
    {
        int row_block = warp_m * 32;
        bool uniform = (se_g[row_block] == se_g[row_block + 31]) && (se_g[row_block] >= 0);
        if (uniform) {
            int gg = se_g[row_block];
            #pragma unroll
            for (int nt = 0; nt < 8; nt++) {
                int cc = warp_n * 64 + nt * 8 + 2 * t;
                float b0 = bm[cc], b1 = bm[cc + 1];
                float ps0 = 0.f, ps1 = 0.f, mx0 = -INFINITY, mx1 = -INFINITY;
                #pragma unroll
                for (int mt = 0; mt < 2; mt++) {
                    int r0 = warp_m * 32 + mt * 16 + g, r1 = r0 + 8;
                    float m00 = smm[r0 * 132 + cc], m01 = smm[r0 * 132 + cc + 1];
                    float m10 = smm[r1 * 132 + cc], m11 = smm[r1 * 132 + cc + 1];
                    ps0 += fast_tanh(facc2[mt][nt].x + b0) * m00
                         + fast_tanh(facc2[mt][nt].z + b0) * m10;
                    ps1 += fast_tanh(facc2[mt][nt].y + b1) * m01
                         + fast_tanh(facc2[mt][nt].w + b1) * m11;
                    mx0 = fmaxf(mx0, fmaxf(m00, m10));
                    mx1 = fmaxf(mx1, fmaxf(m01, m11));
                }
                #pragma unroll
                for (int off = 4; off < 32; off <<= 1) {
                    ps0 += __shfl_xor_sync(0xffffffffu, ps0, off);
                    ps1 += __shfl_xor_sync(0xffffffffu, ps1, off);
                    mx0 = fmaxf(mx0, __shfl_xor_sync(0xffffffffu, mx0, off));
                    mx1 = fmaxf(mx1, __shfl_xor_sync(0xffffffffu, mx1, off));
                }
                if (g == 0) {
                    atomicAdd(&g_out_w[gg * 128 + cc], ps0);
                    atomicAdd(&g_out_w[gg * 128 + cc + 1], ps1);
                    atomicMaxFloat(&g_out_max[gg * 128 + cc], mx0);
                    atomicMaxFloat(&g_out_max[gg * 128 + cc + 1], mx1);
                }
            }
        } else {
            #pragma unroll
            for (int nt = 0; nt < 8; nt++) {
                int cc = warp_n * 64 + nt * 8 + 2 * t;
                float b0 = bm[cc], b1 = bm[cc + 1];
                #pragma unroll
                for (int mt = 0; mt < 2; mt++) {
                    int r0 = warp_m * 32 + mt * 16 + g, r1 = r0 + 8;
                    int g0 = se_g[r0], g1 = se_g[r1];
                    if (g0 >= 0) {
                        float m00 = smm[r0 * 132 + cc], m01 = smm[r0 * 132 + cc + 1];
                        atomicAdd(&g_out_w[g0 * 128 + cc],
                                  fast_tanh(facc2[mt][nt].x + b0) * m00);
                        atomicAdd(&g_out_w[g0 * 128 + cc + 1],
                                  fast_tanh(facc2[mt][nt].y + b1) * m01);
                        atomicMaxFloat(&g_out_max[g0 * 128 + cc], m00);
                        atomicMaxFloat(&g_out_max[g0 * 128 + cc + 1], m01);
                    }
                    if (g1 >= 0) {
                        float m10 = smm[r1 * 132 + cc], m11 = smm[r1 * 132 + cc + 1];
                        atomicAdd(&g_out_w[g1 * 128 + cc],
                                  fast_tanh(facc2[mt][nt].z + b0) * m10);
                        atomicAdd(&g_out_w[g1 * 128 + cc + 1],
                                  fast_tanh(facc2[mt][nt].w + b1) * m11);
                        atomicMaxFloat(&g_out_max[g1 * 128 + cc], m10);
                        atomicMaxFloat(&g_out_max[g1 * 128 + cc + 1], m11);
                    }
                }
            }
        }
    }
}

__global__ void k_final(float* __restrict__ out) {
    int i = blockIdx.x * 256 + threadIdx.x;
    if (i < NGV * 256) {
        int g = i >> 8, j = i & 255;
        float v;
        if (j < 128) v = g_out_w[g * 128 + j];
        else {
            v = g_out_max[g * 128 + j - 128];
            if (!isfinite(v)) v = 0.f;
        }
        out[i] = v;
    }
}

// ---------------- host orchestration ----------------
#define SYM(p, s) do { void* _t = nullptr; cudaGetSymbolAddress(&_t, s); p = (decltype(p))_t; } while (0)

extern "C" void kernel_launch(void* const* d_in, const int* in_sizes, int n_in,
                              void* d_out, int out_size) {
    const float* x_l    = (const float*)d_in[0];
    const float* x_p    = (const float*)d_in[1];
    const float* ea     = (const float*)d_in[2];
    const int*   esrc   = (const int*)  d_in[3];
    const int*   edst   = (const int*)  d_in[4];
    const int*   lbatch = (const int*)  d_in[5];
    const float* W_node = (const float*)d_in[6];
    const float* W_el   = (const float*)d_in[7];
    const float* Wb     = (const float*)d_in[8];
    const float* bb     = (const float*)d_in[9];
    const float* Wn     = (const float*)d_in[10];
    const float* Ws_    = (const float*)d_in[11];
    const float* bconv  = (const float*)d_in[12];
    const float* W1     = (const float*)d_in[13];
    const float* b1     = (const float*)d_in[14];
    const float* W2     = (const float*)d_in[15];
    const float* b2     = (const float*)d_in[16];
    const float* Wm     = (const float*)d_in[17];
    const float* bm     = (const float*)d_in[18];

    float *xl, *xl2, *xlsum, *prel, *xp, *xp2, *xpsum, *prep, *Abuf, *Bbuf;
    int *dcnt, *dptr, *dedges, *scnt, *sptr, *sedges, *stmp, *bsum;
    SYM(xl, g_xl); SYM(xl2, g_xl2); SYM(xlsum, g_xlsum); SYM(prel, g_prel);
    SYM(xp, g_xp); SYM(xp2, g_xp2); SYM(xpsum, g_xpsum); SYM(prep, g_prep);
    SYM(Abuf, g_A); SYM(Bbuf, g_B);
    SYM(dcnt, g_dst_cnt); SYM(dptr, g_dst_ptr); SYM(dedges, g_dst_edges);
    SYM(scnt, g_src_cnt); SYM(sptr, g_src_ptr); SYM(sedges, g_src_edges);
    SYM(stmp, g_scan_tmp); SYM(bsum, g_bsum);

    cudaFuncSetAttribute(k_edge, cudaFuncAttributeMaxDynamicSharedMemorySize,
                         EDGE_SMEM_FLOATS * (int)sizeof(float));

    // node embedding
    k_embed<<<(NLV + 3) / 4, 128>>>(x_l, xl, W_node, NLV);
    k_embed<<<(NPV + 3) / 4, 128>>>(x_p, xp, W_node, NPV);

    // rbf + cvec
    k_rbf<<<(EV + 255) / 256, 256>>>(ea);
    k_cvec<<<2, 256>>>(W_el, W1);

    // CSR (dst and src)
    cudaMemsetAsync(dcnt, 0, NPV * sizeof(int));
    cudaMemsetAsync(scnt, 0, NLV * sizeof(int));
    k_hist<<<(EV + 255) / 256, 256>>>(esrc, edst);
    int nbp = (NPV + 1023) / 1024, nbl = (NLV + 1023) / 1024;
    k_scan1<<<nbp, 1024>>>(dcnt, stmp, bsum, NPV);
    k_scan2<<<1, 1>>>(bsum, nbp);
    k_scan3<<<nbp, 1024>>>(stmp, bsum, dptr, NPV);
    k_scan1<<<nbl, 1024>>>(scnt, stmp, bsum, NLV);
    k_scan2<<<1, 1>>>(bsum, nbl);
    k_scan3<<<nbl, 1024>>>(stmp, bsum, sptr, NLV);
    cudaMemsetAsync(dcnt, 0, NPV * sizeof(int));
    cudaMemsetAsync(scnt, 0, NLV * sizeof(int));
    k_fill<<<(EV + 255) / 256, 256>>>(esrc, edst);

    // running sums
    cudaMemsetAsync(xlsum, 0, (size_t)NLV * 128 * sizeof(float));
    cudaMemsetAsync(xpsum, 0, (size_t)NPV * 128 * sizeof(float));

    // 3 hetero layers (tf32 mma conv GEMMs)
    float *cxl = xl, *cxp = xp, *nxl = xl2, *nxp = xp2;
    for (int l = 0; l < 3; l++) {
        int ilp = 2 * l, ipl = 2 * l + 1;
        k_agg<<<(NPV * 32 + 255) / 256, 256>>>(dptr, dedges, esrc, cxl,
                Wb + ilp * 1024, bb + ilp * 128, prep, NPV);
        k_agg<<<(NLV * 32 + 255) / 256, 256>>>(sptr, sedges, edst, cxp,
                Wb + ipl * 1024, bb + ipl * 128, prel, NLV);
        k_mma<<<dim3(1, (NPV + 127) / 128), 256>>>(cxp, Ws_ + (size_t)ilp * 16384,
                prep, Wn + (size_t)ilp * 16384, bconv + ilp * 128,
                nxp, xpsum, NPV, 128, 128, 128, 1);
        k_mma<<<dim3(1, (NLV + 127) / 128), 256>>>(cxl, Ws_ + (size_t)ipl * 16384,
                prel, Wn + (size_t)ipl * 16384, bconv + ipl * 128,
                nxl, xlsum, NLV, 128, 128, 128, 1);
        float* t;
        t = cxl; cxl = nxl; nxl = t;
        t = cxp; cxp = nxp; nxp = t;
    }

    // edge readout factorization (tf32 mma)
    k_mma<<<dim3(4, (NLV + 127) / 128), 256>>>(xlsum, W1, nullptr, nullptr, b1,
            Abuf, nullptr, NLV, 512, 128, 0, 0);
    k_mma<<<dim3(4, (NPV + 127) / 128), 256>>>(xpsum, W1 + (size_t)128 * 512,
            nullptr, nullptr, nullptr, Bbuf, nullptr, NPV, 512, 128, 0, 0);

    k_init_out<<<(NGV * 128 + 255) / 256, 256>>>();
    k_edge<<<(EV + 127) / 128, 256, EDGE_SMEM_FLOATS * (int)sizeof(float)>>>(
            Abuf, Bbuf, W2, b2, Wm, bm, esrc, edst, ea, lbatch);
    k_final<<<(NGV * 256 + 255) / 256, 256>>>((float*)d_out);
}

// round 11
// speedup vs baseline: 2.2504x; 1.0580x over previous
#include <cuda_runtime.h>
#include <math.h>

#define NLV 50000
#define NPV 150000
#define EV  500000
#define NGV 256

// ---------------- device-global scratch ----------------
__device__ float g_xl   [NLV*128];
__device__ float g_xl2  [NLV*128];
__device__ float g_xlsum[NLV*128];
__device__ float g_prel [NLV*128];
__device__ float g_xp   [NPV*128];
__device__ float g_xp2  [NPV*128];
__device__ float g_xpsum[NPV*128];
__device__ float g_prep [NPV*128];
__device__ float g_rbf  [EV*8];
__device__ float g_A    [(size_t)NLV*512];
__device__ float g_B    [(size_t)NPV*512];
__device__ float g_cvec [512];
__device__ int   g_dst_cnt[NPV];
__device__ int   g_dst_ptr[NPV+1];
__device__ int   g_dst_edges[EV];
__device__ int   g_src_cnt[NLV];
__device__ int   g_src_ptr[NLV+1];
__device__ int   g_src_edges[EV];
__device__ int   g_scan_tmp[NPV];
__device__ int   g_bsum[512];
__device__ float g_out_w  [NGV*128];
__device__ float g_out_max[NGV*128];

// ---------------- helpers ----------------
__device__ __forceinline__ void atomicMaxFloat(float* addr, float v) {
    if (v >= 0.0f) atomicMax((int*)addr, __float_as_int(v));
    else           atomicMin((unsigned int*)addr, __float_as_uint(v));
}
__device__ __forceinline__ float fast_tanh(float x) {
    float y; asm("tanh.approx.f32 %0, %1;" : "=f"(y) : "f"(x)); return y;
}
__device__ __forceinline__ unsigned f2tf32(float f) {
    unsigned u; asm("cvt.rna.tf32.f32 %0, %1;" : "=r"(u) : "f"(f)); return u;
}
__device__ __forceinline__ void mma_tf32(float4& d,
        unsigned a0, unsigned a1, unsigned a2, unsigned a3,
        unsigned b0, unsigned b1) {
    asm("mma.sync.aligned.m16n8k8.row.col.f32.tf32.tf32.f32 "
        "{%0,%1,%2,%3}, {%4,%5,%6,%7}, {%8,%9}, {%0,%1,%2,%3};"
        : "+f"(d.x), "+f"(d.y), "+f"(d.z), "+f"(d.w)
        : "r"(a0), "r"(a1), "r"(a2), "r"(a3), "r"(b0), "r"(b1));
}

// ---------------- node embedding ----------------
__global__ void k_embed(const float* __restrict__ X, float* __restrict__ Y,
                        const float* __restrict__ Wn, int M) {
    __shared__ float xs[4][44];
    int r0 = blockIdx.x * 4;
    int tid = threadIdx.x;  // 128
    for (int i = tid; i < 4 * 44; i += 128) {
        int rr = i / 44, kk = i % 44;
        xs[rr][kk] = (r0 + rr < M) ? X[(size_t)(r0 + rr) * 44 + kk] : 0.f;
    }
    __syncthreads();
    int col = tid;
    #pragma unroll
    for (int rr = 0; rr < 4; rr++) {
        if (r0 + rr < M) {
            float s = 0.f;
            #pragma unroll
            for (int kk = 0; kk < 44; kk++) s = fmaf(xs[rr][kk], Wn[kk * 128 + col], s);
            Y[(size_t)(r0 + rr) * 128 + col] = s;
        }
    }
}

// ---------------- RBF ----------------
__global__ void k_rbf(const float* __restrict__ ea) {
    int e = blockIdx.x * 256 + threadIdx.x;
    if (e < EV) {
        float d = ea[e];
        #pragma unroll
        for (int k = 0; k < 8; k++) {
            float t = (d - (5.0f / 7.0f) * (float)k) * 1.6f;
            g_rbf[e * 8 + k] = __expf(-t * t);
        }
    }
}

// ---------------- CSR construction ----------------
__global__ void k_hist(const int* __restrict__ src, const int* __restrict__ dst) {
    int e = blockIdx.x * 256 + threadIdx.x;
    if (e < EV) {
        atomicAdd(&g_dst_cnt[dst[e]], 1);
        atomicAdd(&g_src_cnt[src[e]], 1);
    }
}
__global__ void k_scan1(const int* __restrict__ cnt, int* __restrict__ excl,
                        int* __restrict__ bsum, int n) {
    __shared__ int s[1024];
    int i = blockIdx.x * 1024 + threadIdx.x;
    int v = (i < n) ? cnt[i] : 0;
    s[threadIdx.x] = v;
    __syncthreads();
    for (int off = 1; off < 1024; off <<= 1) {
        int t = 0;
        if ((int)threadIdx.x >= off) t = s[threadIdx.x - off];
        __syncthreads();
        s[threadIdx.x] += t;
        __syncthreads();
    }
    if (i < n) excl[i] = s[threadIdx.x] - v;
    if (threadIdx.x == 1023) bsum[blockIdx.x] = s[1023];
}
// parallel exclusive scan over <=512 block sums (single block)
__global__ void k_scan2(int* bsum, int nb) {
    __shared__ int s[512];
    int i = threadIdx.x;
    int v = (i < nb) ? bsum[i] : 0;
    s[i] = v;
    __syncthreads();
    for (int off = 1; off < 512; off <<= 1) {
        int t = 0;
        if (i >= off) t = s[i - off];
        __syncthreads();
        s[i] += t;
        __syncthreads();
    }
    if (i < nb) bsum[i] = s[i] - v;
}
__global__ void k_scan3(const int* __restrict__ excl, const int* __restrict__ bsum,
                        int* __restrict__ ptr, int n) {
    int i = blockIdx.x * 1024 + threadIdx.x;
    if (i < n) ptr[i] = excl[i] + bsum[i >> 10];
    if (i == 0) ptr[n] = EV;
}
__global__ void k_fill(const int* __restrict__ src, const int* __restrict__ dst) {
    int e = blockIdx.x * 256 + threadIdx.x;
    if (e < EV) {
        int d = dst[e]; int p = atomicAdd(&g_dst_cnt[d], 1); g_dst_edges[g_dst_ptr[d] + p] = e;
        int s = src[e]; int q = atomicAdd(&g_src_cnt[s], 1); g_src_edges[g_src_ptr[s] + q] = e;
    }
}

// ---------------- aggregation ----------------
__global__ __launch_bounds__(256) void k_agg(
    const int* __restrict__ ptr, const int* __restrict__ eidx,
    const int* __restrict__ partner, const float* __restrict__ xsrc,
    const float* __restrict__ Wb_i, const float* __restrict__ bb_i,
    float* __restrict__ pre, int n_dst)
{
    int w = (blockIdx.x * blockDim.x + threadIdx.x) >> 5;
    int lane = threadIdx.x & 31;
    if (w >= n_dst) return;
    float wreg[8][4], bias[4], acc[4] = {0.f, 0.f, 0.f, 0.f};
    #pragma unroll
    for (int c = 0; c < 4; c++) {
        bias[c] = bb_i[c * 32 + lane];
        #pragma unroll
        for (int k = 0; k < 8; k++) wreg[k][c] = Wb_i[k * 128 + c * 32 + lane];
    }
    int s = ptr[w], e = ptr[w + 1];
    for (int p = s; p < e; p++) {
        int ed = eidx[p];
        float rv = (lane < 8) ? g_rbf[ed * 8 + lane] : 0.f;
        float r[8];
        #pragma unroll
        for (int k = 0; k < 8; k++) r[k] = __shfl_sync(0xffffffffu, rv, k);
        const float* xr = xsrc + (size_t)partner[ed] * 128;
        #pragma unroll
        for (int c = 0; c < 4; c++) {
            float t = bias[c];
            #pragma unroll
            for (int k = 0; k < 8; k++) t = fmaf(r[k], wreg[k][c], t);
            float sg = 1.f / (1.f + __expf(-t));
            acc[c] += (t * sg) * xr[c * 32 + lane];
        }
    }
    float inv = 1.f / (float)((e - s) > 1 ? (e - s) : 1);
    #pragma unroll
    for (int c = 0; c < 4; c++) pre[(size_t)w * 128 + c * 32 + lane] = acc[c] * inv;
}

// ---------------- tf32 mma fused GEMM (double-buffered, reg-prefetch) ----------
// C[M,N] = act( A0[M,K0]@W0 + A1[M,K1]@W1 + bias ); optional sum += C
__global__ __launch_bounds__(256, 2) void k_mma(
    const float* __restrict__ A0, const float* __restrict__ W0,
    const float* __restrict__ A1, const float* __restrict__ W1,
    const float* __restrict__ bias, float* __restrict__ C,
    float* __restrict__ sum, int M, int N, int K0, int K1, int act)
{
    __shared__ unsigned AsU[2 * 16 * 132];
    __shared__ unsigned WsU[2 * 16 * 132];
    int tid = threadIdx.x;
    int m0 = blockIdx.y * 128;
    int n0 = blockIdx.x * 128;
    int K = K0 + K1;
    int nkt = K >> 4;

    int warp = tid >> 5, lane = tid & 31;
    int g = lane >> 2, t = lane & 3;
    int warp_m = warp >> 1, warp_n = warp & 1;

    int le  = tid >> 1;
    int lk8 = (tid & 1) * 8;
    int arow = m0 + le;
    int wrow = tid >> 4;
    int wcol = (tid & 15) * 8;

    float4 facc[2][8];
    #pragma unroll
    for (int mt = 0; mt < 2; mt++)
        #pragma unroll
        for (int nt = 0; nt < 8; nt++) facc[mt][nt] = make_float4(0.f, 0.f, 0.f, 0.f);

    float4 pa0, pa1, pw0, pw1;
    // prologue: load k-block 0
    {
        const float* Ab = (0 < K0) ? A0 : A1;
        const float* Wb_ = (0 < K0) ? W0 : W1;
        int stride = (0 < K0) ? K0 : K1;
        pa0 = make_float4(0.f,0.f,0.f,0.f); pa1 = pa0;
        if (arow < M) {
            const float* p = Ab + (size_t)arow * stride + lk8;
            pa0 = *(const float4*)p; pa1 = *(const float4*)(p + 4);
        }
        const float* pw = Wb_ + (size_t)wrow * N + n0 + wcol;
        pw0 = *(const float4*)pw; pw1 = *(const float4*)(pw + 4);
    }

    for (int kt = 0; kt < nkt; kt++) {
        int buf = (kt & 1) * 2112;
        // store current regs (tf32)
        AsU[buf + (lk8 + 0) * 132 + le] = f2tf32(pa0.x);
        AsU[buf + (lk8 + 1) * 132 + le] = f2tf32(pa0.y);
        AsU[buf + (lk8 + 2) * 132 + le] = f2tf32(pa0.z);
        AsU[buf + (lk8 + 3) * 132 + le] = f2tf32(pa0.w);
        AsU[buf + (lk8 + 4) * 132 + le] = f2tf32(pa1.x);
        AsU[buf + (lk8 + 5) * 132 + le] = f2tf32(pa1.y);
        AsU[buf + (lk8 + 6) * 132 + le] = f2tf32(pa1.z);
        AsU[buf + (lk8 + 7) * 132 + le] = f2tf32(pa1.w);
        WsU[buf + wrow * 132 + wcol + 0] = f2tf32(pw0.x);
        WsU[buf + wrow * 132 + wcol + 1] = f2tf32(pw0.y);
        WsU[buf + wrow * 132 + wcol + 2] = f2tf32(pw0.z);
        WsU[buf + wrow * 132 + wcol + 3] = f2tf32(pw0.w);
        WsU[buf + wrow * 132 + wcol + 4] = f2tf32(pw1.x);
        WsU[buf + wrow * 132 + wcol + 5] = f2tf32(pw1.y);
        WsU[buf + wrow * 132 + wcol + 6] = f2tf32(pw1.z);
        WsU[buf + wrow * 132 + wcol + 7] = f2tf32(pw1.w);
        // prefetch next k-block
        if (kt + 1 < nkt) {
            int k = (kt + 1) * 16;
            const float* Ab; const float* Wb_; int kl; int stride;
            if (k < K0) { Ab = A0; Wb_ = W0; kl = k; stride = K0; }
            else        { Ab = A1; Wb_ = W1; kl = k - K0; stride = K1; }
            pa0 = make_float4(0.f,0.f,0.f,0.f); pa1 = pa0;
            if (arow < M) {
                const float* p = Ab + (size_t)arow * stride + kl + lk8;
                pa0 = *(const float4*)p; pa1 = *(const float4*)(p + 4);
            }
            const float* pw = Wb_ + (size_t)(kl + wrow) * N + n0 + wcol;
            pw0 = *(const float4*)pw; pw1 = *(const float4*)(pw + 4);
        }
        __syncthreads();
        #pragma unroll
        for (int kb = 0; kb < 16; kb += 8) {
            unsigned af[2][4];
            #pragma unroll
            for (int mt = 0; mt < 2; mt++) {
                int rowb = warp_m * 32 + mt * 16;
                af[mt][0] = AsU[buf + (kb + t) * 132 + rowb + g];
                af[mt][1] = AsU[buf + (kb + t) * 132 + rowb + g + 8];
                af[mt][2] = AsU[buf + (kb + t + 4) * 132 + rowb + g];
                af[mt][3] = AsU[buf + (kb + t + 4) * 132 + rowb + g + 8];
            }
            #pragma unroll
            for (int nt = 0; nt < 8; nt++) {
                int colb = warp_n * 64 + nt * 8;
                unsigned bf0 = WsU[buf + (kb + t) * 132 + colb + g];
                unsigned bf1 = WsU[buf + (kb + t + 4) * 132 + colb + g];
                mma_tf32(facc[0][nt], af[0][0], af[0][1], af[0][2], af[0][3], bf0, bf1);
                mma_tf32(facc[1][nt], af[1][0], af[1][1], af[1][2], af[1][3], bf0, bf1);
            }
        }
    }
    #pragma unroll
    for (int mt = 0; mt < 2; mt++) {
        int rowb = m0 + warp_m * 32 + mt * 16;
        #pragma unroll
        for (int nt = 0; nt < 8; nt++) {
            int col = n0 + warp_n * 64 + nt * 8 + 2 * t;
            float ba = 0.f, bb_ = 0.f;
            if (bias) { ba = bias[col]; bb_ = bias[col + 1]; }
            int r0 = rowb + g, r1 = rowb + g + 8;
            float vx = facc[mt][nt].x + ba, vy = facc[mt][nt].y + bb_;
            float vz = facc[mt][nt].z + ba, vw = facc[mt][nt].w + bb_;
            if (act == 1) {
                vx = (vx >= 0.f) ? vx : 0.01f * vx;
                vy = (vy >= 0.f) ? vy : 0.01f * vy;
                vz = (vz >= 0.f) ? vz : 0.01f * vz;
                vw = (vw >= 0.f) ? vw : 0.01f * vw;
            }
            if (r0 < M) {
                *(float2*)(C + (size_t)r0 * N + col) = make_float2(vx, vy);
                if (sum) {
                    float2 s = *(float2*)(sum + (size_t)r0 * N + col);
                    s.x += vx; s.y += vy;
                    *(float2*)(sum + (size_t)r0 * N + col) = s;
                }
            }
            if (r1 < M) {
                *(float2*)(C + (size_t)r1 * N + col) = make_float2(vz, vw);
                if (sum) {
                    float2 s = *(float2*)(sum + (size_t)r1 * N + col);
                    s.x += vz; s.y += vw;
                    *(float2*)(sum + (size_t)r1 * N + col) = s;
                }
            }
        }
    }
}

// ---------------- cvec ----------------
__global__ void k_cvec(const float* __restrict__ W_el, const float* __restrict__ W1) {
    int j = blockIdx.x * 256 + threadIdx.x;
    if (j < 512) {
        float s = 0.f;
        #pragma unroll
        for (int k = 0; k < 8; k++) s = fmaf(W_el[k], W1[(size_t)(256 + k) * 512 + j], s);
        g_cvec[j] = s;
    }
}

__global__ void k_init_out() {
    int i = blockIdx.x * 256 + threadIdx.x;
    if (i < NGV * 128) { g_out_w[i] = 0.f; g_out_max[i] = -INFINITY; }
}

// ---------------- fused edge MLP + per-graph reduction: 128-edge tiles ------------
// dynamic smem layout (floats):
//   As   [2][16*132] @ 0      (tf32 bits, double-buffered)
//   Ws   [2][16*132] @ 4224   (tf32 bits, double-buffered)
//   smm  [128*132]   @ 8448   (fp32 m matrix)
//   cs   [512]       @ 25344
//   se_d [128]       @ 25856
//   se_a [128] (int) @ 25984
//   se_b [128] (int) @ 26112
//   se_g [128] (int) @ 26240
#define EDGE_SMEM_FLOATS 26368
__global__ __launch_bounds__(256, 2) void k_edge(
    const float* __restrict__ Al, const float* __restrict__ Bp,
    const float* __restrict__ W2, const float* __restrict__ b2,
    const float* __restrict__ Wm, const float* __restrict__ bm,
    const int* __restrict__ src, const int* __restrict__ dst,
    const float* __restrict__ ea, const int* __restrict__ lbatch)
{
    extern __shared__ float dynsm[];
    float* smm  = dynsm + 8448;
    float* cs   = dynsm + 25344;
    float* se_d = dynsm + 25856;
    int*   se_a = (int*)(dynsm + 25984);
    int*   se_b = (int*)(dynsm + 26112);
    int*   se_g = (int*)(dynsm + 26240);
    unsigned* AsU = (unsigned*)dynsm;
    unsigned* WsU = (unsigned*)(dynsm + 4224);

    int tid = threadIdx.x;
    int t0 = blockIdx.x * 128;
    if (tid < 128) {
        int slot = t0 + tid;
        if (slot < EV) {
            int e = g_src_edges[slot];
            int s = src[e];
            se_a[tid] = s; se_b[tid] = dst[e];
            se_d[tid] = ea[e];
            se_g[tid] = lbatch[s];
        } else { se_a[tid] = 0; se_b[tid] = 0; se_d[tid] = 0.f; se_g[tid] = -1; }
    }
    for (int i = tid; i < 512; i += 256) cs[i] = g_cvec[i];
    __syncthreads();

    int warp = tid >> 5, lane = tid & 31;
    int g = lane >> 2, t = lane & 3;
    int warp_m = warp >> 1, warp_n = warp & 1;

    int le  = tid >> 1;
    int lk8 = (tid & 1) * 8;
    const float* arow = Al + (size_t)se_a[le] * 512;
    const float* brow = Bp + (size_t)se_b[le] * 512;
    float dv = se_d[le];
    int wrow = tid >> 4;
    int wcol = (tid & 15) * 8;

    // ---- GEMM 1 (tf32 mma, double-buffered): m = relu(A[src]+B[dst]+d*cvec) @ W2 --
    float4 facc[2][8];
    #pragma unroll
    for (int mt = 0; mt < 2; mt++)
        #pragma unroll
        for (int nt = 0; nt < 8; nt++) facc[mt][nt] = make_float4(0.f, 0.f, 0.f, 0.f);

    float4 pa0, pa1, pb0, pb1, pw0, pw1;
    {
        const float* pa = arow + lk8;
        const float* pb = brow + lk8;
        pa0 = *(const float4*)pa; pa1 = *(const float4*)(pa + 4);
        pb0 = *(const float4*)pb; pb1 = *(const float4*)(pb + 4);
        const float* pw = W2 + (size_t)wrow * 128 + wcol;
        pw0 = *(const float4*)pw; pw1 = *(const float4*)(pw + 4);
    }

    for (int kt = 0; kt < 32; kt++) {
        int buf = (kt & 1) * 2112;
        int k = kt * 16;
        float4 c0 = *(const float4*)(cs + k + lk8), c1 = *(const float4*)(cs + k + lk8 + 4);
        AsU[buf + (lk8 + 0) * 132 + le] = f2tf32(fmaxf(pa0.x + pb0.x + dv * c0.x, 0.f));
        AsU[buf + (lk8 + 1) * 132 + le] = f2tf32(fmaxf(pa0.y + pb0.y + dv * c0.y, 0.f));
        AsU[buf + (lk8 + 2) * 132 + le] = f2tf32(fmaxf(pa0.z + pb0.z + dv * c0.z, 0.f));
        AsU[buf + (lk8 + 3) * 132 + le] = f2tf32(fmaxf(pa0.w + pb0.w + dv * c0.w, 0.f));
        AsU[buf + (lk8 + 4) * 132 + le] = f2tf32(fmaxf(pa1.x + pb1.x + dv * c1.x, 0.f));
        AsU[buf + (lk8 + 5) * 132 + le] = f2tf32(fmaxf(pa1.y + pb1.y + dv * c1.y, 0.f));
        AsU[buf + (lk8 + 6) * 132 + le] = f2tf32(fmaxf(pa1.z + pb1.z + dv * c1.z, 0.f));
        AsU[buf + (lk8 + 7) * 132 + le] = f2tf32(fmaxf(pa1.w + pb1.w + dv * c1.w, 0.f));
        WsU[buf + wrow * 132 + wcol + 0] = f2tf32(pw0.x);
        WsU[buf + wrow * 132 + wcol + 1] = f2tf32(pw0.y);
        WsU[buf + wrow * 132 + wcol + 2] = f2tf32(pw0.z);
        WsU[buf + wrow * 132 + wcol + 3] = f2tf32(pw0.w);
        WsU[buf + wrow * 132 + wcol + 4] = f2tf32(pw1.x);
        WsU[buf + wrow * 132 + wcol + 5] = f2tf32(pw1.y);
        WsU[buf + wrow * 132 + wcol + 6] = f2tf32(pw1.z);
        WsU[buf + wrow * 132 + wcol + 7] = f2tf32(pw1.w);
        if (kt + 1 < 32) {
            int kn = k + 16;
            const float* pa = arow + kn + lk8;
            const float* pb = brow + kn + lk8;
            pa0 = *(const float4*)pa; pa1 = *(const float4*)(pa + 4);
            pb0 = *(const float4*)pb; pb1 = *(const float4*)(pb + 4);
            const float* pw = W2 + (size_t)(kn + wrow) * 128 + wcol;
            pw0 = *(const float4*)pw; pw1 = *(const float4*)(pw + 4);
        }
        __syncthreads();
        #pragma unroll
        for (int kb = 0; kb < 16; kb += 8) {
            unsigned af[2][4];
            #pragma unroll
            for (int mt = 0; mt < 2; mt++) {
                int rowb = warp_m * 32 + mt * 16;
                af[mt][0] = AsU[buf + (kb + t) * 132 + rowb + g];
                af[mt][1] = AsU[buf + (kb + t) * 132 + rowb + g + 8];
                af[mt][2] = AsU[buf + (kb + t + 4) * 132 + rowb + g];
                af[mt][3] = AsU[buf + (kb + t + 4) * 132 + rowb + g + 8];
            }
            #pragma unroll
            for (int nt = 0; nt < 8; nt++) {
                int colb = warp_n * 64 + nt * 8;
                unsigned bf0 = WsU[buf + (kb + t) * 132 + colb + g];
                unsigned bf1 = WsU[buf + (kb + t + 4) * 132 + colb + g];
                mma_tf32(facc[0][nt], af[0][0], af[0][1], af[0][2], af[0][3], bf0, bf1);
                mma_tf32(facc[1][nt], af[1][0], af[1][1], af[1][2], af[1][3], bf0, bf1);
            }
        }
    }
    __syncthreads();

    // m = facc + b2 -> smm (fragment-layout stores, fp32)
    #pragma unroll
    for (int mt = 0; mt < 2; mt++) {
        int rowb = warp_m * 32 + mt * 16;
        #pragma unroll
        for (int nt = 0; nt < 8; nt++) {
            int cc = warp_n * 64 + nt * 8 + 2 * t;
            float ba = b2[cc], bb_ = b2[cc + 1];
            *(float2*)(smm + (rowb + g) * 132 + cc) =
                make_float2(facc[mt][nt].x + ba, facc[mt][nt].y + bb_);
            *(float2*)(smm + (rowb + g + 8) * 132 + cc) =
                make_float2(facc[mt][nt].z + ba, facc[mt][nt].w + bb_);
        }
    }
    __syncthreads();

    // ---- GEMM 2 (tf32 mma): u = m @ Wm ; w = tanh(u + bm) ----
    float4 facc2[2][8];
    #pragma unroll
    for (int mt = 0; mt < 2; mt++)
        #pragma unroll
        for (int nt = 0; nt < 8; nt++) facc2[mt][nt] = make_float4(0.f, 0.f, 0.f, 0.f);

    for (int kt = 0; kt < 8; kt++) {
        int buf = (kt & 1) * 2112;
        int k = kt * 16;
        {
            const float* p = Wm + (size_t)(k + wrow) * 128 + wcol;
            float4 w0 = *(const float4*)p, w1 = *(const float4*)(p + 4);
            WsU[buf + wrow * 132 + wcol + 0] = f2tf32(w0.x);
            WsU[buf + wrow * 132 + wcol + 1] = f2tf32(w0.y);
            WsU[buf + wrow * 132 + wcol + 2] = f2tf32(w0.z);
            WsU[buf + wrow * 132 + wcol + 3] = f2tf32(w0.w);
            WsU[buf + wrow * 132 + wcol + 4] = f2tf32(w1.x);
            WsU[buf + wrow * 132 + wcol + 5] = f2tf32(w1.y);
            WsU[buf + wrow * 132 + wcol + 6] = f2tf32(w1.z);
            WsU[buf + wrow * 132 + wcol + 7] = f2tf32(w1.w);
        }
        __syncthreads();
        #pragma unroll
        for (int kb = 0; kb < 16; kb += 8) {
            unsigned af[2][4];
            #pragma unroll
            for (int mt = 0; mt < 2; mt++) {
                int rowb = warp_m * 32 + mt * 16;
                af[mt][0] = f2tf32(smm[(rowb + g) * 132 + k + kb + t]);
                af[mt][1] = f2tf32(smm[(rowb + g + 8) * 132 + k + kb + t]);
                af[mt][2] = f2tf32(smm[(rowb + g) * 132 + k + kb + t + 4]);
                af[mt][3] = f2tf32(smm[(rowb + g + 8) * 132 + k + kb + t + 4]);
            }
            #pragma unroll
            for (int nt = 0; nt < 8; nt++) {
                int colb = warp_n * 64 + nt * 8;
                unsigned bf0 = WsU[buf + (kb + t) * 132 + colb + g];
                unsigned bf1 = WsU[buf + (kb + t + 4) * 132 + colb + g];
                mma_tf32(facc2[0][nt], af[0][0], af[0][1], af[0][2], af[0][3], bf0, bf1);
                mma_tf32(facc2[1][nt], af[1][0], af[1][1], af[1][2], af[1][3], bf0, bf1);
            }
        }
    }

    // ---- per-graph reduction (fragment layout) ----
    {
        int row_block = warp_m * 32;
        bool uniform = (se_g[row_block] == se_g[row_block + 31]) && (se_g[row_block] >= 0);
        if (uniform) {
            int gg = se_g[row_block];
            #pragma unroll
            for (int nt = 0; nt < 8; nt++) {
                int cc = warp_n * 64 + nt * 8 + 2 * t;
                float b0 = bm[cc], b1 = bm[cc + 1];
                float ps0 = 0.f, ps1 = 0.f, mx0 = -INFINITY, mx1 = -INFINITY;
                #pragma unroll
                for (int mt = 0; mt < 2; mt++) {
                    int r0 = warp_m * 32 + mt * 16 + g, r1 = r0 + 8;
                    float m00 = smm[r0 * 132 + cc], m01 = smm[r0 * 132 + cc + 1];
                    float m10 = smm[r1 * 132 + cc], m11 = smm[r1 * 132 + cc + 1];
                    ps0 += fast_tanh(facc2[mt][nt].x + b0) * m00
                         + fast_tanh(facc2[mt][nt].z + b0) * m10;
                    ps1 += fast_tanh(facc2[mt][nt].y + b1) * m01
                         + fast_tanh(facc2[mt][nt].w + b1) * m11;
                    mx0 = fmaxf(mx0, fmaxf(m00, m10));
                    mx1 = fmaxf(mx1, fmaxf(m01, m11));
                }
                #pragma unroll
                for (int off = 4; off < 32; off <<= 1) {
                    ps0 += __shfl_xor_sync(0xffffffffu, ps0, off);
                    ps1 += __shfl_xor_sync(0xffffffffu, ps1, off);
                    mx0 = fmaxf(mx0, __shfl_xor_sync(0xffffffffu, mx0, off));
                    mx1 = fmaxf(mx1, __shfl_xor_sync(0xffffffffu, mx1, off));
                }
                if (g == 0) {
                    atomicAdd(&g_out_w[gg * 128 + cc], ps0);
                    atomicAdd(&g_out_w[gg * 128 + cc + 1], ps1);
                    atomicMaxFloat(&g_out_max[gg * 128 + cc], mx0);
                    atomicMaxFloat(&g_out_max[gg * 128 + cc + 1], mx1);
                }
            }
        } else {
            #pragma unroll
            for (int nt = 0; nt < 8; nt++) {
                int cc = warp_n * 64 + nt * 8 + 2 * t;
                float b0 = bm[cc], b1 = bm[cc + 1];
                #pragma unroll
                for (int mt = 0; mt < 2; mt++) {
                    int r0 = warp_m * 32 + mt * 16 + g, r1 = r0 + 8;
                    int g0 = se_g[r0], g1 = se_g[r1];
                    if (g0 >= 0) {
                        float m00 = smm[r0 * 132 + cc], m01 = smm[r0 * 132 + cc + 1];
                        atomicAdd(&g_out_w[g0 * 128 + cc],
                                  fast_tanh(facc2[mt][nt].x + b0) * m00);
                        atomicAdd(&g_out_w[g0 * 128 + cc + 1],
                                  fast_tanh(facc2[mt][nt].y + b1) * m01);
                        atomicMaxFloat(&g_out_max[g0 * 128 + cc], m00);
                        atomicMaxFloat(&g_out_max[g0 * 128 + cc + 1], m01);
                    }
                    if (g1 >= 0) {
                        float m10 = smm[r1 * 132 + cc], m11 = smm[r1 * 132 + cc + 1];
                        atomicAdd(&g_out_w[g1 * 128 + cc],
                                  fast_tanh(facc2[mt][nt].z + b0) * m10);
                        atomicAdd(&g_out_w[g1 * 128 + cc + 1],
                                  fast_tanh(facc2[mt][nt].w + b1) * m11);
                        atomicMaxFloat(&g_out_max[g1 * 128 + cc], m10);
                        atomicMaxFloat(&g_out_max[g1 * 128 + cc + 1], m11);
                    }
                }
            }
        }
    }
}

__global__ void k_final(float* __restrict__ out) {
    int i = blockIdx.x * 256 + threadIdx.x;
    if (i < NGV * 256) {
        int g = i >> 8, j = i & 255;
        float v;
        if (j < 128) v = g_out_w[g * 128 + j];
        else {
            v = g_out_max[g * 128 + j - 128];
            if (!isfinite(v)) v = 0.f;
        }
        out[i] = v;
    }
}

// ---------------- host orchestration ----------------
#define SYM(p, s) do { void* _t = nullptr; cudaGetSymbolAddress(&_t, s); p = (decltype(p))_t; } while (0)

extern "C" void kernel_launch(void* const* d_in, const int* in_sizes, int n_in,
                              void* d_out, int out_size) {
    const float* x_l    = (const float*)d_in[0];
    const float* x_p    = (const float*)d_in[1];
    const float* ea     = (const float*)d_in[2];
    const int*   esrc   = (const int*)  d_in[3];
    const int*   edst   = (const int*)  d_in[4];
    const int*   lbatch = (const int*)  d_in[5];
    const float* W_node = (const float*)d_in[6];
    const float* W_el   = (const float*)d_in[7];
    const float* Wb     = (const float*)d_in[8];
    const float* bb     = (const float*)d_in[9];
    const float* Wn     = (const float*)d_in[10];
    const float* Ws_    = (const float*)d_in[11];
    const float* bconv  = (const float*)d_in[12];
    const float* W1     = (const float*)d_in[13];
    const float* b1     = (const float*)d_in[14];
    const float* W2     = (const float*)d_in[15];
    const float* b2     = (const float*)d_in[16];
    const float* Wm     = (const float*)d_in[17];
    const float* bm     = (const float*)d_in[18];

    float *xl, *xl2, *xlsum, *prel, *xp, *xp2, *xpsum, *prep, *Abuf, *Bbuf;
    int *dcnt, *dptr, *dedges, *scnt, *sptr, *sedges, *stmp, *bsum;
    SYM(xl, g_xl); SYM(xl2, g_xl2); SYM(xlsum, g_xlsum); SYM(prel, g_prel);
    SYM(xp, g_xp); SYM(xp2, g_xp2); SYM(xpsum, g_xpsum); SYM(prep, g_prep);
    SYM(Abuf, g_A); SYM(Bbuf, g_B);
    SYM(dcnt, g_dst_cnt); SYM(dptr, g_dst_ptr); SYM(dedges, g_dst_edges);
    SYM(scnt, g_src_cnt); SYM(sptr, g_src_ptr); SYM(sedges, g_src_edges);
    SYM(stmp, g_scan_tmp); SYM(bsum, g_bsum);

    cudaFuncSetAttribute(k_edge, cudaFuncAttributeMaxDynamicSharedMemorySize,
                         EDGE_SMEM_FLOATS * (int)sizeof(float));

    // node embedding
    k_embed<<<(NLV + 3) / 4, 128>>>(x_l, xl, W_node, NLV);
    k_embed<<<(NPV + 3) / 4, 128>>>(x_p, xp, W_node, NPV);

    // rbf + cvec
    k_rbf<<<(EV + 255) / 256, 256>>>(ea);
    k_cvec<<<2, 256>>>(W_el, W1);

    // CSR (dst and src)
    cudaMemsetAsync(dcnt, 0, NPV * sizeof(int));
    cudaMemsetAsync(scnt, 0, NLV * sizeof(int));
    k_hist<<<(EV + 255) / 256, 256>>>(esrc, edst);
    int nbp = (NPV + 1023) / 1024, nbl = (NLV + 1023) / 1024;
    k_scan1<<<nbp, 1024>>>(dcnt, stmp, bsum, NPV);
    k_scan2<<<1, 512>>>(bsum, nbp);
    k_scan3<<<nbp, 1024>>>(stmp, bsum, dptr, NPV);
    k_scan1<<<nbl, 1024>>>(scnt, stmp, bsum, NLV);
    k_scan2<<<1, 512>>>(bsum, nbl);
    k_scan3<<<nbl, 1024>>>(stmp, bsum, sptr, NLV);
    cudaMemsetAsync(dcnt, 0, NPV * sizeof(int));
    cudaMemsetAsync(scnt, 0, NLV * sizeof(int));
    k_fill<<<(EV + 255) / 256, 256>>>(esrc, edst);

    // running sums
    cudaMemsetAsync(xlsum, 0, (size_t)NLV * 128 * sizeof(float));
    cudaMemsetAsync(xpsum, 0, (size_t)NPV * 128 * sizeof(float));

    // 3 hetero layers (tf32 mma conv GEMMs)
    float *cxl = xl, *cxp = xp, *nxl = xl2, *nxp = xp2;
    for (int l = 0; l < 3; l++) {
        int ilp = 2 * l, ipl = 2 * l + 1;
        k_agg<<<(NPV * 32 + 255) / 256, 256>>>(dptr, dedges, esrc, cxl,
                Wb + ilp * 1024, bb + ilp * 128, prep, NPV);
        k_agg<<<(NLV * 32 + 255) / 256, 256>>>(sptr, sedges, edst, cxp,
                Wb + ipl * 1024, bb + ipl * 128, prel, NLV);
        k_mma<<<dim3(1, (NPV + 127) / 128), 256>>>(cxp, Ws_ + (size_t)ilp * 16384,
                prep, Wn + (size_t)ilp * 16384, bconv + ilp * 128,
                nxp, xpsum, NPV, 128, 128, 128, 1);
        k_mma<<<dim3(1, (NLV + 127) / 128), 256>>>(cxl, Ws_ + (size_t)ipl * 16384,
                prel, Wn + (size_t)ipl * 16384, bconv + ipl * 128,
                nxl, xlsum, NLV, 128, 128, 128, 1);
        float* t;
        t = cxl; cxl = nxl; nxl = t;
        t = cxp; cxp = nxp; nxp = t;
    }

    // edge readout factorization (tf32 mma)
    k_mma<<<dim3(4, (NLV + 127) / 128), 256>>>(xlsum, W1, nullptr, nullptr, b1,
            Abuf, nullptr, NLV, 512, 128, 0, 0);
    k_mma<<<dim3(4, (NPV + 127) / 128), 256>>>(xpsum, W1 + (size_t)128 * 512,
            nullptr, nullptr, nullptr, Bbuf, nullptr, NPV, 512, 128, 0, 0);

    k_init_out<<<(NGV * 128 + 255) / 256, 256>>>();
    k_edge<<<(EV + 127) / 128, 256, EDGE_SMEM_FLOATS * (int)sizeof(float)>>>(
            Abuf, Bbuf, W2, b2, Wm, bm, esrc, edst, ea, lbatch);
    k_final<<<(NGV * 256 + 255) / 256, 256>>>((float*)d_out);
}

// round 12
// speedup vs baseline: 2.4975x; 1.1098x over previous
#include <cuda_runtime.h>
#include <cuda_fp16.h>
#include <math.h>

#define NLV 50000
#define NPV 150000
#define EV  500000
#define NGV 256

// ---------------- device-global scratch ----------------
__device__ float g_xl   [NLV*128];
__device__ float g_xl2  [NLV*128];
__device__ float g_xlsum[NLV*128];
__device__ float g_prel [NLV*128];
__device__ float g_xp   [NPV*128];
__device__ float g_xp2  [NPV*128];
__device__ float g_xpsum[NPV*128];
__device__ float g_prep [NPV*128];
__device__ float g_rbf  [EV*8];
__device__ float g_A    [(size_t)NLV*512];
__device__ float g_B    [(size_t)NPV*512];
__device__ float g_cvec [512];
__device__ int   g_dst_cnt[NPV];
__device__ int   g_dst_ptr[NPV+1];
__device__ int   g_dst_edges[EV];
__device__ int   g_src_cnt[NLV];
__device__ int   g_src_ptr[NLV+1];
__device__ int   g_src_edges[EV];
__device__ int   g_scan_tmp[NPV];
__device__ int   g_bsum[512];
__device__ float g_out_w  [NGV*128];
__device__ float g_out_max[NGV*128];

// ---------------- helpers ----------------
__device__ __forceinline__ void atomicMaxFloat(float* addr, float v) {
    if (v >= 0.0f) atomicMax((int*)addr, __float_as_int(v));
    else           atomicMin((unsigned int*)addr, __float_as_uint(v));
}
__device__ __forceinline__ float fast_tanh(float x) {
    float y; asm("tanh.approx.f32 %0, %1;" : "=f"(y) : "f"(x)); return y;
}
__device__ __forceinline__ unsigned f2tf32(float f) {
    unsigned u; asm("cvt.rna.tf32.f32 %0, %1;" : "=r"(u) : "f"(f)); return u;
}
__device__ __forceinline__ unsigned packh2(float lo, float hi) {
    __half2 h = __floats2half2_rn(lo, hi);
    return *(unsigned*)&h;
}
__device__ __forceinline__ void mma_tf32(float4& d,
        unsigned a0, unsigned a1, unsigned a2, unsigned a3,
        unsigned b0, unsigned b1) {
    asm("mma.sync.aligned.m16n8k8.row.col.f32.tf32.tf32.f32 "
        "{%0,%1,%2,%3}, {%4,%5,%6,%7}, {%8,%9}, {%0,%1,%2,%3};"
        : "+f"(d.x), "+f"(d.y), "+f"(d.z), "+f"(d.w)
        : "r"(a0), "r"(a1), "r"(a2), "r"(a3), "r"(b0), "r"(b1));
}
__device__ __forceinline__ void mma_f16(float4& d,
        unsigned a0, unsigned a1, unsigned a2, unsigned a3,
        unsigned b0, unsigned b1) {
    asm("mma.sync.aligned.m16n8k16.row.col.f32.f16.f16.f32 "
        "{%0,%1,%2,%3}, {%4,%5,%6,%7}, {%8,%9}, {%0,%1,%2,%3};"
        : "+f"(d.x), "+f"(d.y), "+f"(d.z), "+f"(d.w)
        : "r"(a0), "r"(a1), "r"(a2), "r"(a3), "r"(b0), "r"(b1));
}

// ---------------- node embedding ----------------
__global__ void k_embed(const float* __restrict__ X, float* __restrict__ Y,
                        const float* __restrict__ Wn, int M) {
    __shared__ float xs[4][44];
    int r0 = blockIdx.x * 4;
    int tid = threadIdx.x;  // 128
    for (int i = tid; i < 4 * 44; i += 128) {
        int rr = i / 44, kk = i % 44;
        xs[rr][kk] = (r0 + rr < M) ? X[(size_t)(r0 + rr) * 44 + kk] : 0.f;
    }
    __syncthreads();
    int col = tid;
    #pragma unroll
    for (int rr = 0; rr < 4; rr++) {
        if (r0 + rr < M) {
            float s = 0.f;
            #pragma unroll
            for (int kk = 0; kk < 44; kk++) s = fmaf(xs[rr][kk], Wn[kk * 128 + col], s);
            Y[(size_t)(r0 + rr) * 128 + col] = s;
        }
    }
}

// ---------------- RBF ----------------
__global__ void k_rbf(const float* __restrict__ ea) {
    int e = blockIdx.x * 256 + threadIdx.x;
    if (e < EV) {
        float d = ea[e];
        #pragma unroll
        for (int k = 0; k < 8; k++) {
            float t = (d - (5.0f / 7.0f) * (float)k) * 1.6f;
            g_rbf[e * 8 + k] = __expf(-t * t);
        }
    }
}

// ---------------- CSR construction ----------------
__global__ void k_hist(const int* __restrict__ src, const int* __restrict__ dst) {
    int e = blockIdx.x * 256 + threadIdx.x;
    if (e < EV) {
        atomicAdd(&g_dst_cnt[dst[e]], 1);
        atomicAdd(&g_src_cnt[src[e]], 1);
    }
}
__global__ void k_scan1(const int* __restrict__ cnt, int* __restrict__ excl,
                        int* __restrict__ bsum, int n) {
    __shared__ int s[1024];
    int i = blockIdx.x * 1024 + threadIdx.x;
    int v = (i < n) ? cnt[i] : 0;
    s[threadIdx.x] = v;
    __syncthreads();
    for (int off = 1; off < 1024; off <<= 1) {
        int t = 0;
        if ((int)threadIdx.x >= off) t = s[threadIdx.x - off];
        __syncthreads();
        s[threadIdx.x] += t;
        __syncthreads();
    }
    if (i < n) excl[i] = s[threadIdx.x] - v;
    if (threadIdx.x == 1023) bsum[blockIdx.x] = s[1023];
}
__global__ void k_scan2(int* bsum, int nb) {
    __shared__ int s[512];
    int i = threadIdx.x;
    int v = (i < nb) ? bsum[i] : 0;
    s[i] = v;
    __syncthreads();
    for (int off = 1; off < 512; off <<= 1) {
        int t = 0;
        if (i >= off) t = s[i - off];
        __syncthreads();
        s[i] += t;
        __syncthreads();
    }
    if (i < nb) bsum[i] = s[i] - v;
}
__global__ void k_scan3(const int* __restrict__ excl, const int* __restrict__ bsum,
                        int* __restrict__ ptr, int n) {
    int i = blockIdx.x * 1024 + threadIdx.x;
    if (i < n) ptr[i] = excl[i] + bsum[i >> 10];
    if (i == 0) ptr[n] = EV;
}
__global__ void k_fill(const int* __restrict__ src, const int* __restrict__ dst) {
    int e = blockIdx.x * 256 + threadIdx.x;
    if (e < EV) {
        int d = dst[e]; int p = atomicAdd(&g_dst_cnt[d], 1); g_dst_edges[g_dst_ptr[d] + p] = e;
        int s = src[e]; int q = atomicAdd(&g_src_cnt[s], 1); g_src_edges[g_src_ptr[s] + q] = e;
    }
}

// ---------------- aggregation ----------------
__global__ __launch_bounds__(256) void k_agg(
    const int* __restrict__ ptr, const int* __restrict__ eidx,
    const int* __restrict__ partner, const float* __restrict__ xsrc,
    const float* __restrict__ Wb_i, const float* __restrict__ bb_i,
    float* __restrict__ pre, int n_dst)
{
    int w = (blockIdx.x * blockDim.x + threadIdx.x) >> 5;
    int lane = threadIdx.x & 31;
    if (w >= n_dst) return;
    float wreg[8][4], bias[4], acc[4] = {0.f, 0.f, 0.f, 0.f};
    #pragma unroll
    for (int c = 0; c < 4; c++) {
        bias[c] = bb_i[c * 32 + lane];
        #pragma unroll
        for (int k = 0; k < 8; k++) wreg[k][c] = Wb_i[k * 128 + c * 32 + lane];
    }
    int s = ptr[w], e = ptr[w + 1];
    for (int p = s; p < e; p++) {
        int ed = eidx[p];
        float rv = (lane < 8) ? g_rbf[ed * 8 + lane] : 0.f;
        float r[8];
        #pragma unroll
        for (int k = 0; k < 8; k++) r[k] = __shfl_sync(0xffffffffu, rv, k);
        const float* xr = xsrc + (size_t)partner[ed] * 128;
        #pragma unroll
        for (int c = 0; c < 4; c++) {
            float t = bias[c];
            #pragma unroll
            for (int k = 0; k < 8; k++) t = fmaf(r[k], wreg[k][c], t);
            float sg = 1.f / (1.f + __expf(-t));
            acc[c] += (t * sg) * xr[c * 32 + lane];
        }
    }
    float inv = 1.f / (float)((e - s) > 1 ? (e - s) : 1);
    #pragma unroll
    for (int c = 0; c < 4; c++) pre[(size_t)w * 128 + c * 32 + lane] = acc[c] * inv;
}

// ---------------- tf32 mma fused GEMM (double-buffered, reg-prefetch) ----------
__global__ __launch_bounds__(256, 2) void k_mma(
    const float* __restrict__ A0, const float* __restrict__ W0,
    const float* __restrict__ A1, const float* __restrict__ W1,
    const float* __restrict__ bias, float* __restrict__ C,
    float* __restrict__ sum, int M, int N, int K0, int K1, int act)
{
    __shared__ unsigned AsU[2 * 16 * 132];
    __shared__ unsigned WsU[2 * 16 * 132];
    int tid = threadIdx.x;
    int m0 = blockIdx.y * 128;
    int n0 = blockIdx.x * 128;
    int K = K0 + K1;
    int nkt = K >> 4;

    int warp = tid >> 5, lane = tid & 31;
    int g = lane >> 2, t = lane & 3;
    int warp_m = warp >> 1, warp_n = warp & 1;

    int le  = tid >> 1;
    int lk8 = (tid & 1) * 8;
    int arow = m0 + le;
    int wrow = tid >> 4;
    int wcol = (tid & 15) * 8;

    float4 facc[2][8];
    #pragma unroll
    for (int mt = 0; mt < 2; mt++)
        #pragma unroll
        for (int nt = 0; nt < 8; nt++) facc[mt][nt] = make_float4(0.f, 0.f, 0.f, 0.f);

    float4 pa0, pa1, pw0, pw1;
    {
        const float* Ab = (0 < K0) ? A0 : A1;
        const float* Wb_ = (0 < K0) ? W0 : W1;
        int stride = (0 < K0) ? K0 : K1;
        pa0 = make_float4(0.f,0.f,0.f,0.f); pa1 = pa0;
        if (arow < M) {
            const float* p = Ab + (size_t)arow * stride + lk8;
            pa0 = *(const float4*)p; pa1 = *(const float4*)(p + 4);
        }
        const float* pw = Wb_ + (size_t)wrow * N + n0 + wcol;
        pw0 = *(const float4*)pw; pw1 = *(const float4*)(pw + 4);
    }

    for (int kt = 0; kt < nkt; kt++) {
        int buf = (kt & 1) * 2112;
        AsU[buf + (lk8 + 0) * 132 + le] = f2tf32(pa0.x);
        AsU[buf + (lk8 + 1) * 132 + le] = f2tf32(pa0.y);
        AsU[buf + (lk8 + 2) * 132 + le] = f2tf32(pa0.z);
        AsU[buf + (lk8 + 3) * 132 + le] = f2tf32(pa0.w);
        AsU[buf + (lk8 + 4) * 132 + le] = f2tf32(pa1.x);
        AsU[buf + (lk8 + 5) * 132 + le] = f2tf32(pa1.y);
        AsU[buf + (lk8 + 6) * 132 + le] = f2tf32(pa1.z);
        AsU[buf + (lk8 + 7) * 132 + le] = f2tf32(pa1.w);
        WsU[buf + wrow * 132 + wcol + 0] = f2tf32(pw0.x);
        WsU[buf + wrow * 132 + wcol + 1] = f2tf32(pw0.y);
        WsU[buf + wrow * 132 + wcol + 2] = f2tf32(pw0.z);
        WsU[buf + wrow * 132 + wcol + 3] = f2tf32(pw0.w);
        WsU[buf + wrow * 132 + wcol + 4] = f2tf32(pw1.x);
        WsU[buf + wrow * 132 + wcol + 5] = f2tf32(pw1.y);
        WsU[buf + wrow * 132 + wcol + 6] = f2tf32(pw1.z);
        WsU[buf + wrow * 132 + wcol + 7] = f2tf32(pw1.w);
        if (kt + 1 < nkt) {
            int k = (kt + 1) * 16;
            const float* Ab; const float* Wb_; int kl; int stride;
            if (k < K0) { Ab = A0; Wb_ = W0; kl = k; stride = K0; }
            else        { Ab = A1; Wb_ = W1; kl = k - K0; stride = K1; }
            pa0 = make_float4(0.f,0.f,0.f,0.f); pa1 = pa0;
            if (arow < M) {
                const float* p = Ab + (size_t)arow * stride + kl + lk8;
                pa0 = *(const float4*)p; pa1 = *(const float4*)(p + 4);
            }
            const float* pw = Wb_ + (size_t)(kl + wrow) * N + n0 + wcol;
            pw0 = *(const float4*)pw; pw1 = *(const float4*)(pw + 4);
        }
        __syncthreads();
        #pragma unroll
        for (int kb = 0; kb < 16; kb += 8) {
            unsigned af[2][4];
            #pragma unroll
            for (int mt = 0; mt < 2; mt++) {
                int rowb = warp_m * 32 + mt * 16;
                af[mt][0] = AsU[buf + (kb + t) * 132 + rowb + g];
                af[mt][1] = AsU[buf + (kb + t) * 132 + rowb + g + 8];
                af[mt][2] = AsU[buf + (kb + t + 4) * 132 + rowb + g];
                af[mt][3] = AsU[buf + (kb + t + 4) * 132 + rowb + g + 8];
            }
            #pragma unroll
            for (int nt = 0; nt < 8; nt++) {
                int colb = warp_n * 64 + nt * 8;
                unsigned bf0 = WsU[buf + (kb + t) * 132 + colb + g];
                unsigned bf1 = WsU[buf + (kb + t + 4) * 132 + colb + g];
                mma_tf32(facc[0][nt], af[0][0], af[0][1], af[0][2], af[0][3], bf0, bf1);
                mma_tf32(facc[1][nt], af[1][0], af[1][1], af[1][2], af[1][3], bf0, bf1);
            }
        }
    }
    #pragma unroll
    for (int mt = 0; mt < 2; mt++) {
        int rowb = m0 + warp_m * 32 + mt * 16;
        #pragma unroll
        for (int nt = 0; nt < 8; nt++) {
            int col = n0 + warp_n * 64 + nt * 8 + 2 * t;
            float ba = 0.f, bb_ = 0.f;
            if (bias) { ba = bias[col]; bb_ = bias[col + 1]; }
            int r0 = rowb + g, r1 = rowb + g + 8;
            float vx = facc[mt][nt].x + ba, vy = facc[mt][nt].y + bb_;
            float vz = facc[mt][nt].z + ba, vw = facc[mt][nt].w + bb_;
            if (act == 1) {
                vx = (vx >= 0.f) ? vx : 0.01f * vx;
                vy = (vy >= 0.f) ? vy : 0.01f * vy;
                vz = (vz >= 0.f) ? vz : 0.01f * vz;
                vw = (vw >= 0.f) ? vw : 0.01f * vw;
            }
            if (r0 < M) {
                *(float2*)(C + (size_t)r0 * N + col) = make_float2(vx, vy);
                if (sum) {
                    float2 s = *(float2*)(sum + (size_t)r0 * N + col);
                    s.x += vx; s.y += vy;
                    *(float2*)(sum + (size_t)r0 * N + col) = s;
                }
            }
            if (r1 < M) {
                *(float2*)(C + (size_t)r1 * N + col) = make_float2(vz, vw);
                if (sum) {
                    float2 s = *(float2*)(sum + (size_t)r1 * N + col);
                    s.x += vz; s.y += vw;
                    *(float2*)(sum + (size_t)r1 * N + col) = s;
                }
            }
        }
    }
}

// ---------------- cvec ----------------
__global__ void k_cvec(const float* __restrict__ W_el, const float* __restrict__ W1) {
    int j = blockIdx.x * 256 + threadIdx.x;
    if (j < 512) {
        float s = 0.f;
        #pragma unroll
        for (int k = 0; k < 8; k++) s = fmaf(W_el[k], W1[(size_t)(256 + k) * 512 + j], s);
        g_cvec[j] = s;
    }
}

__global__ void k_init_out() {
    int i = blockIdx.x * 256 + threadIdx.x;
    if (i < NGV * 128) { g_out_w[i] = 0.f; g_out_max[i] = -INFINITY; }
}

// ---------------- fused edge MLP + per-graph reduction: 128-edge tiles ------------
// fp16 m16n8k16 mma for both GEMMs. dynamic smem layout (u32 units):
//   AsH  [2][8*136] @ 0      (half2, double-buffered; stride 136 -> conflict-free)
//   WsH  [2][8*136] @ 2176   (half2, double-buffered)
//   smm  [128*132]  @ 4352   (fp32 m matrix)
//   cs   [512]      @ 21248
//   se_d [128]      @ 21760
//   se_a [128](int) @ 21888
//   se_b [128](int) @ 22016
//   se_g [128](int) @ 22144
#define EDGE_SMEM_FLOATS 22272
__global__ __launch_bounds__(256, 2) void k_edge(
    const float* __restrict__ Al, const float* __restrict__ Bp,
    const float* __restrict__ W2, const float* __restrict__ b2,
    const float* __restrict__ Wm, const float* __restrict__ bm,
    const int* __restrict__ src, const int* __restrict__ dst,
    const float* __restrict__ ea, const int* __restrict__ lbatch)
{
    extern __shared__ float dynsm[];
    unsigned* AsH = (unsigned*)dynsm;
    unsigned* WsH = (unsigned*)(dynsm + 2176);
    float* smm  = dynsm + 4352;
    float* cs   = dynsm + 21248;
    float* se_d = dynsm + 21760;
    int*   se_a = (int*)(dynsm + 21888);
    int*   se_b = (int*)(dynsm + 22016);
    int*   se_g = (int*)(dynsm + 22144);

    int tid = threadIdx.x;
    int t0 = blockIdx.x * 128;
    if (tid < 128) {
        int slot = t0 + tid;
        if (slot < EV) {
            int e = g_src_edges[slot];
            int s = src[e];
            se_a[tid] = s; se_b[tid] = dst[e];
            se_d[tid] = ea[e];
            se_g[tid] = lbatch[s];
        } else { se_a[tid] = 0; se_b[tid] = 0; se_d[tid] = 0.f; se_g[tid] = -1; }
    }
    for (int i = tid; i < 512; i += 256) cs[i] = g_cvec[i];
    __syncthreads();

    int warp = tid >> 5, lane = tid & 31;
    int g = lane >> 2, t = lane & 3;
    int warp_m = warp >> 1, warp_n = warp & 1;

    int le  = tid >> 1;
    int lk8 = (tid & 1) * 8;      // k offset of this thread's 8 A/B values
    int kp0 = (tid & 1) * 4;      // k-pair offset (half2 index)
    const float* arow = Al + (size_t)se_a[le] * 512;
    const float* brow = Bp + (size_t)se_b[le] * 512;
    float dv = se_d[le];
    // W staging: 8 kpairs x 128 cols; thread -> kpair = tid>>5 (8), cols = (tid&31)*4
    int wkp = tid >> 5;
    int wc4 = (tid & 31) * 4;

    // ---- GEMM 1 (fp16 mma, double-buffered): m = relu(A[src]+B[dst]+d*cvec) @ W2 --
    float4 facc[2][8];
    #pragma unroll
    for (int mt = 0; mt < 2; mt++)
        #pragma unroll
        for (int nt = 0; nt < 8; nt++) facc[mt][nt] = make_float4(0.f, 0.f, 0.f, 0.f);

    float4 pa0, pa1, pb0, pb1, pw0, pw1;
    {
        const float* pa = arow + lk8;
        const float* pb = brow + lk8;
        pa0 = *(const float4*)pa; pa1 = *(const float4*)(pa + 4);
        pb0 = *(const float4*)pb; pb1 = *(const float4*)(pb + 4);
        const float* pw = W2 + (size_t)(2 * wkp) * 128 + wc4;
        pw0 = *(const float4*)pw; pw1 = *(const float4*)(pw + 128);
    }

    for (int kt = 0; kt < 32; kt++) {
        int buf = (kt & 1) * 1088;
        int k = kt * 16;
        float4 c0 = *(const float4*)(cs + k + lk8), c1 = *(const float4*)(cs + k + lk8 + 4);
        float h0 = fmaxf(pa0.x + pb0.x + dv * c0.x, 0.f);
        float h1 = fmaxf(pa0.y + pb0.y + dv * c0.y, 0.f);
        float h2 = fmaxf(pa0.z + pb0.z + dv * c0.z, 0.f);
        float h3 = fmaxf(pa0.w + pb0.w + dv * c0.w, 0.f);
        float h4 = fmaxf(pa1.x + pb1.x + dv * c1.x, 0.f);
        float h5 = fmaxf(pa1.y + pb1.y + dv * c1.y, 0.f);
        float h6 = fmaxf(pa1.z + pb1.z + dv * c1.z, 0.f);
        float h7 = fmaxf(pa1.w + pb1.w + dv * c1.w, 0.f);
        AsH[buf + (kp0 + 0) * 136 + le] = packh2(h0, h1);
        AsH[buf + (kp0 + 1) * 136 + le] = packh2(h2, h3);
        AsH[buf + (kp0 + 2) * 136 + le] = packh2(h4, h5);
        AsH[buf + (kp0 + 3) * 136 + le] = packh2(h6, h7);
        WsH[buf + wkp * 136 + wc4 + 0] = packh2(pw0.x, pw1.x);
        WsH[buf + wkp * 136 + wc4 + 1] = packh2(pw0.y, pw1.y);
        WsH[buf + wkp * 136 + wc4 + 2] = packh2(pw0.z, pw1.z);
        WsH[buf + wkp * 136 + wc4 + 3] = packh2(pw0.w, pw1.w);
        if (kt + 1 < 32) {
            int kn = k + 16;
            const float* pa = arow + kn + lk8;
            const float* pb = brow + kn + lk8;
            pa0 = *(const float4*)pa; pa1 = *(const float4*)(pa + 4);
            pb0 = *(const float4*)pb; pb1 = *(const float4*)(pb + 4);
            const float* pw = W2 + (size_t)(kn + 2 * wkp) * 128 + wc4;
            pw0 = *(const float4*)pw; pw1 = *(const float4*)(pw + 128);
        }
        __syncthreads();
        unsigned af[2][4];
        #pragma unroll
        for (int mt = 0; mt < 2; mt++) {
            int rowb = warp_m * 32 + mt * 16;
            af[mt][0] = AsH[buf + t * 136 + rowb + g];
            af[mt][1] = AsH[buf + t * 136 + rowb + g + 8];
            af[mt][2] = AsH[buf + (t + 4) * 136 + rowb + g];
            af[mt][3] = AsH[buf + (t + 4) * 136 + rowb + g + 8];
        }
        #pragma unroll
        for (int nt = 0; nt < 8; nt++) {
            int colb = warp_n * 64 + nt * 8;
            unsigned bf0 = WsH[buf + t * 136 + colb + g];
            unsigned bf1 = WsH[buf + (t + 4) * 136 + colb + g];
            mma_f16(facc[0][nt], af[0][0], af[0][1], af[0][2], af[0][3], bf0, bf1);
            mma_f16(facc[1][nt], af[1][0], af[1][1], af[1][2], af[1][3], bf0, bf1);
        }
    }
    __syncthreads();

    // m = facc + b2 -> smm (fragment-layout stores, fp32)
    #pragma unroll
    for (int mt = 0; mt < 2; mt++) {
        int rowb = warp_m * 32 + mt * 16;
        #pragma unroll
        for (int nt = 0; nt < 8; nt++) {
            int cc = warp_n * 64 + nt * 8 + 2 * t;
            float ba = b2[cc], bb_ = b2[cc + 1];
            *(float2*)(smm + (rowb + g) * 132 + cc) =
                make_float2(facc[mt][nt].x + ba, facc[mt][nt].y + bb_);
            *(float2*)(smm + (rowb + g + 8) * 132 + cc) =
                make_float2(facc[mt][nt].z + ba, facc[mt][nt].w + bb_);
        }
    }
    __syncthreads();

    // ---- GEMM 2 (fp16 mma): u = m @ Wm ; w = tanh(u + bm) ----
    float4 facc2[2][8];
    #pragma unroll
    for (int mt = 0; mt < 2; mt++)
        #pragma unroll
        for (int nt = 0; nt < 8; nt++) facc2[mt][nt] = make_float4(0.f, 0.f, 0.f, 0.f);

    {
        const float* pw = Wm + (size_t)(2 * wkp) * 128 + wc4;
        pw0 = *(const float4*)pw; pw1 = *(const float4*)(pw + 128);
    }
    for (int kt = 0; kt < 8; kt++) {
        int buf = (kt & 1) * 1088;
        int k = kt * 16;
        WsH[buf + wkp * 136 + wc4 + 0] = packh2(pw0.x, pw1.x);
        WsH[buf + wkp * 136 + wc4 + 1] = packh2(pw0.y, pw1.y);
        WsH[buf + wkp * 136 + wc4 + 2] = packh2(pw0.z, pw1.z);
        WsH[buf + wkp * 136 + wc4 + 3] = packh2(pw0.w, pw1.w);
        if (kt + 1 < 8) {
            const float* pw = Wm + (size_t)(k + 16 + 2 * wkp) * 128 + wc4;
            pw0 = *(const float4*)pw; pw1 = *(const float4*)(pw + 128);
        }
        __syncthreads();
        unsigned af[2][4];
        #pragma unroll
        for (int mt = 0; mt < 2; mt++) {
            int rowb = warp_m * 32 + mt * 16;
            const float* r0p = smm + (rowb + g) * 132 + k;
            const float* r1p = smm + (rowb + g + 8) * 132 + k;
            af[mt][0] = packh2(r0p[2 * t], r0p[2 * t + 1]);
            af[mt][1] = packh2(r1p[2 * t], r1p[2 * t + 1]);
            af[mt][2] = packh2(r0p[2 * t + 8], r0p[2 * t + 9]);
            af[mt][3] = packh2(r1p[2 * t + 8], r1p[2 * t + 9]);
        }
        #pragma unroll
        for (int nt = 0; nt < 8; nt++) {
            int colb = warp_n * 64 + nt * 8;
            unsigned bf0 = WsH[buf + t * 136 + colb + g];
            unsigned bf1 = WsH[buf + (t + 4) * 136 + colb + g];
            mma_f16(facc2[0][nt], af[0][0], af[0][1], af[0][2], af[0][3], bf0, bf1);
            mma_f16(facc2[1][nt], af[1][0], af[1][1], af[1][2], af[1][3], bf0, bf1);
        }
    }

    // ---- per-graph reduction (fragment layout) ----
    {
        int row_block = warp_m * 32;
        bool uniform = (se_g[row_block] == se_g[row_block + 31]) && (se_g[row_block] >= 0);
        if (uniform) {
            int gg = se_g[row_block];
            #pragma unroll
            for (int nt = 0; nt < 8; nt++) {
                int cc = warp_n * 64 + nt * 8 + 2 * t;
                float b0 = bm[cc], b1 = bm[cc + 1];
                float ps0 = 0.f, ps1 = 0.f, mx0 = -INFINITY, mx1 = -INFINITY;
                #pragma unroll
                for (int mt = 0; mt < 2; mt++) {
                    int r0 = warp_m * 32 + mt * 16 + g, r1 = r0 + 8;
                    float m00 = smm[r0 * 132 + cc], m01 = smm[r0 * 132 + cc + 1];
                    float m10 = smm[r1 * 132 + cc], m11 = smm[r1 * 132 + cc + 1];
                    ps0 += fast_tanh(facc2[mt][nt].x + b0) * m00
                         + fast_tanh(facc2[mt][nt].z + b0) * m10;
                    ps1 += fast_tanh(facc2[mt][nt].y + b1) * m01
                         + fast_tanh(facc2[mt][nt].w + b1) * m11;
                    mx0 = fmaxf(mx0, fmaxf(m00, m10));
                    mx1 = fmaxf(mx1, fmaxf(m01, m11));
                }
                #pragma unroll
                for (int off = 4; off < 32; off <<= 1) {
                    ps0 += __shfl_xor_sync(0xffffffffu, ps0, off);
                    ps1 += __shfl_xor_sync(0xffffffffu, ps1, off);
                    mx0 = fmaxf(mx0, __shfl_xor_sync(0xffffffffu, mx0, off));
                    mx1 = fmaxf(mx1, __shfl_xor_sync(0xffffffffu, mx1, off));
                }
                if (g == 0) {
                    atomicAdd(&g_out_w[gg * 128 + cc], ps0);
                    atomicAdd(&g_out_w[gg * 128 + cc + 1], ps1);
                    atomicMaxFloat(&g_out_max[gg * 128 + cc], mx0);
                    atomicMaxFloat(&g_out_max[gg * 128 + cc + 1], mx1);
                }
            }
        } else {
            #pragma unroll
            for (int nt = 0; nt < 8; nt++) {
                int cc = warp_n * 64 + nt * 8 + 2 * t;
                float b0 = bm[cc], b1 = bm[cc + 1];
                #pragma unroll
                for (int mt = 0; mt < 2; mt++) {
                    int r0 = warp_m * 32 + mt * 16 + g, r1 = r0 + 8;
                    int g0 = se_g[r0], g1 = se_g[r1];
                    if (g0 >= 0) {
                        float m00 = smm[r0 * 132 + cc], m01 = smm[r0 * 132 + cc + 1];
                        atomicAdd(&g_out_w[g0 * 128 + cc],
                                  fast_tanh(facc2[mt][nt].x + b0) * m00);
                        atomicAdd(&g_out_w[g0 * 128 + cc + 1],
                                  fast_tanh(facc2[mt][nt].y + b1) * m01);
                        atomicMaxFloat(&g_out_max[g0 * 128 + cc], m00);
                        atomicMaxFloat(&g_out_max[g0 * 128 + cc + 1], m01);
                    }
                    if (g1 >= 0) {
                        float m10 = smm[r1 * 132 + cc], m11 = smm[r1 * 132 + cc + 1];
                        atomicAdd(&g_out_w[g1 * 128 + cc],
                                  fast_tanh(facc2[mt][nt].z + b0) * m10);
                        atomicAdd(&g_out_w[g1 * 128 + cc + 1],
                                  fast_tanh(facc2[mt][nt].w + b1) * m11);
                        atomicMaxFloat(&g_out_max[g1 * 128 + cc], m10);
                        atomicMaxFloat(&g_out_max[g1 * 128 + cc + 1], m11);
                    }
                }
            }
        }
    }
}

__global__ void k_final(float* __restrict__ out) {
    int i = blockIdx.x * 256 + threadIdx.x;
    if (i < NGV * 256) {
        int g = i >> 8, j = i & 255;
        float v;
        if (j < 128) v = g_out_w[g * 128 + j];
        else {
            v = g_out_max[g * 128 + j - 128];
            if (!isfinite(v)) v = 0.f;
        }
        out[i] = v;
    }
}

// ---------------- host orchestration ----------------
#define SYM(p, s) do { void* _t = nullptr; cudaGetSymbolAddress(&_t, s); p = (decltype(p))_t; } while (0)

extern "C" void kernel_launch(void* const* d_in, const int* in_sizes, int n_in,
                              void* d_out, int out_size) {
    const float* x_l    = (const float*)d_in[0];
    const float* x_p    = (const float*)d_in[1];
    const float* ea     = (const float*)d_in[2];
    const int*   esrc   = (const int*)  d_in[3];
    const int*   edst   = (const int*)  d_in[4];
    const int*   lbatch = (const int*)  d_in[5];
    const float* W_node = (const float*)d_in[6];
    const float* W_el   = (const float*)d_in[7];
    const float* Wb     = (const float*)d_in[8];
    const float* bb     = (const float*)d_in[9];
    const float* Wn     = (const float*)d_in[10];
    const float* Ws_    = (const float*)d_in[11];
    const float* bconv  = (const float*)d_in[12];
    const float* W1     = (const float*)d_in[13];
    const float* b1     = (const float*)d_in[14];
    const float* W2     = (const float*)d_in[15];
    const float* b2     = (const float*)d_in[16];
    const float* Wm     = (const float*)d_in[17];
    const float* bm     = (const float*)d_in[18];

    float *xl, *xl2, *xlsum, *prel, *xp, *xp2, *xpsum, *prep, *Abuf, *Bbuf;
    int *dcnt, *dptr, *dedges, *scnt, *sptr, *sedges, *stmp, *bsum;
    SYM(xl, g_xl); SYM(xl2, g_xl2); SYM(xlsum, g_xlsum); SYM(prel, g_prel);
    SYM(xp, g_xp); SYM(xp2, g_xp2); SYM(xpsum, g_xpsum); SYM(prep, g_prep);
    SYM(Abuf, g_A); SYM(Bbuf, g_B);
    SYM(dcnt, g_dst_cnt); SYM(dptr, g_dst_ptr); SYM(dedges, g_dst_edges);
    SYM(scnt, g_src_cnt); SYM(sptr, g_src_ptr); SYM(sedges, g_src_edges);
    SYM(stmp, g_scan_tmp); SYM(bsum, g_bsum);

    cudaFuncSetAttribute(k_edge, cudaFuncAttributeMaxDynamicSharedMemorySize,
                         EDGE_SMEM_FLOATS * (int)sizeof(float));

    // node embedding
    k_embed<<<(NLV + 3) / 4, 128>>>(x_l, xl, W_node, NLV);
    k_embed<<<(NPV + 3) / 4, 128>>>(x_p, xp, W_node, NPV);

    // rbf + cvec
    k_rbf<<<(EV + 255) / 256, 256>>>(ea);
    k_cvec<<<2, 256>>>(W_el, W1);

    // CSR (dst and src)
    cudaMemsetAsync(dcnt, 0, NPV * sizeof(int));
    cudaMemsetAsync(scnt, 0, NLV * sizeof(int));
    k_hist<<<(EV + 255) / 256, 256>>>(esrc, edst);
    int nbp = (NPV + 1023) / 1024, nbl = (NLV + 1023) / 1024;
    k_scan1<<<nbp, 1024>>>(dcnt, stmp, bsum, NPV);
    k_scan2<<<1, 512>>>(bsum, nbp);
    k_scan3<<<nbp, 1024>>>(stmp, bsum, dptr, NPV);
    k_scan1<<<nbl, 1024>>>(scnt, stmp, bsum, NLV);
    k_scan2<<<1, 512>>>(bsum, nbl);
    k_scan3<<<nbl, 1024>>>(stmp, bsum, sptr, NLV);
    cudaMemsetAsync(dcnt, 0, NPV * sizeof(int));
    cudaMemsetAsync(scnt, 0, NLV * sizeof(int));
    k_fill<<<(EV + 255) / 256, 256>>>(esrc, edst);

    // running sums
    cudaMemsetAsync(xlsum, 0, (size_t)NLV * 128 * sizeof(float));
    cudaMemsetAsync(xpsum, 0, (size_t)NPV * 128 * sizeof(float));

    // 3 hetero layers (tf32 mma conv GEMMs)
    float *cxl = xl, *cxp = xp, *nxl = xl2, *nxp = xp2;
    for (int l = 0; l < 3; l++) {
        int ilp = 2 * l, ipl = 2 * l + 1;
        k_agg<<<(NPV * 32 + 255) / 256, 256>>>(dptr, dedges, esrc, cxl,
                Wb + ilp * 1024, bb + ilp * 128, prep, NPV);
        k_agg<<<(NLV * 32 + 255) / 256, 256>>>(sptr, sedges, edst, cxp,
                Wb + ipl * 1024, bb + ipl * 128, prel, NLV);
        k_mma<<<dim3(1, (NPV + 127) / 128), 256>>>(cxp, Ws_ + (size_t)ilp * 16384,
                prep, Wn + (size_t)ilp * 16384, bconv + ilp * 128,
                nxp, xpsum, NPV, 128, 128, 128, 1);
        k_mma<<<dim3(1, (NLV + 127) / 128), 256>>>(cxl, Ws_ + (size_t)ipl * 16384,
                prel, Wn + (size_t)ipl * 16384, bconv + ipl * 128,
                nxl, xlsum, NLV, 128, 128, 128, 1);
        float* t;
        t = cxl; cxl = nxl; nxl = t;
        t = cxp; cxp = nxp; nxp = t;
    }

    // edge readout factorization (tf32 mma)
    k_mma<<<dim3(4, (NLV + 127) / 128), 256>>>(xlsum, W1, nullptr, nullptr, b1,
            Abuf, nullptr, NLV, 512, 128, 0, 0);
    k_mma<<<dim3(4, (NPV + 127) / 128), 256>>>(xpsum, W1 + (size_t)128 * 512,
            nullptr, nullptr, nullptr, Bbuf, nullptr, NPV, 512, 128, 0, 0);

    k_init_out<<<(NGV * 128 + 255) / 256, 256>>>();
    k_edge<<<(EV + 127) / 128, 256, EDGE_SMEM_FLOATS * (int)sizeof(float)>>>(
            Abuf, Bbuf, W2, b2, Wm, bm, esrc, edst, ea, lbatch);
    k_final<<<(NGV * 256 + 255) / 256, 256>>>((float*)d_out);
}

// round 13
// speedup vs baseline: 3.1071x; 1.2441x over previous
#include <cuda_runtime.h>
#include <cuda_fp16.h>
#include <math.h>

#define NLV 50000
#define NPV 150000
#define EV  500000
#define NGV 256

// ---------------- device-global scratch ----------------
__device__ float g_xl   [NLV*128];
__device__ float g_xl2  [NLV*128];
__device__ float g_xlsum[NLV*128];
__device__ float g_prel [NLV*128];
__device__ float g_xp   [NPV*128];
__device__ float g_xp2  [NPV*128];
__device__ float g_xpsum[NPV*128];
__device__ float g_prep [NPV*128];
__device__ float g_rbf  [EV*8];
__device__ float g_A    [(size_t)NLV*512];
__device__ float g_B    [(size_t)NPV*512];
__device__ float g_cvec [512];
__device__ int   g_dst_cnt[NPV];
__device__ int   g_dst_ptr[NPV+1];
__device__ int2  g_dst_edges[EV];   // (edge, partner=src)
__device__ int   g_src_cnt[NLV];
__device__ int   g_src_ptr[NLV+1];
__device__ int2  g_src_edges[EV];   // (edge, partner=dst)
__device__ int   g_scan_tmp[NPV];
__device__ int   g_bsum[512];
__device__ float g_out_w  [NGV*128];
__device__ float g_out_max[NGV*128];

// ---------------- helpers ----------------
__device__ __forceinline__ void atomicMaxFloat(float* addr, float v) {
    if (v >= 0.0f) atomicMax((int*)addr, __float_as_int(v));
    else           atomicMin((unsigned int*)addr, __float_as_uint(v));
}
__device__ __forceinline__ float fast_tanh(float x) {
    float y; asm("tanh.approx.f32 %0, %1;" : "=f"(y) : "f"(x)); return y;
}
__device__ __forceinline__ unsigned f2tf32(float f) {
    unsigned u; asm("cvt.rna.tf32.f32 %0, %1;" : "=r"(u) : "f"(f)); return u;
}
__device__ __forceinline__ unsigned packh2(float lo, float hi) {
    __half2 h = __floats2half2_rn(lo, hi);
    return *(unsigned*)&h;
}
__device__ __forceinline__ void mma_tf32(float4& d,
        unsigned a0, unsigned a1, unsigned a2, unsigned a3,
        unsigned b0, unsigned b1) {
    asm("mma.sync.aligned.m16n8k8.row.col.f32.tf32.tf32.f32 "
        "{%0,%1,%2,%3}, {%4,%5,%6,%7}, {%8,%9}, {%0,%1,%2,%3};"
        : "+f"(d.x), "+f"(d.y), "+f"(d.z), "+f"(d.w)
        : "r"(a0), "r"(a1), "r"(a2), "r"(a3), "r"(b0), "r"(b1));
}
__device__ __forceinline__ void mma_f16(float4& d,
        unsigned a0, unsigned a1, unsigned a2, unsigned a3,
        unsigned b0, unsigned b1) {
    asm("mma.sync.aligned.m16n8k16.row.col.f32.f16.f16.f32 "
        "{%0,%1,%2,%3}, {%4,%5,%6,%7}, {%8,%9}, {%0,%1,%2,%3};"
        : "+f"(d.x), "+f"(d.y), "+f"(d.z), "+f"(d.w)
        : "r"(a0), "r"(a1), "r"(a2), "r"(a3), "r"(b0), "r"(b1));
}

// ---------------- node embedding ----------------
__global__ void k_embed(const float* __restrict__ X, float* __restrict__ Y,
                        const float* __restrict__ Wn, int M) {
    __shared__ float xs[4][44];
    int r0 = blockIdx.x * 4;
    int tid = threadIdx.x;  // 128
    for (int i = tid; i < 4 * 44; i += 128) {
        int rr = i / 44, kk = i % 44;
        xs[rr][kk] = (r0 + rr < M) ? X[(size_t)(r0 + rr) * 44 + kk] : 0.f;
    }
    __syncthreads();
    int col = tid;
    #pragma unroll
    for (int rr = 0; rr < 4; rr++) {
        if (r0 + rr < M) {
            float s = 0.f;
            #pragma unroll
            for (int kk = 0; kk < 44; kk++) s = fmaf(xs[rr][kk], Wn[kk * 128 + col], s);
            Y[(size_t)(r0 + rr) * 128 + col] = s;
        }
    }
}

// ---------------- RBF ----------------
__global__ void k_rbf(const float* __restrict__ ea) {
    int e = blockIdx.x * 256 + threadIdx.x;
    if (e < EV) {
        float d = ea[e];
        #pragma unroll
        for (int k = 0; k < 8; k++) {
            float t = (d - (5.0f / 7.0f) * (float)k) * 1.6f;
            g_rbf[e * 8 + k] = __expf(-t * t);
        }
    }
}

// ---------------- CSR construction ----------------
__global__ void k_hist(const int* __restrict__ src, const int* __restrict__ dst) {
    int e = blockIdx.x * 256 + threadIdx.x;
    if (e < EV) {
        atomicAdd(&g_dst_cnt[dst[e]], 1);
        atomicAdd(&g_src_cnt[src[e]], 1);
    }
}
__global__ void k_scan1(const int* __restrict__ cnt, int* __restrict__ excl,
                        int* __restrict__ bsum, int n) {
    __shared__ int s[1024];
    int i = blockIdx.x * 1024 + threadIdx.x;
    int v = (i < n) ? cnt[i] : 0;
    s[threadIdx.x] = v;
    __syncthreads();
    for (int off = 1; off < 1024; off <<= 1) {
        int t = 0;
        if ((int)threadIdx.x >= off) t = s[threadIdx.x - off];
        __syncthreads();
        s[threadIdx.x] += t;
        __syncthreads();
    }
    if (i < n) excl[i] = s[threadIdx.x] - v;
    if (threadIdx.x == 1023) bsum[blockIdx.x] = s[1023];
}
__global__ void k_scan2(int* bsum, int nb) {
    __shared__ int s[512];
    int i = threadIdx.x;
    int v = (i < nb) ? bsum[i] : 0;
    s[i] = v;
    __syncthreads();
    for (int off = 1; off < 512; off <<= 1) {
        int t = 0;
        if (i >= off) t = s[i - off];
        __syncthreads();
        s[i] += t;
        __syncthreads();
    }
    if (i < nb) bsum[i] = s[i] - v;
}
__global__ void k_scan3(const int* __restrict__ excl, const int* __restrict__ bsum,
                        int* __restrict__ ptr, int n) {
    int i = blockIdx.x * 1024 + threadIdx.x;
    if (i < n) ptr[i] = excl[i] + bsum[i >> 10];
    if (i == 0) ptr[n] = EV;
}
__global__ void k_fill(const int* __restrict__ src, const int* __restrict__ dst) {
    int e = blockIdx.x * 256 + threadIdx.x;
    if (e < EV) {
        int s = src[e], d = dst[e];
        int p = atomicAdd(&g_dst_cnt[d], 1);
        g_dst_edges[g_dst_ptr[d] + p] = make_int2(e, s);
        int q = atomicAdd(&g_src_cnt[s], 1);
        g_src_edges[g_src_ptr[s] + q] = make_int2(e, d);
    }
}

// ---------------- merged per-layer aggregation (both directions) --------------
// warp w < NPV: pre_p[w] = mean_e silu(rbf@Wbp+bbp) * xl[src(e)]   (dst CSR)
// warp w >= NPV: pre_l[w-NPV] via src CSR and xp.
__global__ __launch_bounds__(256) void k_agg2(
    const float* __restrict__ xl, const float* __restrict__ xp,
    const float* __restrict__ Wbp, const float* __restrict__ bbp,
    const float* __restrict__ Wbl, const float* __restrict__ bbl,
    float* __restrict__ prep, float* __restrict__ prel)
{
    int w = (blockIdx.x * blockDim.x + threadIdx.x) >> 5;
    int lane = threadIdx.x & 31;
    const int* ptr; const int2* eidx; const float* xsrc;
    const float* Wb_i; const float* bb_i; float* pre;
    if (w < NPV) {
        ptr = g_dst_ptr; eidx = g_dst_edges; xsrc = xl;
        Wb_i = Wbp; bb_i = bbp; pre = prep;
    } else {
        w -= NPV;
        if (w >= NLV) return;
        ptr = g_src_ptr; eidx = g_src_edges; xsrc = xp;
        Wb_i = Wbl; bb_i = bbl; pre = prel;
    }
    float wreg[8][4], bias[4], acc[4] = {0.f, 0.f, 0.f, 0.f};
    #pragma unroll
    for (int c = 0; c < 4; c++) {
        bias[c] = bb_i[c * 32 + lane];
        #pragma unroll
        for (int k = 0; k < 8; k++) wreg[k][c] = Wb_i[k * 128 + c * 32 + lane];
    }
    int s = ptr[w], e = ptr[w + 1];
    int p = s;
    for (; p + 2 <= e; p += 2) {
        int2 e0 = eidx[p];
        int2 e1 = eidx[p + 1];
        float rv0 = (lane < 8) ? g_rbf[e0.x * 8 + lane] : 0.f;
        float rv1 = (lane < 8) ? g_rbf[e1.x * 8 + lane] : 0.f;
        const float* x0 = xsrc + (size_t)e0.y * 128;
        const float* x1 = xsrc + (size_t)e1.y * 128;
        float xv0[4], xv1[4];
        #pragma unroll
        for (int c = 0; c < 4; c++) { xv0[c] = x0[c * 32 + lane]; xv1[c] = x1[c * 32 + lane]; }
        float r0[8], r1[8];
        #pragma unroll
        for (int k = 0; k < 8; k++) {
            r0[k] = __shfl_sync(0xffffffffu, rv0, k);
            r1[k] = __shfl_sync(0xffffffffu, rv1, k);
        }
        #pragma unroll
        for (int c = 0; c < 4; c++) {
            float t0 = bias[c], t1 = bias[c];
            #pragma unroll
            for (int k = 0; k < 8; k++) {
                t0 = fmaf(r0[k], wreg[k][c], t0);
                t1 = fmaf(r1[k], wreg[k][c], t1);
            }
            float sg0 = 1.f / (1.f + __expf(-t0));
            float sg1 = 1.f / (1.f + __expf(-t1));
            acc[c] += (t0 * sg0) * xv0[c] + (t1 * sg1) * xv1[c];
        }
    }
    if (p < e) {
        int2 e0 = eidx[p];
        float rv0 = (lane < 8) ? g_rbf[e0.x * 8 + lane] : 0.f;
        const float* x0 = xsrc + (size_t)e0.y * 128;
        float xv0[4];
        #pragma unroll
        for (int c = 0; c < 4; c++) xv0[c] = x0[c * 32 + lane];
        float r0[8];
        #pragma unroll
        for (int k = 0; k < 8; k++) r0[k] = __shfl_sync(0xffffffffu, rv0, k);
        #pragma unroll
        for (int c = 0; c < 4; c++) {
            float t0 = bias[c];
            #pragma unroll
            for (int k = 0; k < 8; k++) t0 = fmaf(r0[k], wreg[k][c], t0);
            float sg0 = 1.f / (1.f + __expf(-t0));
            acc[c] += (t0 * sg0) * xv0[c];
        }
    }
    float inv = 1.f / (float)((e - s) > 1 ? (e - s) : 1);
    #pragma unroll
    for (int c = 0; c < 4; c++) pre[(size_t)w * 128 + c * 32 + lane] = acc[c] * inv;
}

// ---------------- tf32 mma fused GEMM (double-buffered, reg-prefetch) ----------
__global__ __launch_bounds__(256, 2) void k_mma(
    const float* __restrict__ A0, const float* __restrict__ W0,
    const float* __restrict__ A1, const float* __restrict__ W1,
    const float* __restrict__ bias, float* __restrict__ C,
    float* __restrict__ sum, int M, int N, int K0, int K1, int act)
{
    __shared__ unsigned AsU[2 * 16 * 132];
    __shared__ unsigned WsU[2 * 16 * 132];
    int tid = threadIdx.x;
    int m0 = blockIdx.y * 128;
    int n0 = blockIdx.x * 128;
    int K = K0 + K1;
    int nkt = K >> 4;

    int warp = tid >> 5, lane = tid & 31;
    int g = lane >> 2, t = lane & 3;
    int warp_m = warp >> 1, warp_n = warp & 1;

    int le  = tid >> 1;
    int lk8 = (tid & 1) * 8;
    int arow = m0 + le;
    int wrow = tid >> 4;
    int wcol = (tid & 15) * 8;

    float4 facc[2][8];
    #pragma unroll
    for (int mt = 0; mt < 2; mt++)
        #pragma unroll
        for (int nt = 0; nt < 8; nt++) facc[mt][nt] = make_float4(0.f, 0.f, 0.f, 0.f);

    float4 pa0, pa1, pw0, pw1;
    {
        const float* Ab = (0 < K0) ? A0 : A1;
        const float* Wb_ = (0 < K0) ? W0 : W1;
        int stride = (0 < K0) ? K0 : K1;
        pa0 = make_float4(0.f,0.f,0.f,0.f); pa1 = pa0;
        if (arow < M) {
            const float* p = Ab + (size_t)arow * stride + lk8;
            pa0 = *(const float4*)p; pa1 = *(const float4*)(p + 4);
        }
        const float* pw = Wb_ + (size_t)wrow * N + n0 + wcol;
        pw0 = *(const float4*)pw; pw1 = *(const float4*)(pw + 4);
    }

    for (int kt = 0; kt < nkt; kt++) {
        int buf = (kt & 1) * 2112;
        AsU[buf + (lk8 + 0) * 132 + le] = f2tf32(pa0.x);
        AsU[buf + (lk8 + 1) * 132 + le] = f2tf32(pa0.y);
        AsU[buf + (lk8 + 2) * 132 + le] = f2tf32(pa0.z);
        AsU[buf + (lk8 + 3) * 132 + le] = f2tf32(pa0.w);
        AsU[buf + (lk8 + 4) * 132 + le] = f2tf32(pa1.x);
        AsU[buf + (lk8 + 5) * 132 + le] = f2tf32(pa1.y);
        AsU[buf + (lk8 + 6) * 132 + le] = f2tf32(pa1.z);
        AsU[buf + (lk8 + 7) * 132 + le] = f2tf32(pa1.w);
        WsU[buf + wrow * 132 + wcol + 0] = f2tf32(pw0.x);
        WsU[buf + wrow * 132 + wcol + 1] = f2tf32(pw0.y);
        WsU[buf + wrow * 132 + wcol + 2] = f2tf32(pw0.z);
        WsU[buf + wrow * 132 + wcol + 3] = f2tf32(pw0.w);
        WsU[buf + wrow * 132 + wcol + 4] = f2tf32(pw1.x);
        WsU[buf + wrow * 132 + wcol + 5] = f2tf32(pw1.y);
        WsU[buf + wrow * 132 + wcol + 6] = f2tf32(pw1.z);
        WsU[buf + wrow * 132 + wcol + 7] = f2tf32(pw1.w);
        if (kt + 1 < nkt) {
            int k = (kt + 1) * 16;
            const float* Ab; const float* Wb_; int kl; int stride;
            if (k < K0) { Ab = A0; Wb_ = W0; kl = k; stride = K0; }
            else        { Ab = A1; Wb_ = W1; kl = k - K0; stride = K1; }
            pa0 = make_float4(0.f,0.f,0.f,0.f); pa1 = pa0;
            if (arow < M) {
                const float* p = Ab + (size_t)arow * stride + kl + lk8;
                pa0 = *(const float4*)p; pa1 = *(const float4*)(p + 4);
            }
            const float* pw = Wb_ + (size_t)(kl + wrow) * N + n0 + wcol;
            pw0 = *(const float4*)pw; pw1 = *(const float4*)(pw + 4);
        }
        __syncthreads();
        #pragma unroll
        for (int kb = 0; kb < 16; kb += 8) {
            unsigned af[2][4];
            #pragma unroll
            for (int mt = 0; mt < 2; mt++) {
                int rowb = warp_m * 32 + mt * 16;
                af[mt][0] = AsU[buf + (kb + t) * 132 + rowb + g];
                af[mt][1] = AsU[buf + (kb + t) * 132 + rowb + g + 8];
                af[mt][2] = AsU[buf + (kb + t + 4) * 132 + rowb + g];
                af[mt][3] = AsU[buf + (kb + t + 4) * 132 + rowb + g + 8];
            }
            #pragma unroll
            for (int nt = 0; nt < 8; nt++) {
                int colb = warp_n * 64 + nt * 8;
                unsigned bf0 = WsU[buf + (kb + t) * 132 + colb + g];
                unsigned bf1 = WsU[buf + (kb + t + 4) * 132 + colb + g];
                mma_tf32(facc[0][nt], af[0][0], af[0][1], af[0][2], af[0][3], bf0, bf1);
                mma_tf32(facc[1][nt], af[1][0], af[1][1], af[1][2], af[1][3], bf0, bf1);
            }
        }
    }
    #pragma unroll
    for (int mt = 0; mt < 2; mt++) {
        int rowb = m0 + warp_m * 32 + mt * 16;
        #pragma unroll
        for (int nt = 0; nt < 8; nt++) {
            int col = n0 + warp_n * 64 + nt * 8 + 2 * t;
            float ba = 0.f, bb_ = 0.f;
            if (bias) { ba = bias[col]; bb_ = bias[col + 1]; }
            int r0 = rowb + g, r1 = rowb + g + 8;
            float vx = facc[mt][nt].x + ba, vy = facc[mt][nt].y + bb_;
            float vz = facc[mt][nt].z + ba, vw = facc[mt][nt].w + bb_;
            if (act == 1) {
                vx = (vx >= 0.f) ? vx : 0.01f * vx;
                vy = (vy >= 0.f) ? vy : 0.01f * vy;
                vz = (vz >= 0.f) ? vz : 0.01f * vz;
                vw = (vw >= 0.f) ? vw : 0.01f * vw;
            }
            if (r0 < M) {
                *(float2*)(C + (size_t)r0 * N + col) = make_float2(vx, vy);
                if (sum) {
                    float2 s = *(float2*)(sum + (size_t)r0 * N + col);
                    s.x += vx; s.y += vy;
                    *(float2*)(sum + (size_t)r0 * N + col) = s;
                }
            }
            if (r1 < M) {
                *(float2*)(C + (size_t)r1 * N + col) = make_float2(vz, vw);
                if (sum) {
                    float2 s = *(float2*)(sum + (size_t)r1 * N + col);
                    s.x += vz; s.y += vw;
                    *(float2*)(sum + (size_t)r1 * N + col) = s;
                }
            }
        }
    }
}

// ---------------- cvec ----------------
__global__ void k_cvec(const float* __restrict__ W_el, const float* __restrict__ W1) {
    int j = blockIdx.x * 256 + threadIdx.x;
    if (j < 512) {
        float s = 0.f;
        #pragma unroll
        for (int k = 0; k < 8; k++) s = fmaf(W_el[k], W1[(size_t)(256 + k) * 512 + j], s);
        g_cvec[j] = s;
    }
}

__global__ void k_init_out() {
    int i = blockIdx.x * 256 + threadIdx.x;
    if (i < NGV * 128) { g_out_w[i] = 0.f; g_out_max[i] = -INFINITY; }
}

// ---------------- fused edge MLP + per-graph reduction: 128-edge tiles ------------
#define EDGE_SMEM_FLOATS 22272
__global__ __launch_bounds__(256, 2) void k_edge(
    const float* __restrict__ Al, const float* __restrict__ Bp,
    const float* __restrict__ W2, const float* __restrict__ b2,
    const float* __restrict__ Wm, const float* __restrict__ bm,
    const int* __restrict__ src,
    const float* __restrict__ ea, const int* __restrict__ lbatch)
{
    extern __shared__ float dynsm[];
    unsigned* AsH = (unsigned*)dynsm;
    unsigned* WsH = (unsigned*)(dynsm + 2176);
    float* smm  = dynsm + 4352;
    float* cs   = dynsm + 21248;
    float* se_d = dynsm + 21760;
    int*   se_a = (int*)(dynsm + 21888);
    int*   se_b = (int*)(dynsm + 22016);
    int*   se_g = (int*)(dynsm + 22144);

    int tid = threadIdx.x;
    int t0 = blockIdx.x * 128;
    if (tid < 128) {
        int slot = t0 + tid;
        if (slot < EV) {
            int2 ei = g_src_edges[slot];
            int e = ei.x;
            int s = src[e];
            se_a[tid] = s; se_b[tid] = ei.y;
            se_d[tid] = ea[e];
            se_g[tid] = lbatch[s];
        } else { se_a[tid] = 0; se_b[tid] = 0; se_d[tid] = 0.f; se_g[tid] = -1; }
    }
    for (int i = tid; i < 512; i += 256) cs[i] = g_cvec[i];
    __syncthreads();

    int warp = tid >> 5, lane = tid & 31;
    int g = lane >> 2, t = lane & 3;
    int warp_m = warp >> 1, warp_n = warp & 1;

    int le  = tid >> 1;
    int lk8 = (tid & 1) * 8;
    int kp0 = (tid & 1) * 4;
    const float* arow = Al + (size_t)se_a[le] * 512;
    const float* brow = Bp + (size_t)se_b[le] * 512;
    float dv = se_d[le];
    int wkp = tid >> 5;
    int wc4 = (tid & 31) * 4;

    // ---- GEMM 1 (fp16 mma, double-buffered): m = relu(A[src]+B[dst]+d*cvec) @ W2 --
    float4 facc[2][8];
    #pragma unroll
    for (int mt = 0; mt < 2; mt++)
        #pragma unroll
        for (int nt = 0; nt < 8; nt++) facc[mt][nt] = make_float4(0.f, 0.f, 0.f, 0.f);

    float4 pa0, pa1, pb0, pb1, pw0, pw1;
    {
        const float* pa = arow + lk8;
        const float* pb = brow + lk8;
        pa0 = *(const float4*)pa; pa1 = *(const float4*)(pa + 4);
        pb0 = *(const float4*)pb; pb1 = *(const float4*)(pb + 4);
        const float* pw = W2 + (size_t)(2 * wkp) * 128 + wc4;
        pw0 = *(const float4*)pw; pw1 = *(const float4*)(pw + 128);
    }

    for (int kt = 0; kt < 32; kt++) {
        int buf = (kt & 1) * 1088;
        int k = kt * 16;
        float4 c0 = *(const float4*)(cs + k + lk8), c1 = *(const float4*)(cs + k + lk8 + 4);
        float h0 = fmaxf(pa0.x + pb0.x + dv * c0.x, 0.f);
        float h1 = fmaxf(pa0.y + pb0.y + dv * c0.y, 0.f);
        float h2 = fmaxf(pa0.z + pb0.z + dv * c0.z, 0.f);
        float h3 = fmaxf(pa0.w + pb0.w + dv * c0.w, 0.f);
        float h4 = fmaxf(pa1.x + pb1.x + dv * c1.x, 0.f);
        float h5 = fmaxf(pa1.y + pb1.y + dv * c1.y, 0.f);
        float h6 = fmaxf(pa1.z + pb1.z + dv * c1.z, 0.f);
        float h7 = fmaxf(pa1.w + pb1.w + dv * c1.w, 0.f);
        AsH[buf + (kp0 + 0) * 136 + le] = packh2(h0, h1);
        AsH[buf + (kp0 + 1) * 136 + le] = packh2(h2, h3);
        AsH[buf + (kp0 + 2) * 136 + le] = packh2(h4, h5);
        AsH[buf + (kp0 + 3) * 136 + le] = packh2(h6, h7);
        WsH[buf + wkp * 136 + wc4 + 0] = packh2(pw0.x, pw1.x);
        WsH[buf + wkp * 136 + wc4 + 1] = packh2(pw0.y, pw1.y);
        WsH[buf + wkp * 136 + wc4 + 2] = packh2(pw0.z, pw1.z);
        WsH[buf + wkp * 136 + wc4 + 3] = packh2(pw0.w, pw1.w);
        if (kt + 1 < 32) {
            int kn = k + 16;
            const float* pa = arow + kn + lk8;
            const float* pb = brow + kn + lk8;
            pa0 = *(const float4*)pa; pa1 = *(const float4*)(pa + 4);
            pb0 = *(const float4*)pb; pb1 = *(const float4*)(pb + 4);
            const float* pw = W2 + (size_t)(kn + 2 * wkp) * 128 + wc4;
            pw0 = *(const float4*)pw; pw1 = *(const float4*)(pw + 128);
        }
        __syncthreads();
        unsigned af[2][4];
        #pragma unroll
        for (int mt = 0; mt < 2; mt++) {
            int rowb = warp_m * 32 + mt * 16;
            af[mt][0] = AsH[buf + t * 136 + rowb + g];
            af[mt][1] = AsH[buf + t * 136 + rowb + g + 8];
            af[mt][2] = AsH[buf + (t + 4) * 136 + rowb + g];
            af[mt][3] = AsH[buf + (t + 4) * 136 + rowb + g + 8];
        }
        #pragma unroll
        for (int nt = 0; nt < 8; nt++) {
            int colb = warp_n * 64 + nt * 8;
            unsigned bf0 = WsH[buf + t * 136 + colb + g];
            unsigned bf1 = WsH[buf + (t + 4) * 136 + colb + g];
            mma_f16(facc[0][nt], af[0][0], af[0][1], af[0][2], af[0][3], bf0, bf1);
            mma_f16(facc[1][nt], af[1][0], af[1][1], af[1][2], af[1][3], bf0, bf1);
        }
    }
    __syncthreads();

    // m = facc + b2 -> smm (fragment-layout stores, fp32)
    #pragma unroll
    for (int mt = 0; mt < 2; mt++) {
        int rowb = warp_m * 32 + mt * 16;
        #pragma unroll
        for (int nt = 0; nt < 8; nt++) {
            int cc = warp_n * 64 + nt * 8 + 2 * t;
            float ba = b2[cc], bb_ = b2[cc + 1];
            *(float2*)(smm + (rowb + g) * 132 + cc) =
                make_float2(facc[mt][nt].x + ba, facc[mt][nt].y + bb_);
            *(float2*)(smm + (rowb + g + 8) * 132 + cc) =
                make_float2(facc[mt][nt].z + ba, facc[mt][nt].w + bb_);
        }
    }
    __syncthreads();

    // ---- GEMM 2 (fp16 mma): u = m @ Wm ; w = tanh(u + bm) ----
    float4 facc2[2][8];
    #pragma unroll
    for (int mt = 0; mt < 2; mt++)
        #pragma unroll
        for (int nt = 0; nt < 8; nt++) facc2[mt][nt] = make_float4(0.f, 0.f, 0.f, 0.f);

    {
        const float* pw = Wm + (size_t)(2 * wkp) * 128 + wc4;
        pw0 = *(const float4*)pw; pw1 = *(const float4*)(pw + 128);
    }
    for (int kt = 0; kt < 8; kt++) {
        int buf = (kt & 1) * 1088;
        int k = kt * 16;
        WsH[buf + wkp * 136 + wc4 + 0] = packh2(pw0.x, pw1.x);
        WsH[buf + wkp * 136 + wc4 + 1] = packh2(pw0.y, pw1.y);
        WsH[buf + wkp * 136 + wc4 + 2] = packh2(pw0.z, pw1.z);
        WsH[buf + wkp * 136 + wc4 + 3] = packh2(pw0.w, pw1.w);
        if (kt + 1 < 8) {
            const float* pw = Wm + (size_t)(k + 16 + 2 * wkp) * 128 + wc4;
            pw0 = *(const float4*)pw; pw1 = *(const float4*)(pw + 128);
        }
        __syncthreads();
        unsigned af[2][4];
        #pragma unroll
        for (int mt = 0; mt < 2; mt++) {
            int rowb = warp_m * 32 + mt * 16;
            const float* r0p = smm + (rowb + g) * 132 + k;
            const float* r1p = smm + (rowb + g + 8) * 132 + k;
            af[mt][0] = packh2(r0p[2 * t], r0p[2 * t + 1]);
            af[mt][1] = packh2(r1p[2 * t], r1p[2 * t + 1]);
            af[mt][2] = packh2(r0p[2 * t + 8], r0p[2 * t + 9]);
            af[mt][3] = packh2(r1p[2 * t + 8], r1p[2 * t + 9]);
        }
        #pragma unroll
        for (int nt = 0; nt < 8; nt++) {
            int colb = warp_n * 64 + nt * 8;
            unsigned bf0 = WsH[buf + t * 136 + colb + g];
            unsigned bf1 = WsH[buf + (t + 4) * 136 + colb + g];
            mma_f16(facc2[0][nt], af[0][0], af[0][1], af[0][2], af[0][3], bf0, bf1);
            mma_f16(facc2[1][nt], af[1][0], af[1][1], af[1][2], af[1][3], bf0, bf1);
        }
    }

    // ---- per-graph reduction (fragment layout) ----
    {
        int row_block = warp_m * 32;
        bool uniform = (se_g[row_block] == se_g[row_block + 31]) && (se_g[row_block] >= 0);
        if (uniform) {
            int gg = se_g[row_block];
            #pragma unroll
            for (int nt = 0; nt < 8; nt++) {
                int cc = warp_n * 64 + nt * 8 + 2 * t;
                float b0 = bm[cc], b1 = bm[cc + 1];
                float ps0 = 0.f, ps1 = 0.f, mx0 = -INFINITY, mx1 = -INFINITY;
                #pragma unroll
                for (int mt = 0; mt < 2; mt++) {
                    int r0 = warp_m * 32 + mt * 16 + g, r1 = r0 + 8;
                    float m00 = smm[r0 * 132 + cc], m01 = smm[r0 * 132 + cc + 1];
                    float m10 = smm[r1 * 132 + cc], m11 = smm[r1 * 132 + cc + 1];
                    ps0 += fast_tanh(facc2[mt][nt].x + b0) * m00
                         + fast_tanh(facc2[mt][nt].z + b0) * m10;
                    ps1 += fast_tanh(facc2[mt][nt].y + b1) * m01
                         + fast_tanh(facc2[mt][nt].w + b1) * m11;
                    mx0 = fmaxf(mx0, fmaxf(m00, m10));
                    mx1 = fmaxf(mx1, fmaxf(m01, m11));
                }
                #pragma unroll
                for (int off = 4; off < 32; off <<= 1) {
                    ps0 += __shfl_xor_sync(0xffffffffu, ps0, off);
                    ps1 += __shfl_xor_sync(0xffffffffu, ps1, off);
                    mx0 = fmaxf(mx0, __shfl_xor_sync(0xffffffffu, mx0, off));
                    mx1 = fmaxf(mx1, __shfl_xor_sync(0xffffffffu, mx1, off));
                }
                if (g == 0) {
                    atomicAdd(&g_out_w[gg * 128 + cc], ps0);
                    atomicAdd(&g_out_w[gg * 128 + cc + 1], ps1);
                    atomicMaxFloat(&g_out_max[gg * 128 + cc], mx0);
                    atomicMaxFloat(&g_out_max[gg * 128 + cc + 1], mx1);
                }
            }
        } else {
            #pragma unroll
            for (int nt = 0; nt < 8; nt++) {
                int cc = warp_n * 64 + nt * 8 + 2 * t;
                float b0 = bm[cc], b1 = bm[cc + 1];
                #pragma unroll
                for (int mt = 0; mt < 2; mt++) {
                    int r0 = warp_m * 32 + mt * 16 + g, r1 = r0 + 8;
                    int g0 = se_g[r0], g1 = se_g[r1];
                    if (g0 >= 0) {
                        float m00 = smm[r0 * 132 + cc], m01 = smm[r0 * 132 + cc + 1];
                        atomicAdd(&g_out_w[g0 * 128 + cc],
                                  fast_tanh(facc2[mt][nt].x + b0) * m00);
                        atomicAdd(&g_out_w[g0 * 128 + cc + 1],
                                  fast_tanh(facc2[mt][nt].y + b1) * m01);
                        atomicMaxFloat(&g_out_max[g0 * 128 + cc], m00);
                        atomicMaxFloat(&g_out_max[g0 * 128 + cc + 1], m01);
                    }
                    if (g1 >= 0) {
                        float m10 = smm[r1 * 132 + cc], m11 = smm[r1 * 132 + cc + 1];
                        atomicAdd(&g_out_w[g1 * 128 + cc],
                                  fast_tanh(facc2[mt][nt].z + b0) * m10);
                        atomicAdd(&g_out_w[g1 * 128 + cc + 1],
                                  fast_tanh(facc2[mt][nt].w + b1) * m11);
                        atomicMaxFloat(&g_out_max[g1 * 128 + cc], m10);
                        atomicMaxFloat(&g_out_max[g1 * 128 + cc + 1], m11);
                    }
                }
            }
        }
    }
}

__global__ void k_final(float* __restrict__ out) {
    int i = blockIdx.x * 256 + threadIdx.x;
    if (i < NGV * 256) {
        int g = i >> 8, j = i & 255;
        float v;
        if (j < 128) v = g_out_w[g * 128 + j];
        else {
            v = g_out_max[g * 128 + j - 128];
            if (!isfinite(v)) v = 0.f;
        }
        out[i] = v;
    }
}

// ---------------- host orchestration ----------------
#define SYM(p, s) do { void* _t = nullptr; cudaGetSymbolAddress(&_t, s); p = (decltype(p))_t; } while (0)

extern "C" void kernel_launch(void* const* d_in, const int* in_sizes, int n_in,
                              void* d_out, int out_size) {
    const float* x_l    = (const float*)d_in[0];
    const float* x_p    = (const float*)d_in[1];
    const float* ea     = (const float*)d_in[2];
    const int*   esrc   = (const int*)  d_in[3];
    const int*   edst   = (const int*)  d_in[4];
    const int*   lbatch = (const int*)  d_in[5];
    const float* W_node = (const float*)d_in[6];
    const float* W_el   = (const float*)d_in[7];
    const float* Wb     = (const float*)d_in[8];
    const float* bb     = (const float*)d_in[9];
    const float* Wn     = (const float*)d_in[10];
    const float* Ws_    = (const float*)d_in[11];
    const float* bconv  = (const float*)d_in[12];
    const float* W1     = (const float*)d_in[13];
    const float* b1     = (const float*)d_in[14];
    const float* W2     = (const float*)d_in[15];
    const float* b2     = (const float*)d_in[16];
    const float* Wm     = (const float*)d_in[17];
    const float* bm     = (const float*)d_in[18];

    float *xl, *xl2, *xlsum, *prel, *xp, *xp2, *xpsum, *prep, *Abuf, *Bbuf;
    int *dcnt, *dptr, *scnt, *sptr, *stmp, *bsum;
    SYM(xl, g_xl); SYM(xl2, g_xl2); SYM(xlsum, g_xlsum); SYM(prel, g_prel);
    SYM(xp, g_xp); SYM(xp2, g_xp2); SYM(xpsum, g_xpsum); SYM(prep, g_prep);
    SYM(Abuf, g_A); SYM(Bbuf, g_B);
    SYM(dcnt, g_dst_cnt); SYM(dptr, g_dst_ptr);
    SYM(scnt, g_src_cnt); SYM(sptr, g_src_ptr);
    SYM(stmp, g_scan_tmp); SYM(bsum, g_bsum);

    cudaFuncSetAttribute(k_edge, cudaFuncAttributeMaxDynamicSharedMemorySize,
                         EDGE_SMEM_FLOATS * (int)sizeof(float));

    // node embedding
    k_embed<<<(NLV + 3) / 4, 128>>>(x_l, xl, W_node, NLV);
    k_embed<<<(NPV + 3) / 4, 128>>>(x_p, xp, W_node, NPV);

    // rbf + cvec
    k_rbf<<<(EV + 255) / 256, 256>>>(ea);
    k_cvec<<<2, 256>>>(W_el, W1);

    // CSR (dst and src)
    cudaMemsetAsync(dcnt, 0, NPV * sizeof(int));
    cudaMemsetAsync(scnt, 0, NLV * sizeof(int));
    k_hist<<<(EV + 255) / 256, 256>>>(esrc, edst);
    int nbp = (NPV + 1023) / 1024, nbl = (NLV + 1023) / 1024;
    k_scan1<<<nbp, 1024>>>(dcnt, stmp, bsum, NPV);
    k_scan2<<<1, 512>>>(bsum, nbp);
    k_scan3<<<nbp, 1024>>>(stmp, bsum, dptr, NPV);
    k_scan1<<<nbl, 1024>>>(scnt, stmp, bsum, NLV);
    k_scan2<<<1, 512>>>(bsum, nbl);
    k_scan3<<<nbl, 1024>>>(stmp, bsum, sptr, NLV);
    cudaMemsetAsync(dcnt, 0, NPV * sizeof(int));
    cudaMemsetAsync(scnt, 0, NLV * sizeof(int));
    k_fill<<<(EV + 255) / 256, 256>>>(esrc, edst);

    // running sums
    cudaMemsetAsync(xlsum, 0, (size_t)NLV * 128 * sizeof(float));
    cudaMemsetAsync(xpsum, 0, (size_t)NPV * 128 * sizeof(float));

    // 3 hetero layers
    float *cxl = xl, *cxp = xp, *nxl = xl2, *nxp = xp2;
    for (int l = 0; l < 3; l++) {
        int ilp = 2 * l, ipl = 2 * l + 1;
        k_agg2<<<((NPV + NLV) * 32 + 255) / 256, 256>>>(cxl, cxp,
                Wb + ilp * 1024, bb + ilp * 128,
                Wb + ipl * 1024, bb + ipl * 128, prep, prel);
        k_mma<<<dim3(1, (NPV + 127) / 128), 256>>>(cxp, Ws_ + (size_t)ilp * 16384,
                prep, Wn + (size_t)ilp * 16384, bconv + ilp * 128,
                nxp, xpsum, NPV, 128, 128, 128, 1);
        k_mma<<<dim3(1, (NLV + 127) / 128), 256>>>(cxl, Ws_ + (size_t)ipl * 16384,
                prel, Wn + (size_t)ipl * 16384, bconv + ipl * 128,
                nxl, xlsum, NLV, 128, 128, 128, 1);
        float* t;
        t = cxl; cxl = nxl; nxl = t;
        t = cxp; cxp = nxp; nxp = t;
    }

    // edge readout factorization (tf32 mma)
    k_mma<<<dim3(4, (NLV + 127) / 128), 256>>>(xlsum, W1, nullptr, nullptr, b1,
            Abuf, nullptr, NLV, 512, 128, 0, 0);
    k_mma<<<dim3(4, (NPV + 127) / 128), 256>>>(xpsum, W1 + (size_t)128 * 512,
            nullptr, nullptr, nullptr, Bbuf, nullptr, NPV, 512, 128, 0, 0);

    k_init_out<<<(NGV * 128 + 255) / 256, 256>>>();
    k_edge<<<(EV + 127) / 128, 256, EDGE_SMEM_FLOATS * (int)sizeof(float)>>>(
            Abuf, Bbuf, W2, b2, Wm, bm, esrc, ea, lbatch);
    k_final<<<(NGV * 256 + 255) / 256, 256>>>((float*)d_out);
}

// round 14
// speedup vs baseline: 3.3181x; 1.0679x over previous
#include <cuda_runtime.h>
#include <cuda_fp16.h>
#include <math.h>

#define NLV 50000
#define NPV 150000
#define EV  500000
#define NGV 256

// ---------------- device-global scratch ----------------
__device__ float g_xl   [NLV*128];
__device__ float g_xl2  [NLV*128];
__device__ float g_xlsum[NLV*128];
__device__ float g_prel [NLV*128];
__device__ float g_xp   [NPV*128];
__device__ float g_xp2  [NPV*128];
__device__ float g_xpsum[NPV*128];
__device__ float g_prep [NPV*128];
__device__ float g_rbf  [EV*8];
__device__ __half g_Ah  [(size_t)NLV*512];
__device__ __half g_Bh  [(size_t)NPV*512];
__device__ float g_cvec [512];
__device__ int   g_dst_cnt[NPV];
__device__ int   g_dst_ptr[NPV+1];
__device__ int2  g_dst_edges[EV];   // (edge, partner=src)
__device__ int   g_src_cnt[NLV];
__device__ int   g_src_ptr[NLV+1];
__device__ int2  g_src_edges[EV];   // (edge, partner=dst)
__device__ int   g_scan_tmp[NPV];
__device__ int   g_bsum[512];
__device__ float g_out_w  [NGV*128];
__device__ float g_out_max[NGV*128];

// ---------------- helpers ----------------
__device__ __forceinline__ void atomicMaxFloat(float* addr, float v) {
    if (v >= 0.0f) atomicMax((int*)addr, __float_as_int(v));
    else           atomicMin((unsigned int*)addr, __float_as_uint(v));
}
__device__ __forceinline__ float fast_tanh(float x) {
    float y; asm("tanh.approx.f32 %0, %1;" : "=f"(y) : "f"(x)); return y;
}
__device__ __forceinline__ unsigned f2tf32(float f) {
    unsigned u; asm("cvt.rna.tf32.f32 %0, %1;" : "=r"(u) : "f"(f)); return u;
}
__device__ __forceinline__ unsigned packh2(float lo, float hi) {
    __half2 h = __floats2half2_rn(lo, hi);
    return *(unsigned*)&h;
}
__device__ __forceinline__ void mma_tf32(float4& d,
        unsigned a0, unsigned a1, unsigned a2, unsigned a3,
        unsigned b0, unsigned b1) {
    asm("mma.sync.aligned.m16n8k8.row.col.f32.tf32.tf32.f32 "
        "{%0,%1,%2,%3}, {%4,%5,%6,%7}, {%8,%9}, {%0,%1,%2,%3};"
        : "+f"(d.x), "+f"(d.y), "+f"(d.z), "+f"(d.w)
        : "r"(a0), "r"(a1), "r"(a2), "r"(a3), "r"(b0), "r"(b1));
}
__device__ __forceinline__ void mma_f16(float4& d,
        unsigned a0, unsigned a1, unsigned a2, unsigned a3,
        unsigned b0, unsigned b1) {
    asm("mma.sync.aligned.m16n8k16.row.col.f32.f16.f16.f32 "
        "{%0,%1,%2,%3}, {%4,%5,%6,%7}, {%8,%9}, {%0,%1,%2,%3};"
        : "+f"(d.x), "+f"(d.y), "+f"(d.z), "+f"(d.w)
        : "r"(a0), "r"(a1), "r"(a2), "r"(a3), "r"(b0), "r"(b1));
}

// ---------------- node embedding ----------------
__global__ void k_embed(const float* __restrict__ X, float* __restrict__ Y,
                        const float* __restrict__ Wn, int M) {
    __shared__ float xs[4][44];
    int r0 = blockIdx.x * 4;
    int tid = threadIdx.x;  // 128
    for (int i = tid; i < 4 * 44; i += 128) {
        int rr = i / 44, kk = i % 44;
        xs[rr][kk] = (r0 + rr < M) ? X[(size_t)(r0 + rr) * 44 + kk] : 0.f;
    }
    __syncthreads();
    int col = tid;
    #pragma unroll
    for (int rr = 0; rr < 4; rr++) {
        if (r0 + rr < M) {
            float s = 0.f;
            #pragma unroll
            for (int kk = 0; kk < 44; kk++) s = fmaf(xs[rr][kk], Wn[kk * 128 + col], s);
            Y[(size_t)(r0 + rr) * 128 + col] = s;
        }
    }
}

// ---------------- RBF ----------------
__global__ void k_rbf(const float* __restrict__ ea) {
    int e = blockIdx.x * 256 + threadIdx.x;
    if (e < EV) {
        float d = ea[e];
        #pragma unroll
        for (int k = 0; k < 8; k++) {
            float t = (d - (5.0f / 7.0f) * (float)k) * 1.6f;
            g_rbf[e * 8 + k] = __expf(-t * t);
        }
    }
}

// ---------------- CSR construction ----------------
__global__ void k_hist(const int* __restrict__ src, const int* __restrict__ dst) {
    int e = blockIdx.x * 256 + threadIdx.x;
    if (e < EV) {
        atomicAdd(&g_dst_cnt[dst[e]], 1);
        atomicAdd(&g_src_cnt[src[e]], 1);
    }
}
__global__ void k_scan1(const int* __restrict__ cnt, int* __restrict__ excl,
                        int* __restrict__ bsum, int n) {
    __shared__ int s[1024];
    int i = blockIdx.x * 1024 + threadIdx.x;
    int v = (i < n) ? cnt[i] : 0;
    s[threadIdx.x] = v;
    __syncthreads();
    for (int off = 1; off < 1024; off <<= 1) {
        int t = 0;
        if ((int)threadIdx.x >= off) t = s[threadIdx.x - off];
        __syncthreads();
        s[threadIdx.x] += t;
        __syncthreads();
    }
    if (i < n) excl[i] = s[threadIdx.x] - v;
    if (threadIdx.x == 1023) bsum[blockIdx.x] = s[1023];
}
__global__ void k_scan2(int* bsum, int nb) {
    __shared__ int s[512];
    int i = threadIdx.x;
    int v = (i < nb) ? bsum[i] : 0;
    s[i] = v;
    __syncthreads();
    for (int off = 1; off < 512; off <<= 1) {
        int t = 0;
        if (i >= off) t = s[i - off];
        __syncthreads();
        s[i] += t;
        __syncthreads();
    }
    if (i < nb) bsum[i] = s[i] - v;
}
__global__ void k_scan3(const int* __restrict__ excl, const int* __restrict__ bsum,
                        int* __restrict__ ptr, int n) {
    int i = blockIdx.x * 1024 + threadIdx.x;
    if (i < n) ptr[i] = excl[i] + bsum[i >> 10];
    if (i == 0) ptr[n] = EV;
}
__global__ void k_fill(const int* __restrict__ src, const int* __restrict__ dst) {
    int e = blockIdx.x * 256 + threadIdx.x;
    if (e < EV) {
        int s = src[e], d = dst[e];
        int p = atomicAdd(&g_dst_cnt[d], 1);
        g_dst_edges[g_dst_ptr[d] + p] = make_int2(e, s);
        int q = atomicAdd(&g_src_cnt[s], 1);
        g_src_edges[g_src_ptr[s] + q] = make_int2(e, d);
    }
}

// ---------------- merged per-layer aggregation (both directions) --------------
__global__ __launch_bounds__(256) void k_agg2(
    const float* __restrict__ xl, const float* __restrict__ xp,
    const float* __restrict__ Wbp, const float* __restrict__ bbp,
    const float* __restrict__ Wbl, const float* __restrict__ bbl,
    float* __restrict__ prep, float* __restrict__ prel)
{
    int w = (blockIdx.x * blockDim.x + threadIdx.x) >> 5;
    int lane = threadIdx.x & 31;
    const int* ptr; const int2* eidx; const float* xsrc;
    const float* Wb_i; const float* bb_i; float* pre;
    if (w < NPV) {
        ptr = g_dst_ptr; eidx = g_dst_edges; xsrc = xl;
        Wb_i = Wbp; bb_i = bbp; pre = prep;
    } else {
        w -= NPV;
        if (w >= NLV) return;
        ptr = g_src_ptr; eidx = g_src_edges; xsrc = xp;
        Wb_i = Wbl; bb_i = bbl; pre = prel;
    }
    float wreg[8][4], bias[4], acc[4] = {0.f, 0.f, 0.f, 0.f};
    #pragma unroll
    for (int c = 0; c < 4; c++) {
        bias[c] = bb_i[c * 32 + lane];
        #pragma unroll
        for (int k = 0; k < 8; k++) wreg[k][c] = Wb_i[k * 128 + c * 32 + lane];
    }
    int s = ptr[w], e = ptr[w + 1];
    int p = s;
    for (; p + 2 <= e; p += 2) {
        int2 e0 = eidx[p];
        int2 e1 = eidx[p + 1];
        float rv0 = (lane < 8) ? g_rbf[e0.x * 8 + lane] : 0.f;
        float rv1 = (lane < 8) ? g_rbf[e1.x * 8 + lane] : 0.f;
        const float* x0 = xsrc + (size_t)e0.y * 128;
        const float* x1 = xsrc + (size_t)e1.y * 128;
        float xv0[4], xv1[4];
        #pragma unroll
        for (int c = 0; c < 4; c++) { xv0[c] = x0[c * 32 + lane]; xv1[c] = x1[c * 32 + lane]; }
        float r0[8], r1[8];
        #pragma unroll
        for (int k = 0; k < 8; k++) {
            r0[k] = __shfl_sync(0xffffffffu, rv0, k);
            r1[k] = __shfl_sync(0xffffffffu, rv1, k);
        }
        #pragma unroll
        for (int c = 0; c < 4; c++) {
            float t0 = bias[c], t1 = bias[c];
            #pragma unroll
            for (int k = 0; k < 8; k++) {
                t0 = fmaf(r0[k], wreg[k][c], t0);
                t1 = fmaf(r1[k], wreg[k][c], t1);
            }
            float sg0 = 1.f / (1.f + __expf(-t0));
            float sg1 = 1.f / (1.f + __expf(-t1));
            acc[c] += (t0 * sg0) * xv0[c] + (t1 * sg1) * xv1[c];
        }
    }
    if (p < e) {
        int2 e0 = eidx[p];
        float rv0 = (lane < 8) ? g_rbf[e0.x * 8 + lane] : 0.f;
        const float* x0 = xsrc + (size_t)e0.y * 128;
        float xv0[4];
        #pragma unroll
        for (int c = 0; c < 4; c++) xv0[c] = x0[c * 32 + lane];
        float r0[8];
        #pragma unroll
        for (int k = 0; k < 8; k++) r0[k] = __shfl_sync(0xffffffffu, rv0, k);
        #pragma unroll
        for (int c = 0; c < 4; c++) {
            float t0 = bias[c];
            #pragma unroll
            for (int k = 0; k < 8; k++) t0 = fmaf(r0[k], wreg[k][c], t0);
            float sg0 = 1.f / (1.f + __expf(-t0));
            acc[c] += (t0 * sg0) * xv0[c];
        }
    }
    float inv = 1.f / (float)((e - s) > 1 ? (e - s) : 1);
    #pragma unroll
    for (int c = 0; c < 4; c++) pre[(size_t)w * 128 + c * 32 + lane] = acc[c] * inv;
}

// ---------------- tf32 mma fused GEMM (conv chain; double-buffered) ----------
__global__ __launch_bounds__(256, 2) void k_mma(
    const float* __restrict__ A0, const float* __restrict__ W0,
    const float* __restrict__ A1, const float* __restrict__ W1,
    const float* __restrict__ bias, float* __restrict__ C,
    float* __restrict__ sum, int M, int N, int K0, int K1, int act)
{
    __shared__ unsigned AsU[2 * 16 * 132];
    __shared__ unsigned WsU[2 * 16 * 132];
    int tid = threadIdx.x;
    int m0 = blockIdx.y * 128;
    int n0 = blockIdx.x * 128;
    int K = K0 + K1;
    int nkt = K >> 4;

    int warp = tid >> 5, lane = tid & 31;
    int g = lane >> 2, t = lane & 3;
    int warp_m = warp >> 1, warp_n = warp & 1;

    int le  = tid >> 1;
    int lk8 = (tid & 1) * 8;
    int arow = m0 + le;
    int wrow = tid >> 4;
    int wcol = (tid & 15) * 8;

    float4 facc[2][8];
    #pragma unroll
    for (int mt = 0; mt < 2; mt++)
        #pragma unroll
        for (int nt = 0; nt < 8; nt++) facc[mt][nt] = make_float4(0.f, 0.f, 0.f, 0.f);

    float4 pa0, pa1, pw0, pw1;
    {
        const float* Ab = (0 < K0) ? A0 : A1;
        const float* Wb_ = (0 < K0) ? W0 : W1;
        int stride = (0 < K0) ? K0 : K1;
        pa0 = make_float4(0.f,0.f,0.f,0.f); pa1 = pa0;
        if (arow < M) {
            const float* p = Ab + (size_t)arow * stride + lk8;
            pa0 = *(const float4*)p; pa1 = *(const float4*)(p + 4);
        }
        const float* pw = Wb_ + (size_t)wrow * N + n0 + wcol;
        pw0 = *(const float4*)pw; pw1 = *(const float4*)(pw + 4);
    }

    for (int kt = 0; kt < nkt; kt++) {
        int buf = (kt & 1) * 2112;
        AsU[buf + (lk8 + 0) * 132 + le] = f2tf32(pa0.x);
        AsU[buf + (lk8 + 1) * 132 + le] = f2tf32(pa0.y);
        AsU[buf + (lk8 + 2) * 132 + le] = f2tf32(pa0.z);
        AsU[buf + (lk8 + 3) * 132 + le] = f2tf32(pa0.w);
        AsU[buf + (lk8 + 4) * 132 + le] = f2tf32(pa1.x);
        AsU[buf + (lk8 + 5) * 132 + le] = f2tf32(pa1.y);
        AsU[buf + (lk8 + 6) * 132 + le] = f2tf32(pa1.z);
        AsU[buf + (lk8 + 7) * 132 + le] = f2tf32(pa1.w);
        WsU[buf + wrow * 132 + wcol + 0] = f2tf32(pw0.x);
        WsU[buf + wrow * 132 + wcol + 1] = f2tf32(pw0.y);
        WsU[buf + wrow * 132 + wcol + 2] = f2tf32(pw0.z);
        WsU[buf + wrow * 132 + wcol + 3] = f2tf32(pw0.w);
        WsU[buf + wrow * 132 + wcol + 4] = f2tf32(pw1.x);
        WsU[buf + wrow * 132 + wcol + 5] = f2tf32(pw1.y);
        WsU[buf + wrow * 132 + wcol + 6] = f2tf32(pw1.z);
        WsU[buf + wrow * 132 + wcol + 7] = f2tf32(pw1.w);
        if (kt + 1 < nkt) {
            int k = (kt + 1) * 16;
            const float* Ab; const float* Wb_; int kl; int stride;
            if (k < K0) { Ab = A0; Wb_ = W0; kl = k; stride = K0; }
            else        { Ab = A1; Wb_ = W1; kl = k - K0; stride = K1; }
            pa0 = make_float4(0.f,0.f,0.f,0.f); pa1 = pa0;
            if (arow < M) {
                const float* p = Ab + (size_t)arow * stride + kl + lk8;
                pa0 = *(const float4*)p; pa1 = *(const float4*)(p + 4);
            }
            const float* pw = Wb_ + (size_t)(kl + wrow) * N + n0 + wcol;
            pw0 = *(const float4*)pw; pw1 = *(const float4*)(pw + 4);
        }
        __syncthreads();
        #pragma unroll
        for (int kb = 0; kb < 16; kb += 8) {
            unsigned af[2][4];
            #pragma unroll
            for (int mt = 0; mt < 2; mt++) {
                int rowb = warp_m * 32 + mt * 16;
                af[mt][0] = AsU[buf + (kb + t) * 132 + rowb + g];
                af[mt][1] = AsU[buf + (kb + t) * 132 + rowb + g + 8];
                af[mt][2] = AsU[buf + (kb + t + 4) * 132 + rowb + g];
                af[mt][3] = AsU[buf + (kb + t + 4) * 132 + rowb + g + 8];
            }
            #pragma unroll
            for (int nt = 0; nt < 8; nt++) {
                int colb = warp_n * 64 + nt * 8;
                unsigned bf0 = WsU[buf + (kb + t) * 132 + colb + g];
                unsigned bf1 = WsU[buf + (kb + t + 4) * 132 + colb + g];
                mma_tf32(facc[0][nt], af[0][0], af[0][1], af[0][2], af[0][3], bf0, bf1);
                mma_tf32(facc[1][nt], af[1][0], af[1][1], af[1][2], af[1][3], bf0, bf1);
            }
        }
    }
    #pragma unroll
    for (int mt = 0; mt < 2; mt++) {
        int rowb = m0 + warp_m * 32 + mt * 16;
        #pragma unroll
        for (int nt = 0; nt < 8; nt++) {
            int col = n0 + warp_n * 64 + nt * 8 + 2 * t;
            float ba = 0.f, bb_ = 0.f;
            if (bias) { ba = bias[col]; bb_ = bias[col + 1]; }
            int r0 = rowb + g, r1 = rowb + g + 8;
            float vx = facc[mt][nt].x + ba, vy = facc[mt][nt].y + bb_;
            float vz = facc[mt][nt].z + ba, vw = facc[mt][nt].w + bb_;
            if (act == 1) {
                vx = (vx >= 0.f) ? vx : 0.01f * vx;
                vy = (vy >= 0.f) ? vy : 0.01f * vy;
                vz = (vz >= 0.f) ? vz : 0.01f * vz;
                vw = (vw >= 0.f) ? vw : 0.01f * vw;
            }
            if (r0 < M) {
                *(float2*)(C + (size_t)r0 * N + col) = make_float2(vx, vy);
                if (sum) {
                    float2 s = *(float2*)(sum + (size_t)r0 * N + col);
                    s.x += vx; s.y += vy;
                    *(float2*)(sum + (size_t)r0 * N + col) = s;
                }
            }
            if (r1 < M) {
                *(float2*)(C + (size_t)r1 * N + col) = make_float2(vz, vw);
                if (sum) {
                    float2 s = *(float2*)(sum + (size_t)r1 * N + col);
                    s.x += vz; s.y += vw;
                    *(float2*)(sum + (size_t)r1 * N + col) = s;
                }
            }
        }
    }
}

// ---------------- fp16 mma factor GEMM: Ch[M,N] = A[M,128]@W[128,N] + bias -----
// fp16 output, fp32 accumulate. 128x128 tile per block, K=128 fixed.
__global__ __launch_bounds__(256, 2) void k_mma16(
    const float* __restrict__ A, const float* __restrict__ W,
    const float* __restrict__ bias, __half* __restrict__ C,
    int M, int N)
{
    __shared__ unsigned AsH[2 * 8 * 136];
    __shared__ unsigned WsH[2 * 8 * 136];
    int tid = threadIdx.x;
    int m0 = blockIdx.y * 128;
    int n0 = blockIdx.x * 128;

    int warp = tid >> 5, lane = tid & 31;
    int g = lane >> 2, t = lane & 3;
    int warp_m = warp >> 1, warp_n = warp & 1;

    int le  = tid >> 1;
    int lk8 = (tid & 1) * 8;
    int kp0 = (tid & 1) * 4;
    int arow = m0 + le;
    int wkp = tid >> 5;
    int wc4 = (tid & 31) * 4;

    float4 facc[2][8];
    #pragma unroll
    for (int mt = 0; mt < 2; mt++)
        #pragma unroll
        for (int nt = 0; nt < 8; nt++) facc[mt][nt] = make_float4(0.f, 0.f, 0.f, 0.f);

    float4 pa0, pa1, pw0, pw1;
    {
        pa0 = make_float4(0.f,0.f,0.f,0.f); pa1 = pa0;
        if (arow < M) {
            const float* p = A + (size_t)arow * 128 + lk8;
            pa0 = *(const float4*)p; pa1 = *(const float4*)(p + 4);
        }
        const float* pw = W + (size_t)(2 * wkp) * N + n0 + wc4;
        pw0 = *(const float4*)pw; pw1 = *(const float4*)(pw + N);
    }

    for (int kt = 0; kt < 8; kt++) {
        int buf = (kt & 1) * 1088;
        int k = kt * 16;
        AsH[buf + (kp0 + 0) * 136 + le] = packh2(pa0.x, pa0.y);
        AsH[buf + (kp0 + 1) * 136 + le] = packh2(pa0.z, pa0.w);
        AsH[buf + (kp0 + 2) * 136 + le] = packh2(pa1.x, pa1.y);
        AsH[buf + (kp0 + 3) * 136 + le] = packh2(pa1.z, pa1.w);
        WsH[buf + wkp * 136 + wc4 + 0] = packh2(pw0.x, pw1.x);
        WsH[buf + wkp * 136 + wc4 + 1] = packh2(pw0.y, pw1.y);
        WsH[buf + wkp * 136 + wc4 + 2] = packh2(pw0.z, pw1.z);
        WsH[buf + wkp * 136 + wc4 + 3] = packh2(pw0.w, pw1.w);
        if (kt + 1 < 8) {
            int kn = k + 16;
            pa0 = make_float4(0.f,0.f,0.f,0.f); pa1 = pa0;
            if (arow < M) {
                const float* p = A + (size_t)arow * 128 + kn + lk8;
                pa0 = *(const float4*)p; pa1 = *(const float4*)(p + 4);
            }
            const float* pw = W + (size_t)(kn + 2 * wkp) * N + n0 + wc4;
            pw0 = *(const float4*)pw; pw1 = *(const float4*)(pw + N);
        }
        __syncthreads();
        unsigned af[2][4];
        #pragma unroll
        for (int mt = 0; mt < 2; mt++) {
            int rowb = warp_m * 32 + mt * 16;
            af[mt][0] = AsH[buf + t * 136 + rowb + g];
            af[mt][1] = AsH[buf + t * 136 + rowb + g + 8];
            af[mt][2] = AsH[buf + (t + 4) * 136 + rowb + g];
            af[mt][3] = AsH[buf + (t + 4) * 136 + rowb + g + 8];
        }
        #pragma unroll
        for (int nt = 0; nt < 8; nt++) {
            int colb = warp_n * 64 + nt * 8;
            unsigned bf0 = WsH[buf + t * 136 + colb + g];
            unsigned bf1 = WsH[buf + (t + 4) * 136 + colb + g];
            mma_f16(facc[0][nt], af[0][0], af[0][1], af[0][2], af[0][3], bf0, bf1);
            mma_f16(facc[1][nt], af[1][0], af[1][1], af[1][2], af[1][3], bf0, bf1);
        }
    }
    #pragma unroll
    for (int mt = 0; mt < 2; mt++) {
        int rowb = m0 + warp_m * 32 + mt * 16;
        #pragma unroll
        for (int nt = 0; nt < 8; nt++) {
            int col = n0 + warp_n * 64 + nt * 8 + 2 * t;
            float ba = 0.f, bb_ = 0.f;
            if (bias) { ba = bias[col]; bb_ = bias[col + 1]; }
            int r0 = rowb + g, r1 = rowb + g + 8;
            if (r0 < M)
                *(__half2*)(C + (size_t)r0 * N + col) =
                    __floats2half2_rn(facc[mt][nt].x + ba, facc[mt][nt].y + bb_);
            if (r1 < M)
                *(__half2*)(C + (size_t)r1 * N + col) =
                    __floats2half2_rn(facc[mt][nt].z + ba, facc[mt][nt].w + bb_);
        }
    }
}

// ---------------- cvec ----------------
__global__ void k_cvec(const float* __restrict__ W_el, const float* __restrict__ W1) {
    int j = blockIdx.x * 256 + threadIdx.x;
    if (j < 512) {
        float s = 0.f;
        #pragma unroll
        for (int k = 0; k < 8; k++) s = fmaf(W_el[k], W1[(size_t)(256 + k) * 512 + j], s);
        g_cvec[j] = s;
    }
}

__global__ void k_init_out() {
    int i = blockIdx.x * 256 + threadIdx.x;
    if (i < NGV * 128) { g_out_w[i] = 0.f; g_out_max[i] = -INFINITY; }
}

// ---------------- fused edge MLP + per-graph reduction: 128-edge tiles ------------
#define EDGE_SMEM_FLOATS 22272
__global__ __launch_bounds__(256, 2) void k_edge(
    const __half* __restrict__ Al, const __half* __restrict__ Bp,
    const float* __restrict__ W2, const float* __restrict__ b2,
    const float* __restrict__ Wm, const float* __restrict__ bm,
    const int* __restrict__ src,
    const float* __restrict__ ea, const int* __restrict__ lbatch)
{
    extern __shared__ float dynsm[];
    unsigned* AsH = (unsigned*)dynsm;
    unsigned* WsH = (unsigned*)(dynsm + 2176);
    float* smm  = dynsm + 4352;
    float* cs   = dynsm + 21248;
    float* se_d = dynsm + 21760;
    int*   se_a = (int*)(dynsm + 21888);
    int*   se_b = (int*)(dynsm + 22016);
    int*   se_g = (int*)(dynsm + 22144);

    int tid = threadIdx.x;
    int t0 = blockIdx.x * 128;
    if (tid < 128) {
        int slot = t0 + tid;
        if (slot < EV) {
            int2 ei = g_src_edges[slot];
            int e = ei.x;
            int s = src[e];
            se_a[tid] = s; se_b[tid] = ei.y;
            se_d[tid] = ea[e];
            se_g[tid] = lbatch[s];
        } else { se_a[tid] = 0; se_b[tid] = 0; se_d[tid] = 0.f; se_g[tid] = -1; }
    }
    for (int i = tid; i < 512; i += 256) cs[i] = g_cvec[i];
    __syncthreads();

    int warp = tid >> 5, lane = tid & 31;
    int g = lane >> 2, t = lane & 3;
    int warp_m = warp >> 1, warp_n = warp & 1;

    int le  = tid >> 1;
    int lk8 = (tid & 1) * 8;
    int kp0 = (tid & 1) * 4;
    const __half* arow = Al + (size_t)se_a[le] * 512;
    const __half* brow = Bp + (size_t)se_b[le] * 512;
    float dv = se_d[le];
    int wkp = tid >> 5;
    int wc4 = (tid & 31) * 4;

    // ---- GEMM 1 (fp16 mma): m = relu(A[src]+B[dst]+d*cvec) @ W2 ----
    float4 facc[2][8];
    #pragma unroll
    for (int mt = 0; mt < 2; mt++)
        #pragma unroll
        for (int nt = 0; nt < 8; nt++) facc[mt][nt] = make_float4(0.f, 0.f, 0.f, 0.f);

    uint4 pa, pb;
    float4 pw0, pw1;
    {
        pa = *(const uint4*)(arow + lk8);
        pb = *(const uint4*)(brow + lk8);
        const float* pw = W2 + (size_t)(2 * wkp) * 128 + wc4;
        pw0 = *(const float4*)pw; pw1 = *(const float4*)(pw + 128);
    }

    for (int kt = 0; kt < 32; kt++) {
        int buf = (kt & 1) * 1088;
        int k = kt * 16;
        float4 c0 = *(const float4*)(cs + k + lk8), c1 = *(const float4*)(cs + k + lk8 + 4);
        const __half2* a2 = (const __half2*)&pa;
        const __half2* b2v = (const __half2*)&pb;
        float2 fa0 = __half22float2(a2[0]), fb0 = __half22float2(b2v[0]);
        float2 fa1 = __half22float2(a2[1]), fb1 = __half22float2(b2v[1]);
        float2 fa2 = __half22float2(a2[2]), fb2 = __half22float2(b2v[2]);
        float2 fa3 = __half22float2(a2[3]), fb3 = __half22float2(b2v[3]);
        float h0 = fmaxf(fa0.x + fb0.x + dv * c0.x, 0.f);
        float h1 = fmaxf(fa0.y + fb0.y + dv * c0.y, 0.f);
        float h2 = fmaxf(fa1.x + fb1.x + dv * c0.z, 0.f);
        float h3 = fmaxf(fa1.y + fb1.y + dv * c0.w, 0.f);
        float h4 = fmaxf(fa2.x + fb2.x + dv * c1.x, 0.f);
        float h5 = fmaxf(fa2.y + fb2.y + dv * c1.y, 0.f);
        float h6 = fmaxf(fa3.x + fb3.x + dv * c1.z, 0.f);
        float h7 = fmaxf(fa3.y + fb3.y + dv * c1.w, 0.f);
        AsH[buf + (kp0 + 0) * 136 + le] = packh2(h0, h1);
        AsH[buf + (kp0 + 1) * 136 + le] = packh2(h2, h3);
        AsH[buf + (kp0 + 2) * 136 + le] = packh2(h4, h5);
        AsH[buf + (kp0 + 3) * 136 + le] = packh2(h6, h7);
        WsH[buf + wkp * 136 + wc4 + 0] = packh2(pw0.x, pw1.x);
        WsH[buf + wkp * 136 + wc4 + 1] = packh2(pw0.y, pw1.y);
        WsH[buf + wkp * 136 + wc4 + 2] = packh2(pw0.z, pw1.z);
        WsH[buf + wkp * 136 + wc4 + 3] = packh2(pw0.w, pw1.w);
        if (kt + 1 < 32) {
            int kn = k + 16;
            pa = *(const uint4*)(arow + kn + lk8);
            pb = *(const uint4*)(brow + kn + lk8);
            const float* pw = W2 + (size_t)(kn + 2 * wkp) * 128 + wc4;
            pw0 = *(const float4*)pw; pw1 = *(const float4*)(pw + 128);
        }
        __syncthreads();
        unsigned af[2][4];
        #pragma unroll
        for (int mt = 0; mt < 2; mt++) {
            int rowb = warp_m * 32 + mt * 16;
            af[mt][0] = AsH[buf + t * 136 + rowb + g];
            af[mt][1] = AsH[buf + t * 136 + rowb + g + 8];
            af[mt][2] = AsH[buf + (t + 4) * 136 + rowb + g];
            af[mt][3] = AsH[buf + (t + 4) * 136 + rowb + g + 8];
        }
        #pragma unroll
        for (int nt = 0; nt < 8; nt++) {
            int colb = warp_n * 64 + nt * 8;
            unsigned bf0 = WsH[buf + t * 136 + colb + g];
            unsigned bf1 = WsH[buf + (t + 4) * 136 + colb + g];
            mma_f16(facc[0][nt], af[0][0], af[0][1], af[0][2], af[0][3], bf0, bf1);
            mma_f16(facc[1][nt], af[1][0], af[1][1], af[1][2], af[1][3], bf0, bf1);
        }
    }
    __syncthreads();

    // m = facc + b2 -> smm (fragment-layout stores, fp32)
    #pragma unroll
    for (int mt = 0; mt < 2; mt++) {
        int rowb = warp_m * 32 + mt * 16;
        #pragma unroll
        for (int nt = 0; nt < 8; nt++) {
            int cc = warp_n * 64 + nt * 8 + 2 * t;
            float ba = b2[cc], bb_ = b2[cc + 1];
            *(float2*)(smm + (rowb + g) * 132 + cc) =
                make_float2(facc[mt][nt].x + ba, facc[mt][nt].y + bb_);
            *(float2*)(smm + (rowb + g + 8) * 132 + cc) =
                make_float2(facc[mt][nt].z + ba, facc[mt][nt].w + bb_);
        }
    }
    __syncthreads();

    // ---- GEMM 2 (fp16 mma): u = m @ Wm ; w = tanh(u + bm) ----
    float4 facc2[2][8];
    #pragma unroll
    for (int mt = 0; mt < 2; mt++)
        #pragma unroll
        for (int nt = 0; nt < 8; nt++) facc2[mt][nt] = make_float4(0.f, 0.f, 0.f, 0.f);

    {
        const float* pw = Wm + (size_t)(2 * wkp) * 128 + wc4;
        pw0 = *(const float4*)pw; pw1 = *(const float4*)(pw + 128);
    }
    for (int kt = 0; kt < 8; kt++) {
        int buf = (kt & 1) * 1088;
        int k = kt * 16;
        WsH[buf + wkp * 136 + wc4 + 0] = packh2(pw0.x, pw1.x);
        WsH[buf + wkp * 136 + wc4 + 1] = packh2(pw0.y, pw1.y);
        WsH[buf + wkp * 136 + wc4 + 2] = packh2(pw0.z, pw1.z);
        WsH[buf + wkp * 136 + wc4 + 3] = packh2(pw0.w, pw1.w);
        if (kt + 1 < 8) {
            const float* pw = Wm + (size_t)(k + 16 + 2 * wkp) * 128 + wc4;
            pw0 = *(const float4*)pw; pw1 = *(const float4*)(pw + 128);
        }
        __syncthreads();
        unsigned af[2][4];
        #pragma unroll
        for (int mt = 0; mt < 2; mt++) {
            int rowb = warp_m * 32 + mt * 16;
            const float* r0p = smm + (rowb + g) * 132 + k;
            const float* r1p = smm + (rowb + g + 8) * 132 + k;
            af[mt][0] = packh2(r0p[2 * t], r0p[2 * t + 1]);
            af[mt][1] = packh2(r1p[2 * t], r1p[2 * t + 1]);
            af[mt][2] = packh2(r0p[2 * t + 8], r0p[2 * t + 9]);
            af[mt][3] = packh2(r1p[2 * t + 8], r1p[2 * t + 9]);
        }
        #pragma unroll
        for (int nt = 0; nt < 8; nt++) {
            int colb = warp_n * 64 + nt * 8;
            unsigned bf0 = WsH[buf + t * 136 + colb + g];
            unsigned bf1 = WsH[buf + (t + 4) * 136 + colb + g];
            mma_f16(facc2[0][nt], af[0][0], af[0][1], af[0][2], af[0][3], bf0, bf1);
            mma_f16(facc2[1][nt], af[1][0], af[1][1], af[1][2], af[1][3], bf0, bf1);
        }
    }

    // ---- per-graph reduction (fragment layout) ----
    {
        int row_block = warp_m * 32;
        bool uniform = (se_g[row_block] == se_g[row_block + 31]) && (se_g[row_block] >= 0);
        if (uniform) {
            int gg = se_g[row_block];
            #pragma unroll
            for (int nt = 0; nt < 8; nt++) {
                int cc = warp_n * 64 + nt * 8 + 2 * t;
                float b0 = bm[cc], b1 = bm[cc + 1];
                float ps0 = 0.f, ps1 = 0.f, mx0 = -INFINITY, mx1 = -INFINITY;
                #pragma unroll
                for (int mt = 0; mt < 2; mt++) {
                    int r0 = warp_m * 32 + mt * 16 + g, r1 = r0 + 8;
                    float m00 = smm[r0 * 132 + cc], m01 = smm[r0 * 132 + cc + 1];
                    float m10 = smm[r1 * 132 + cc], m11 = smm[r1 * 132 + cc + 1];
                    ps0 += fast_tanh(facc2[mt][nt].x + b0) * m00
                         + fast_tanh(facc2[mt][nt].z + b0) * m10;
                    ps1 += fast_tanh(facc2[mt][nt].y + b1) * m01
                         + fast_tanh(facc2[mt][nt].w + b1) * m11;
                    mx0 = fmaxf(mx0, fmaxf(m00, m10));
                    mx1 = fmaxf(mx1, fmaxf(m01, m11));
                }
                #pragma unroll
                for (int off = 4; off < 32; off <<= 1) {
                    ps0 += __shfl_xor_sync(0xffffffffu, ps0, off);
                    ps1 += __shfl_xor_sync(0xffffffffu, ps1, off);
                    mx0 = fmaxf(mx0, __shfl_xor_sync(0xffffffffu, mx0, off));
                    mx1 = fmaxf(mx1, __shfl_xor_sync(0xffffffffu, mx1, off));
                }
                if (g == 0) {
                    atomicAdd(&g_out_w[gg * 128 + cc], ps0);
                    atomicAdd(&g_out_w[gg * 128 + cc + 1], ps1);
                    atomicMaxFloat(&g_out_max[gg * 128 + cc], mx0);
                    atomicMaxFloat(&g_out_max[gg * 128 + cc + 1], mx1);
                }
            }
        } else {
            #pragma unroll
            for (int nt = 0; nt < 8; nt++) {
                int cc = warp_n * 64 + nt * 8 + 2 * t;
                float b0 = bm[cc], b1 = bm[cc + 1];
                #pragma unroll
                for (int mt = 0; mt < 2; mt++) {
                    int r0 = warp_m * 32 + mt * 16 + g, r1 = r0 + 8;
                    int g0 = se_g[r0], g1 = se_g[r1];
                    if (g0 >= 0) {
                        float m00 = smm[r0 * 132 + cc], m01 = smm[r0 * 132 + cc + 1];
                        atomicAdd(&g_out_w[g0 * 128 + cc],
                                  fast_tanh(facc2[mt][nt].x + b0) * m00);
                        atomicAdd(&g_out_w[g0 * 128 + cc + 1],
                                  fast_tanh(facc2[mt][nt].y + b1) * m01);
                        atomicMaxFloat(&g_out_max[g0 * 128 + cc], m00);
                        atomicMaxFloat(&g_out_max[g0 * 128 + cc + 1], m01);
                    }
                    if (g1 >= 0) {
                        float m10 = smm[r1 * 132 + cc], m11 = smm[r1 * 132 + cc + 1];
                        atomicAdd(&g_out_w[g1 * 128 + cc],
                                  fast_tanh(facc2[mt][nt].z + b0) * m10);
                        atomicAdd(&g_out_w[g1 * 128 + cc + 1],
                                  fast_tanh(facc2[mt][nt].w + b1) * m11);
                        atomicMaxFloat(&g_out_max[g1 * 128 + cc], m10);
                        atomicMaxFloat(&g_out_max[g1 * 128 + cc + 1], m11);
                    }
                }
            }
        }
    }
}

__global__ void k_final(float* __restrict__ out) {
    int i = blockIdx.x * 256 + threadIdx.x;
    if (i < NGV * 256) {
        int g = i >> 8, j = i & 255;
        float v;
        if (j < 128) v = g_out_w[g * 128 + j];
        else {
            v = g_out_max[g * 128 + j - 128];
            if (!isfinite(v)) v = 0.f;
        }
        out[i] = v;
    }
}

// ---------------- host orchestration ----------------
#define SYM(p, s) do { void* _t = nullptr; cudaGetSymbolAddress(&_t, s); p = (decltype(p))_t; } while (0)

extern "C" void kernel_launch(void* const* d_in, const int* in_sizes, int n_in,
                              void* d_out, int out_size) {
    const float* x_l    = (const float*)d_in[0];
    const float* x_p    = (const float*)d_in[1];
    const float* ea     = (const float*)d_in[2];
    const int*   esrc   = (const int*)  d_in[3];
    const int*   edst   = (const int*)  d_in[4];
    const int*   lbatch = (const int*)  d_in[5];
    const float* W_node = (const float*)d_in[6];
    const float* W_el   = (const float*)d_in[7];
    const float* Wb     = (const float*)d_in[8];
    const float* bb     = (const float*)d_in[9];
    const float* Wn     = (const float*)d_in[10];
    const float* Ws_    = (const float*)d_in[11];
    const float* bconv  = (const float*)d_in[12];
    const float* W1     = (const float*)d_in[13];
    const float* b1     = (const float*)d_in[14];
    const float* W2     = (const float*)d_in[15];
    const float* b2     = (const float*)d_in[16];
    const float* Wm     = (const float*)d_in[17];
    const float* bm     = (const float*)d_in[18];

    float *xl, *xl2, *xlsum, *prel, *xp, *xp2, *xpsum, *prep;
    __half *Ah, *Bh;
    int *dcnt, *dptr, *scnt, *sptr, *stmp, *bsum;
    SYM(xl, g_xl); SYM(xl2, g_xl2); SYM(xlsum, g_xlsum); SYM(prel, g_prel);
    SYM(xp, g_xp); SYM(xp2, g_xp2); SYM(xpsum, g_xpsum); SYM(prep, g_prep);
    SYM(Ah, g_Ah); SYM(Bh, g_Bh);
    SYM(dcnt, g_dst_cnt); SYM(dptr, g_dst_ptr);
    SYM(scnt, g_src_cnt); SYM(sptr, g_src_ptr);
    SYM(stmp, g_scan_tmp); SYM(bsum, g_bsum);

    cudaFuncSetAttribute(k_edge, cudaFuncAttributeMaxDynamicSharedMemorySize,
                         EDGE_SMEM_FLOATS * (int)sizeof(float));

    // node embedding
    k_embed<<<(NLV + 3) / 4, 128>>>(x_l, xl, W_node, NLV);
    k_embed<<<(NPV + 3) / 4, 128>>>(x_p, xp, W_node, NPV);

    // rbf + cvec
    k_rbf<<<(EV + 255) / 256, 256>>>(ea);
    k_cvec<<<2, 256>>>(W_el, W1);

    // CSR (dst and src)
    cudaMemsetAsync(dcnt, 0, NPV * sizeof(int));
    cudaMemsetAsync(scnt, 0, NLV * sizeof(int));
    k_hist<<<(EV + 255) / 256, 256>>>(esrc, edst);
    int nbp = (NPV + 1023) / 1024, nbl = (NLV + 1023) / 1024;
    k_scan1<<<nbp, 1024>>>(dcnt, stmp, bsum, NPV);
    k_scan2<<<1, 512>>>(bsum, nbp);
    k_scan3<<<nbp, 1024>>>(stmp, bsum, dptr, NPV);
    k_scan1<<<nbl, 1024>>>(scnt, stmp, bsum, NLV);
    k_scan2<<<1, 512>>>(bsum, nbl);
    k_scan3<<<nbl, 1024>>>(stmp, bsum, sptr, NLV);
    cudaMemsetAsync(dcnt, 0, NPV * sizeof(int));
    cudaMemsetAsync(scnt, 0, NLV * sizeof(int));
    k_fill<<<(EV + 255) / 256, 256>>>(esrc, edst);

    // running sums
    cudaMemsetAsync(xlsum, 0, (size_t)NLV * 128 * sizeof(float));
    cudaMemsetAsync(xpsum, 0, (size_t)NPV * 128 * sizeof(float));

    // 3 hetero layers (tf32 conv GEMMs — kept higher precision)
    float *cxl = xl, *cxp = xp, *nxl = xl2, *nxp = xp2;
    for (int l = 0; l < 3; l++) {
        int ilp = 2 * l, ipl = 2 * l + 1;
        k_agg2<<<((NPV + NLV) * 32 + 255) / 256, 256>>>(cxl, cxp,
                Wb + ilp * 1024, bb + ilp * 128,
                Wb + ipl * 1024, bb + ipl * 128, prep, prel);
        k_mma<<<dim3(1, (NPV + 127) / 128), 256>>>(cxp, Ws_ + (size_t)ilp * 16384,
                prep, Wn + (size_t)ilp * 16384, bconv + ilp * 128,
                nxp, xpsum, NPV, 128, 128, 128, 1);
        k_mma<<<dim3(1, (NLV + 127) / 128), 256>>>(cxl, Ws_ + (size_t)ipl * 16384,
                prel, Wn + (size_t)ipl * 16384, bconv + ipl * 128,
                nxl, xlsum, NLV, 128, 128, 128, 1);
        float* t;
        t = cxl; cxl = nxl; nxl = t;
        t = cxp; cxp = nxp; nxp = t;
    }

    // edge readout factorization (fp16 mma, fp16 output)
    k_mma16<<<dim3(4, (NLV + 127) / 128), 256>>>(xlsum, W1, b1, Ah, NLV, 512);
    k_mma16<<<dim3(4, (NPV + 127) / 128), 256>>>(xpsum, W1 + (size_t)128 * 512,
                                                 nullptr, Bh, NPV, 512);

    k_init_out<<<(NGV * 128 + 255) / 256, 256>>>();
    k_edge<<<(EV + 127) / 128, 256, EDGE_SMEM_FLOATS * (int)sizeof(float)>>>(
            Ah, Bh, W2, b2, Wm, bm, esrc, ea, lbatch);
    k_final<<<(NGV * 256 + 255) / 256, 256>>>((float*)d_out);
}

// round 15
// speedup vs baseline: 3.7749x; 1.1377x over previous
#include <cuda_runtime.h>
#include <cuda_fp16.h>
#include <math.h>

#define NLV 50000
#define NPV 150000
#define EV  500000
#define NGV 256

// ---------------- device-global scratch ----------------
__device__ float g_xl   [NLV*128];
__device__ float g_xl2  [NLV*128];
__device__ float g_xlsum[NLV*128];
__device__ float g_prel [NLV*128];
__device__ float g_xp   [NPV*128];
__device__ float g_xp2  [NPV*128];
__device__ float g_xpsum[NPV*128];
__device__ float g_prep [NPV*128];
__device__ __half g_Ah  [(size_t)NLV*512];
__device__ __half g_Bh  [(size_t)NPV*512];
__device__ float g_cvec [512];
__device__ int   g_dst_cnt[NPV];
__device__ int   g_dst_ptr[NPV+1];
__device__ int2  g_dst_edges[EV];   // (edge, partner=src)
__device__ int   g_src_cnt[NLV];
__device__ int   g_src_ptr[NLV+1];
__device__ int2  g_src_edges[EV];   // (edge, partner=dst)
__device__ int   g_scan_tmp[NPV];
__device__ int   g_bsum[512];
__device__ float g_out_w  [NGV*128];
__device__ float g_out_max[NGV*128];

// ---------------- helpers ----------------
__device__ __forceinline__ void atomicMaxFloat(float* addr, float v) {
    if (v >= 0.0f) atomicMax((int*)addr, __float_as_int(v));
    else           atomicMin((unsigned int*)addr, __float_as_uint(v));
}
__device__ __forceinline__ float fast_tanh(float x) {
    float y; asm("tanh.approx.f32 %0, %1;" : "=f"(y) : "f"(x)); return y;
}
__device__ __forceinline__ unsigned packh2(float lo, float hi) {
    __half2 h = __floats2half2_rn(lo, hi);
    return *(unsigned*)&h;
}
__device__ __forceinline__ void mma_f16(float4& d,
        unsigned a0, unsigned a1, unsigned a2, unsigned a3,
        unsigned b0, unsigned b1) {
    asm("mma.sync.aligned.m16n8k16.row.col.f32.f16.f16.f32 "
        "{%0,%1,%2,%3}, {%4,%5,%6,%7}, {%8,%9}, {%0,%1,%2,%3};"
        : "+f"(d.x), "+f"(d.y), "+f"(d.z), "+f"(d.w)
        : "r"(a0), "r"(a1), "r"(a2), "r"(a3), "r"(b0), "r"(b1));
}

// ---------------- node embedding ----------------
__global__ void k_embed(const float* __restrict__ X, float* __restrict__ Y,
                        const float* __restrict__ Wn, int M) {
    __shared__ float xs[4][44];
    int r0 = blockIdx.x * 4;
    int tid = threadIdx.x;  // 128
    for (int i = tid; i < 4 * 44; i += 128) {
        int rr = i / 44, kk = i % 44;
        xs[rr][kk] = (r0 + rr < M) ? X[(size_t)(r0 + rr) * 44 + kk] : 0.f;
    }
    __syncthreads();
    int col = tid;
    #pragma unroll
    for (int rr = 0; rr < 4; rr++) {
        if (r0 + rr < M) {
            float s = 0.f;
            #pragma unroll
            for (int kk = 0; kk < 44; kk++) s = fmaf(xs[rr][kk], Wn[kk * 128 + col], s);
            Y[(size_t)(r0 + rr) * 128 + col] = s;
        }
    }
}

// ---------------- CSR construction ----------------
__global__ void k_hist(const int* __restrict__ src, const int* __restrict__ dst) {
    int e = blockIdx.x * 256 + threadIdx.x;
    if (e < EV) {
        atomicAdd(&g_dst_cnt[dst[e]], 1);
        atomicAdd(&g_src_cnt[src[e]], 1);
    }
}
__global__ void k_scan1(const int* __restrict__ cnt, int* __restrict__ excl,
                        int* __restrict__ bsum, int n) {
    __shared__ int s[1024];
    int i = blockIdx.x * 1024 + threadIdx.x;
    int v = (i < n) ? cnt[i] : 0;
    s[threadIdx.x] = v;
    __syncthreads();
    for (int off = 1; off < 1024; off <<= 1) {
        int t = 0;
        if ((int)threadIdx.x >= off) t = s[threadIdx.x - off];
        __syncthreads();
        s[threadIdx.x] += t;
        __syncthreads();
    }
    if (i < n) excl[i] = s[threadIdx.x] - v;
    if (threadIdx.x == 1023) bsum[blockIdx.x] = s[1023];
}
__global__ void k_scan2(int* bsum, int nb) {
    __shared__ int s[512];
    int i = threadIdx.x;
    int v = (i < nb) ? bsum[i] : 0;
    s[i] = v;
    __syncthreads();
    for (int off = 1; off < 512; off <<= 1) {
        int t = 0;
        if (i >= off) t = s[i - off];
        __syncthreads();
        s[i] += t;
        __syncthreads();
    }
    if (i < nb) bsum[i] = s[i] - v;
}
__global__ void k_scan3(const int* __restrict__ excl, const int* __restrict__ bsum,
                        int* __restrict__ ptr, int n) {
    int i = blockIdx.x * 1024 + threadIdx.x;
    if (i < n) ptr[i] = excl[i] + bsum[i >> 10];
    if (i == 0) ptr[n] = EV;
}
__global__ void k_fill(const int* __restrict__ src, const int* __restrict__ dst) {
    int e = blockIdx.x * 256 + threadIdx.x;
    if (e < EV) {
        int s = src[e], d = dst[e];
        int p = atomicAdd(&g_dst_cnt[d], 1);
        g_dst_edges[g_dst_ptr[d] + p] = make_int2(e, s);
        int q = atomicAdd(&g_src_cnt[s], 1);
        g_src_edges[g_src_ptr[s] + q] = make_int2(e, d);
    }
}

// ---------------- merged per-layer aggregation (rbf computed inline) ----------
__global__ __launch_bounds__(256) void k_agg2(
    const float* __restrict__ xl, const float* __restrict__ xp,
    const float* __restrict__ ea,
    const float* __restrict__ Wbp, const float* __restrict__ bbp,
    const float* __restrict__ Wbl, const float* __restrict__ bbl,
    float* __restrict__ prep, float* __restrict__ prel)
{
    int w = (blockIdx.x * blockDim.x + threadIdx.x) >> 5;
    int lane = threadIdx.x & 31;
    const int* ptr; const int2* eidx; const float* xsrc;
    const float* Wb_i; const float* bb_i; float* pre;
    if (w < NPV) {
        ptr = g_dst_ptr; eidx = g_dst_edges; xsrc = xl;
        Wb_i = Wbp; bb_i = bbp; pre = prep;
    } else {
        w -= NPV;
        if (w >= NLV) return;
        ptr = g_src_ptr; eidx = g_src_edges; xsrc = xp;
        Wb_i = Wbl; bb_i = bbl; pre = prel;
    }
    float mu = (5.0f / 7.0f) * (float)lane;
    float wreg[8][4], bias[4], acc[4] = {0.f, 0.f, 0.f, 0.f};
    #pragma unroll
    for (int c = 0; c < 4; c++) {
        bias[c] = bb_i[c * 32 + lane];
        #pragma unroll
        for (int k = 0; k < 8; k++) wreg[k][c] = Wb_i[k * 128 + c * 32 + lane];
    }
    int s = ptr[w], e = ptr[w + 1];
    int p = s;
    for (; p + 2 <= e; p += 2) {
        int2 e0 = eidx[p];
        int2 e1 = eidx[p + 1];
        float d0 = ea[e0.x];
        float d1 = ea[e1.x];
        const float* x0 = xsrc + (size_t)e0.y * 128;
        const float* x1 = xsrc + (size_t)e1.y * 128;
        float xv0[4], xv1[4];
        #pragma unroll
        for (int c = 0; c < 4; c++) { xv0[c] = x0[c * 32 + lane]; xv1[c] = x1[c * 32 + lane]; }
        float tt0 = (d0 - mu) * 1.6f, tt1 = (d1 - mu) * 1.6f;
        float rv0 = __expf(-tt0 * tt0), rv1 = __expf(-tt1 * tt1);
        float r0[8], r1[8];
        #pragma unroll
        for (int k = 0; k < 8; k++) {
            r0[k] = __shfl_sync(0xffffffffu, rv0, k);
            r1[k] = __shfl_sync(0xffffffffu, rv1, k);
        }
        #pragma unroll
        for (int c = 0; c < 4; c++) {
            float t0 = bias[c], t1 = bias[c];
            #pragma unroll
            for (int k = 0; k < 8; k++) {
                t0 = fmaf(r0[k], wreg[k][c], t0);
                t1 = fmaf(r1[k], wreg[k][c], t1);
            }
            float sg0 = 1.f / (1.f + __expf(-t0));
            float sg1 = 1.f / (1.f + __expf(-t1));
            acc[c] += (t0 * sg0) * xv0[c] + (t1 * sg1) * xv1[c];
        }
    }
    if (p < e) {
        int2 e0 = eidx[p];
        float d0 = ea[e0.x];
        const float* x0 = xsrc + (size_t)e0.y * 128;
        float xv0[4];
        #pragma unroll
        for (int c = 0; c < 4; c++) xv0[c] = x0[c * 32 + lane];
        float tt0 = (d0 - mu) * 1.6f;
        float rv0 = __expf(-tt0 * tt0);
        float r0[8];
        #pragma unroll
        for (int k = 0; k < 8; k++) r0[k] = __shfl_sync(0xffffffffu, rv0, k);
        #pragma unroll
        for (int c = 0; c < 4; c++) {
            float t0 = bias[c];
            #pragma unroll
            for (int k = 0; k < 8; k++) t0 = fmaf(r0[k], wreg[k][c], t0);
            float sg0 = 1.f / (1.f + __expf(-t0));
            acc[c] += (t0 * sg0) * xv0[c];
        }
    }
    float inv = 1.f / (float)((e - s) > 1 ? (e - s) : 1);
    #pragma unroll
    for (int c = 0; c < 4; c++) pre[(size_t)w * 128 + c * 32 + lane] = acc[c] * inv;
}

// ---------------- fp16 mma fused conv GEMM ----------------
// C[M,128] = lrelu( A0[M,128]@W0[128,128] + A1[M,128]@W1[128,128] + bias ); sum += C
__global__ __launch_bounds__(256, 2) void k_mmac16(
    const float* __restrict__ A0, const float* __restrict__ W0,
    const float* __restrict__ A1, const float* __restrict__ W1,
    const float* __restrict__ bias, float* __restrict__ C,
    float* __restrict__ sum, int M)
{
    __shared__ unsigned AsH[2 * 8 * 136];
    __shared__ unsigned WsH[2 * 8 * 136];
    int tid = threadIdx.x;
    int m0 = blockIdx.y * 128;

    int warp = tid >> 5, lane = tid & 31;
    int g = lane >> 2, t = lane & 3;
    int warp_m = warp >> 1, warp_n = warp & 1;

    int le  = tid >> 1;
    int lk8 = (tid & 1) * 8;
    int kp0 = (tid & 1) * 4;
    int arow = m0 + le;
    int wkp = tid >> 5;
    int wc4 = (tid & 31) * 4;

    float4 facc[2][8];
    #pragma unroll
    for (int mt = 0; mt < 2; mt++)
        #pragma unroll
        for (int nt = 0; nt < 8; nt++) facc[mt][nt] = make_float4(0.f, 0.f, 0.f, 0.f);

    float4 pa0, pa1, pw0, pw1;
    {
        pa0 = make_float4(0.f,0.f,0.f,0.f); pa1 = pa0;
        if (arow < M) {
            const float* p = A0 + (size_t)arow * 128 + lk8;
            pa0 = *(const float4*)p; pa1 = *(const float4*)(p + 4);
        }
        const float* pw = W0 + (size_t)(2 * wkp) * 128 + wc4;
        pw0 = *(const float4*)pw; pw1 = *(const float4*)(pw + 128);
    }

    for (int kt = 0; kt < 16; kt++) {
        int buf = (kt & 1) * 1088;
        AsH[buf + (kp0 + 0) * 136 + le] = packh2(pa0.x, pa0.y);
        AsH[buf + (kp0 + 1) * 136 + le] = packh2(pa0.z, pa0.w);
        AsH[buf + (kp0 + 2) * 136 + le] = packh2(pa1.x, pa1.y);
        AsH[buf + (kp0 + 3) * 136 + le] = packh2(pa1.z, pa1.w);
        WsH[buf + wkp * 136 + wc4 + 0] = packh2(pw0.x, pw1.x);
        WsH[buf + wkp * 136 + wc4 + 1] = packh2(pw0.y, pw1.y);
        WsH[buf + wkp * 136 + wc4 + 2] = packh2(pw0.z, pw1.z);
        WsH[buf + wkp * 136 + wc4 + 3] = packh2(pw0.w, pw1.w);
        if (kt + 1 < 16) {
            int kn = kt + 1;
            const float* Ab = (kn < 8) ? A0 : A1;
            const float* Wb_ = (kn < 8) ? W0 : W1;
            int kl = (kn & 7) * 16;
            pa0 = make_float4(0.f,0.f,0.f,0.f); pa1 = pa0;
            if (arow < M) {
                const float* p = Ab + (size_t)arow * 128 + kl + lk8;
                pa0 = *(const float4*)p; pa1 = *(const float4*)(p + 4);
            }
            const float* pw = Wb_ + (size_t)(kl + 2 * wkp) * 128 + wc4;
            pw0 = *(const float4*)pw; pw1 = *(const float4*)(pw + 128);
        }
        __syncthreads();
        unsigned af[2][4];
        #pragma unroll
        for (int mt = 0; mt < 2; mt++) {
            int rowb = warp_m * 32 + mt * 16;
            af[mt][0] = AsH[buf + t * 136 + rowb + g];
            af[mt][1] = AsH[buf + t * 136 + rowb + g + 8];
            af[mt][2] = AsH[buf + (t + 4) * 136 + rowb + g];
            af[mt][3] = AsH[buf + (t + 4) * 136 + rowb + g + 8];
        }
        #pragma unroll
        for (int nt = 0; nt < 8; nt++) {
            int colb = warp_n * 64 + nt * 8;
            unsigned bf0 = WsH[buf + t * 136 + colb + g];
            unsigned bf1 = WsH[buf + (t + 4) * 136 + colb + g];
            mma_f16(facc[0][nt], af[0][0], af[0][1], af[0][2], af[0][3], bf0, bf1);
            mma_f16(facc[1][nt], af[1][0], af[1][1], af[1][2], af[1][3], bf0, bf1);
        }
    }
    #pragma unroll
    for (int mt = 0; mt < 2; mt++) {
        int rowb = m0 + warp_m * 32 + mt * 16;
        #pragma unroll
        for (int nt = 0; nt < 8; nt++) {
            int col = warp_n * 64 + nt * 8 + 2 * t;
            float ba = bias[col], bb_ = bias[col + 1];
            int r0 = rowb + g, r1 = rowb + g + 8;
            float vx = facc[mt][nt].x + ba, vy = facc[mt][nt].y + bb_;
            float vz = facc[mt][nt].z + ba, vw = facc[mt][nt].w + bb_;
            vx = (vx >= 0.f) ? vx : 0.01f * vx;
            vy = (vy >= 0.f) ? vy : 0.01f * vy;
            vz = (vz >= 0.f) ? vz : 0.01f * vz;
            vw = (vw >= 0.f) ? vw : 0.01f * vw;
            if (r0 < M) {
                *(float2*)(C + (size_t)r0 * 128 + col) = make_float2(vx, vy);
                float2 s = *(float2*)(sum + (size_t)r0 * 128 + col);
                s.x += vx; s.y += vy;
                *(float2*)(sum + (size_t)r0 * 128 + col) = s;
            }
            if (r1 < M) {
                *(float2*)(C + (size_t)r1 * 128 + col) = make_float2(vz, vw);
                float2 s = *(float2*)(sum + (size_t)r1 * 128 + col);
                s.x += vz; s.y += vw;
                *(float2*)(sum + (size_t)r1 * 128 + col) = s;
            }
        }
    }
}

// ---------------- fp16 mma factor GEMM: Ch[M,N] = A[M,128]@W[128,N] + bias -----
__global__ __launch_bounds__(256, 2) void k_mma16(
    const float* __restrict__ A, const float* __restrict__ W,
    const float* __restrict__ bias, __half* __restrict__ C,
    int M, int N)
{
    __shared__ unsigned AsH[2 * 8 * 136];
    __shared__ unsigned WsH[2 * 8 * 136];
    int tid = threadIdx.x;
    int m0 = blockIdx.y * 128;
    int n0 = blockIdx.x * 128;

    int warp = tid >> 5, lane = tid & 31;
    int g = lane >> 2, t = lane & 3;
    int warp_m = warp >> 1, warp_n = warp & 1;

    int le  = tid >> 1;
    int lk8 = (tid & 1) * 8;
    int kp0 = (tid & 1) * 4;
    int arow = m0 + le;
    int wkp = tid >> 5;
    int wc4 = (tid & 31) * 4;

    float4 facc[2][8];
    #pragma unroll
    for (int mt = 0; mt < 2; mt++)
        #pragma unroll
        for (int nt = 0; nt < 8; nt++) facc[mt][nt] = make_float4(0.f, 0.f, 0.f, 0.f);

    float4 pa0, pa1, pw0, pw1;
    {
        pa0 = make_float4(0.f,0.f,0.f,0.f); pa1 = pa0;
        if (arow < M) {
            const float* p = A + (size_t)arow * 128 + lk8;
            pa0 = *(const float4*)p; pa1 = *(const float4*)(p + 4);
        }
        const float* pw = W + (size_t)(2 * wkp) * N + n0 + wc4;
        pw0 = *(const float4*)pw; pw1 = *(const float4*)(pw + N);
    }

    for (int kt = 0; kt < 8; kt++) {
        int buf = (kt & 1) * 1088;
        int k = kt * 16;
        AsH[buf + (kp0 + 0) * 136 + le] = packh2(pa0.x, pa0.y);
        AsH[buf + (kp0 + 1) * 136 + le] = packh2(pa0.z, pa0.w);
        AsH[buf + (kp0 + 2) * 136 + le] = packh2(pa1.x, pa1.y);
        AsH[buf + (kp0 + 3) * 136 + le] = packh2(pa1.z, pa1.w);
        WsH[buf + wkp * 136 + wc4 + 0] = packh2(pw0.x, pw1.x);
        WsH[buf + wkp * 136 + wc4 + 1] = packh2(pw0.y, pw1.y);
        WsH[buf + wkp * 136 + wc4 + 2] = packh2(pw0.z, pw1.z);
        WsH[buf + wkp * 136 + wc4 + 3] = packh2(pw0.w, pw1.w);
        if (kt + 1 < 8) {
            int kn = k + 16;
            pa0 = make_float4(0.f,0.f,0.f,0.f); pa1 = pa0;
            if (arow < M) {
                const float* p = A + (size_t)arow * 128 + kn + lk8;
                pa0 = *(const float4*)p; pa1 = *(const float4*)(p + 4);
            }
            const float* pw = W + (size_t)(kn + 2 * wkp) * N + n0 + wc4;
            pw0 = *(const float4*)pw; pw1 = *(const float4*)(pw + N);
        }
        __syncthreads();
        unsigned af[2][4];
        #pragma unroll
        for (int mt = 0; mt < 2; mt++) {
            int rowb = warp_m * 32 + mt * 16;
            af[mt][0] = AsH[buf + t * 136 + rowb + g];
            af[mt][1] = AsH[buf + t * 136 + rowb + g + 8];
            af[mt][2] = AsH[buf + (t + 4) * 136 + rowb + g];
            af[mt][3] = AsH[buf + (t + 4) * 136 + rowb + g + 8];
        }
        #pragma unroll
        for (int nt = 0; nt < 8; nt++) {
            int colb = warp_n * 64 + nt * 8;
            unsigned bf0 = WsH[buf + t * 136 + colb + g];
            unsigned bf1 = WsH[buf + (t + 4) * 136 + colb + g];
            mma_f16(facc[0][nt], af[0][0], af[0][1], af[0][2], af[0][3], bf0, bf1);
            mma_f16(facc[1][nt], af[1][0], af[1][1], af[1][2], af[1][3], bf0, bf1);
        }
    }
    #pragma unroll
    for (int mt = 0; mt < 2; mt++) {
        int rowb = m0 + warp_m * 32 + mt * 16;
        #pragma unroll
        for (int nt = 0; nt < 8; nt++) {
            int col = n0 + warp_n * 64 + nt * 8 + 2 * t;
            float ba = 0.f, bb_ = 0.f;
            if (bias) { ba = bias[col]; bb_ = bias[col + 1]; }
            int r0 = rowb + g, r1 = rowb + g + 8;
            if (r0 < M)
                *(__half2*)(C + (size_t)r0 * N + col) =
                    __floats2half2_rn(facc[mt][nt].x + ba, facc[mt][nt].y + bb_);
            if (r1 < M)
                *(__half2*)(C + (size_t)r1 * N + col) =
                    __floats2half2_rn(facc[mt][nt].z + ba, facc[mt][nt].w + bb_);
        }
    }
}

// ---------------- cvec ----------------
__global__ void k_cvec(const float* __restrict__ W_el, const float* __restrict__ W1) {
    int j = blockIdx.x * 256 + threadIdx.x;
    if (j < 512) {
        float s = 0.f;
        #pragma unroll
        for (int k = 0; k < 8; k++) s = fmaf(W_el[k], W1[(size_t)(256 + k) * 512 + j], s);
        g_cvec[j] = s;
    }
}

__global__ void k_init_out() {
    int i = blockIdx.x * 256 + threadIdx.x;
    if (i < NGV * 128) { g_out_w[i] = 0.f; g_out_max[i] = -INFINITY; }
}

// ---------------- fused edge MLP + per-graph reduction: 128-edge tiles ------------
#define EDGE_SMEM_FLOATS 22272
__global__ __launch_bounds__(256, 2) void k_edge(
    const __half* __restrict__ Al, const __half* __restrict__ Bp,
    const float* __restrict__ W2, const float* __restrict__ b2,
    const float* __restrict__ Wm, const float* __restrict__ bm,
    const int* __restrict__ src,
    const float* __restrict__ ea, const int* __restrict__ lbatch)
{
    extern __shared__ float dynsm[];
    unsigned* AsH = (unsigned*)dynsm;
    unsigned* WsH = (unsigned*)(dynsm + 2176);
    float* smm  = dynsm + 4352;
    float* cs   = dynsm + 21248;
    float* se_d = dynsm + 21760;
    int*   se_a = (int*)(dynsm + 21888);
    int*   se_b = (int*)(dynsm + 22016);
    int*   se_g = (int*)(dynsm + 22144);

    int tid = threadIdx.x;
    int t0 = blockIdx.x * 128;
    if (tid < 128) {
        int slot = t0 + tid;
        if (slot < EV) {
            int2 ei = g_src_edges[slot];
            int e = ei.x;
            int s = src[e];
            se_a[tid] = s; se_b[tid] = ei.y;
            se_d[tid] = ea[e];
            se_g[tid] = lbatch[s];
        } else { se_a[tid] = 0; se_b[tid] = 0; se_d[tid] = 0.f; se_g[tid] = -1; }
    }
    for (int i = tid; i < 512; i += 256) cs[i] = g_cvec[i];
    __syncthreads();

    int warp = tid >> 5, lane = tid & 31;
    int g = lane >> 2, t = lane & 3;
    int warp_m = warp >> 1, warp_n = warp & 1;

    int le  = tid >> 1;
    int lk8 = (tid & 1) * 8;
    int kp0 = (tid & 1) * 4;
    const __half* arow = Al + (size_t)se_a[le] * 512;
    const __half* brow = Bp + (size_t)se_b[le] * 512;
    float dv = se_d[le];
    int wkp = tid >> 5;
    int wc4 = (tid & 31) * 4;

    // ---- GEMM 1 (fp16 mma): m = relu(A[src]+B[dst]+d*cvec) @ W2 ----
    float4 facc[2][8];
    #pragma unroll
    for (int mt = 0; mt < 2; mt++)
        #pragma unroll
        for (int nt = 0; nt < 8; nt++) facc[mt][nt] = make_float4(0.f, 0.f, 0.f, 0.f);

    uint4 pa, pb;
    float4 pw0, pw1;
    {
        pa = *(const uint4*)(arow + lk8);
        pb = *(const uint4*)(brow + lk8);
        const float* pw = W2 + (size_t)(2 * wkp) * 128 + wc4;
        pw0 = *(const float4*)pw; pw1 = *(const float4*)(pw + 128);
    }

    for (int kt = 0; kt < 32; kt++) {
        int buf = (kt & 1) * 1088;
        int k = kt * 16;
        float4 c0 = *(const float4*)(cs + k + lk8), c1 = *(const float4*)(cs + k + lk8 + 4);
        const __half2* a2 = (const __half2*)&pa;
        const __half2* b2v = (const __half2*)&pb;
        float2 fa0 = __half22float2(a2[0]), fb0 = __half22float2(b2v[0]);
        float2 fa1 = __half22float2(a2[1]), fb1 = __half22float2(b2v[1]);
        float2 fa2 = __half22float2(a2[2]), fb2 = __half22float2(b2v[2]);
        float2 fa3 = __half22float2(a2[3]), fb3 = __half22float2(b2v[3]);
        float h0 = fmaxf(fa0.x + fb0.x + dv * c0.x, 0.f);
        float h1 = fmaxf(fa0.y + fb0.y + dv * c0.y, 0.f);
        float h2 = fmaxf(fa1.x + fb1.x + dv * c0.z, 0.f);
        float h3 = fmaxf(fa1.y + fb1.y + dv * c0.w, 0.f);
        float h4 = fmaxf(fa2.x + fb2.x + dv * c1.x, 0.f);
        float h5 = fmaxf(fa2.y + fb2.y + dv * c1.y, 0.f);
        float h6 = fmaxf(fa3.x + fb3.x + dv * c1.z, 0.f);
        float h7 = fmaxf(fa3.y + fb3.y + dv * c1.w, 0.f);
        AsH[buf + (kp0 + 0) * 136 + le] = packh2(h0, h1);
        AsH[buf + (kp0 + 1) * 136 + le] = packh2(h2, h3);
        AsH[buf + (kp0 + 2) * 136 + le] = packh2(h4, h5);
        AsH[buf + (kp0 + 3) * 136 + le] = packh2(h6, h7);
        WsH[buf + wkp * 136 + wc4 + 0] = packh2(pw0.x, pw1.x);
        WsH[buf + wkp * 136 + wc4 + 1] = packh2(pw0.y, pw1.y);
        WsH[buf + wkp * 136 + wc4 + 2] = packh2(pw0.z, pw1.z);
        WsH[buf + wkp * 136 + wc4 + 3] = packh2(pw0.w, pw1.w);
        if (kt + 1 < 32) {
            int kn = k + 16;
            pa = *(const uint4*)(arow + kn + lk8);
            pb = *(const uint4*)(brow + kn + lk8);
            const float* pw = W2 + (size_t)(kn + 2 * wkp) * 128 + wc4;
            pw0 = *(const float4*)pw; pw1 = *(const float4*)(pw + 128);
        }
        __syncthreads();
        unsigned af[2][4];
        #pragma unroll
        for (int mt = 0; mt < 2; mt++) {
            int rowb = warp_m * 32 + mt * 16;
            af[mt][0] = AsH[buf + t * 136 + rowb + g];
            af[mt][1] = AsH[buf + t * 136 + rowb + g + 8];
            af[mt][2] = AsH[buf + (t + 4) * 136 + rowb + g];
            af[mt][3] = AsH[buf + (t + 4) * 136 + rowb + g + 8];
        }
        #pragma unroll
        for (int nt = 0; nt < 8; nt++) {
            int colb = warp_n * 64 + nt * 8;
            unsigned bf0 = WsH[buf + t * 136 + colb + g];
            unsigned bf1 = WsH[buf + (t + 4) * 136 + colb + g];
            mma_f16(facc[0][nt], af[0][0], af[0][1], af[0][2], af[0][3], bf0, bf1);
            mma_f16(facc[1][nt], af[1][0], af[1][1], af[1][2], af[1][3], bf0, bf1);
        }
    }
    __syncthreads();

    // m = facc + b2 -> smm (fragment-layout stores, fp32)
    #pragma unroll
    for (int mt = 0; mt < 2; mt++) {
        int rowb = warp_m * 32 + mt * 16;
        #pragma unroll
        for (int nt = 0; nt < 8; nt++) {
            int cc = warp_n * 64 + nt * 8 + 2 * t;
            float ba = b2[cc], bb_ = b2[cc + 1];
            *(float2*)(smm + (rowb + g) * 132 + cc) =
                make_float2(facc[mt][nt].x + ba, facc[mt][nt].y + bb_);
            *(float2*)(smm + (rowb + g + 8) * 132 + cc) =
                make_float2(facc[mt][nt].z + ba, facc[mt][nt].w + bb_);
        }
    }
    __syncthreads();

    // ---- GEMM 2 (fp16 mma): u = m @ Wm ; w = tanh(u + bm) ----
    float4 facc2[2][8];
    #pragma unroll
    for (int mt = 0; mt < 2; mt++)
        #pragma unroll
        for (int nt = 0; nt < 8; nt++) facc2[mt][nt] = make_float4(0.f, 0.f, 0.f, 0.f);

    {
        const float* pw = Wm + (size_t)(2 * wkp) * 128 + wc4;
        pw0 = *(const float4*)pw; pw1 = *(const float4*)(pw + 128);
    }
    for (int kt = 0; kt < 8; kt++) {
        int buf = (kt & 1) * 1088;
        int k = kt * 16;
        WsH[buf + wkp * 136 + wc4 + 0] = packh2(pw0.x, pw1.x);
        WsH[buf + wkp * 136 + wc4 + 1] = packh2(pw0.y, pw1.y);
        WsH[buf + wkp * 136 + wc4 + 2] = packh2(pw0.z, pw1.z);
        WsH[buf + wkp * 136 + wc4 + 3] = packh2(pw0.w, pw1.w);
        if (kt + 1 < 8) {
            const float* pw = Wm + (size_t)(k + 16 + 2 * wkp) * 128 + wc4;
            pw0 = *(const float4*)pw; pw1 = *(const float4*)(pw + 128);
        }
        __syncthreads();
        unsigned af[2][4];
        #pragma unroll
        for (int mt = 0; mt < 2; mt++) {
            int rowb = warp_m * 32 + mt * 16;
            const float* r0p = smm + (rowb + g) * 132 + k;
            const float* r1p = smm + (rowb + g + 8) * 132 + k;
            af[mt][0] = packh2(r0p[2 * t], r0p[2 * t + 1]);
            af[mt][1] = packh2(r1p[2 * t], r1p[2 * t + 1]);
            af[mt][2] = packh2(r0p[2 * t + 8], r0p[2 * t + 9]);
            af[mt][3] = packh2(r1p[2 * t + 8], r1p[2 * t + 9]);
        }
        #pragma unroll
        for (int nt = 0; nt < 8; nt++) {
            int colb = warp_n * 64 + nt * 8;
            unsigned bf0 = WsH[buf + t * 136 + colb + g];
            unsigned bf1 = WsH[buf + (t + 4) * 136 + colb + g];
            mma_f16(facc2[0][nt], af[0][0], af[0][1], af[0][2], af[0][3], bf0, bf1);
            mma_f16(facc2[1][nt], af[1][0], af[1][1], af[1][2], af[1][3], bf0, bf1);
        }
    }

    // ---- per-graph reduction (fragment layout) ----
    {
        int row_block = warp_m * 32;
        bool uniform = (se_g[row_block] == se_g[row_block + 31]) && (se_g[row_block] >= 0);
        if (uniform) {
            int gg = se_g[row_block];
            #pragma unroll
            for (int nt = 0; nt < 8; nt++) {
                int cc = warp_n * 64 + nt * 8 + 2 * t;
                float b0 = bm[cc], b1 = bm[cc + 1];
                float ps0 = 0.f, ps1 = 0.f, mx0 = -INFINITY, mx1 = -INFINITY;
                #pragma unroll
                for (int mt = 0; mt < 2; mt++) {
                    int r0 = warp_m * 32 + mt * 16 + g, r1 = r0 + 8;
                    float m00 = smm[r0 * 132 + cc], m01 = smm[r0 * 132 + cc + 1];
                    float m10 = smm[r1 * 132 + cc], m11 = smm[r1 * 132 + cc + 1];
                    ps0 += fast_tanh(facc2[mt][nt].x + b0) * m00
                         + fast_tanh(facc2[mt][nt].z + b0) * m10;
                    ps1 += fast_tanh(facc2[mt][nt].y + b1) * m01
                         + fast_tanh(facc2[mt][nt].w + b1) * m11;
                    mx0 = fmaxf(mx0, fmaxf(m00, m10));
                    mx1 = fmaxf(mx1, fmaxf(m01, m11));
                }
                #pragma unroll
                for (int off = 4; off < 32; off <<= 1) {
                    ps0 += __shfl_xor_sync(0xffffffffu, ps0, off);
                    ps1 += __shfl_xor_sync(0xffffffffu, ps1, off);
                    mx0 = fmaxf(mx0, __shfl_xor_sync(0xffffffffu, mx0, off));
                    mx1 = fmaxf(mx1, __shfl_xor_sync(0xffffffffu, mx1, off));
                }
                if (g == 0) {
                    atomicAdd(&g_out_w[gg * 128 + cc], ps0);
                    atomicAdd(&g_out_w[gg * 128 + cc + 1], ps1);
                    atomicMaxFloat(&g_out_max[gg * 128 + cc], mx0);
                    atomicMaxFloat(&g_out_max[gg * 128 + cc + 1], mx1);
                }
            }
        } else {
            #pragma unroll
            for (int nt = 0; nt < 8; nt++) {
                int cc = warp_n * 64 + nt * 8 + 2 * t;
                float b0 = bm[cc], b1 = bm[cc + 1];
                #pragma unroll
                for (int mt = 0; mt < 2; mt++) {
                    int r0 = warp_m * 32 + mt * 16 + g, r1 = r0 + 8;
                    int g0 = se_g[r0], g1 = se_g[r1];
                    if (g0 >= 0) {
                        float m00 = smm[r0 * 132 + cc], m01 = smm[r0 * 132 + cc + 1];
                        atomicAdd(&g_out_w[g0 * 128 + cc],
                                  fast_tanh(facc2[mt][nt].x + b0) * m00);
                        atomicAdd(&g_out_w[g0 * 128 + cc + 1],
                                  fast_tanh(facc2[mt][nt].y + b1) * m01);
                        atomicMaxFloat(&g_out_max[g0 * 128 + cc], m00);
                        atomicMaxFloat(&g_out_max[g0 * 128 + cc + 1], m01);
                    }
                    if (g1 >= 0) {
                        float m10 = smm[r1 * 132 + cc], m11 = smm[r1 * 132 + cc + 1];
                        atomicAdd(&g_out_w[g1 * 128 + cc],
                                  fast_tanh(facc2[mt][nt].z + b0) * m10);
                        atomicAdd(&g_out_w[g1 * 128 + cc + 1],
                                  fast_tanh(facc2[mt][nt].w + b1) * m11);
                        atomicMaxFloat(&g_out_max[g1 * 128 + cc], m10);
                        atomicMaxFloat(&g_out_max[g1 * 128 + cc + 1], m11);
                    }
                }
            }
        }
    }
}

__global__ void k_final(float* __restrict__ out) {
    int i = blockIdx.x * 256 + threadIdx.x;
    if (i < NGV * 256) {
        int g = i >> 8, j = i & 255;
        float v;
        if (j < 128) v = g_out_w[g * 128 + j];
        else {
            v = g_out_max[g * 128 + j - 128];
            if (!isfinite(v)) v = 0.f;
        }
        out[i] = v;
    }
}

// ---------------- host orchestration ----------------
#define SYM(p, s) do { void* _t = nullptr; cudaGetSymbolAddress(&_t, s); p = (decltype(p))_t; } while (0)

extern "C" void kernel_launch(void* const* d_in, const int* in_sizes, int n_in,
                              void* d_out, int out_size) {
    const float* x_l    = (const float*)d_in[0];
    const float* x_p    = (const float*)d_in[1];
    const float* ea     = (const float*)d_in[2];
    const int*   esrc   = (const int*)  d_in[3];
    const int*   edst   = (const int*)  d_in[4];
    const int*   lbatch = (const int*)  d_in[5];
    const float* W_node = (const float*)d_in[6];
    const float* W_el   = (const float*)d_in[7];
    const float* Wb     = (const float*)d_in[8];
    const float* bb     = (const float*)d_in[9];
    const float* Wn     = (const float*)d_in[10];
    const float* Ws_    = (const float*)d_in[11];
    const float* bconv  = (const float*)d_in[12];
    const float* W1     = (const float*)d_in[13];
    const float* b1     = (const float*)d_in[14];
    const float* W2     = (const float*)d_in[15];
    const float* b2     = (const float*)d_in[16];
    const float* Wm     = (const float*)d_in[17];
    const float* bm     = (const float*)d_in[18];

    float *xl, *xl2, *xlsum, *prel, *xp, *xp2, *xpsum, *prep;
    __half *Ah, *Bh;
    int *dcnt, *dptr, *scnt, *sptr, *stmp, *bsum;
    SYM(xl, g_xl); SYM(xl2, g_xl2); SYM(xlsum, g_xlsum); SYM(prel, g_prel);
    SYM(xp, g_xp); SYM(xp2, g_xp2); SYM(xpsum, g_xpsum); SYM(prep, g_prep);
    SYM(Ah, g_Ah); SYM(Bh, g_Bh);
    SYM(dcnt, g_dst_cnt); SYM(dptr, g_dst_ptr);
    SYM(scnt, g_src_cnt); SYM(sptr, g_src_ptr);
    SYM(stmp, g_scan_tmp); SYM(bsum, g_bsum);

    cudaFuncSetAttribute(k_edge, cudaFuncAttributeMaxDynamicSharedMemorySize,
                         EDGE_SMEM_FLOATS * (int)sizeof(float));

    // node embedding
    k_embed<<<(NLV + 3) / 4, 128>>>(x_l, xl, W_node, NLV);
    k_embed<<<(NPV + 3) / 4, 128>>>(x_p, xp, W_node, NPV);

    // cvec
    k_cvec<<<2, 256>>>(W_el, W1);

    // CSR (dst and src)
    cudaMemsetAsync(dcnt, 0, NPV * sizeof(int));
    cudaMemsetAsync(scnt, 0, NLV * sizeof(int));
    k_hist<<<(EV + 255) / 256, 256>>>(esrc, edst);
    int nbp = (NPV + 1023) / 1024, nbl = (NLV + 1023) / 1024;
    k_scan1<<<nbp, 1024>>>(dcnt, stmp, bsum, NPV);
    k_scan2<<<1, 512>>>(bsum, nbp);
    k_scan3<<<nbp, 1024>>>(stmp, bsum, dptr, NPV);
    k_scan1<<<nbl, 1024>>>(scnt, stmp, bsum, NLV);
    k_scan2<<<1, 512>>>(bsum, nbl);
    k_scan3<<<nbl, 1024>>>(stmp, bsum, sptr, NLV);
    cudaMemsetAsync(dcnt, 0, NPV * sizeof(int));
    cudaMemsetAsync(scnt, 0, NLV * sizeof(int));
    k_fill<<<(EV + 255) / 256, 256>>>(esrc, edst);

    // running sums
    cudaMemsetAsync(xlsum, 0, (size_t)NLV * 128 * sizeof(float));
    cudaMemsetAsync(xpsum, 0, (size_t)NPV * 128 * sizeof(float));

    // 3 hetero layers (fp16 mma conv GEMMs)
    float *cxl = xl, *cxp = xp, *nxl = xl2, *nxp = xp2;
    for (int l = 0; l < 3; l++) {
        int ilp = 2 * l, ipl = 2 * l + 1;
        k_agg2<<<((NPV + NLV) * 32 + 255) / 256, 256>>>(cxl, cxp, ea,
                Wb + ilp * 1024, bb + ilp * 128,
                Wb + ipl * 1024, bb + ipl * 128, prep, prel);
        k_mmac16<<<dim3(1, (NPV + 127) / 128), 256>>>(cxp, Ws_ + (size_t)ilp * 16384,
                prep, Wn + (size_t)ilp * 16384, bconv + ilp * 128,
                nxp, xpsum, NPV);
        k_mmac16<<<dim3(1, (NLV + 127) / 128), 256>>>(cxl, Ws_ + (size_t)ipl * 16384,
                prel, Wn + (size_t)ipl * 16384, bconv + ipl * 128,
                nxl, xlsum, NLV);
        float* t;
        t = cxl; cxl = nxl; nxl = t;
        t = cxp; cxp = nxp; nxp = t;
    }

    // edge readout factorization (fp16 mma, fp16 output)
    k_mma16<<<dim3(4, (NLV + 127) / 128), 256>>>(xlsum, W1, b1, Ah, NLV, 512);
    k_mma16<<<dim3(4, (NPV + 127) / 128), 256>>>(xpsum, W1 + (size_t)128 * 512,
                                                 nullptr, Bh, NPV, 512);

    k_init_out<<<(NGV * 128 + 255) / 256, 256>>>();
    k_edge<<<(EV + 127) / 128, 256, EDGE_SMEM_FLOATS * (int)sizeof(float)>>>(
            Ah, Bh, W2, b2, Wm, bm, esrc, ea, lbatch);
    k_final<<<(NGV * 256 + 255) / 256, 256>>>((float*)d_out);
}